// round 1
// baseline (speedup 1.0000x reference)
#include <cuda_runtime.h>
#include <math.h>

#define BATCH   2
#define SEQLEN  512
#define DMODEL  768
#define DINNER  1536
#define NHEADS  24
#define HEADDIM 64
#define DSTATE  128
#define CONVDIM 1792            // DINNER + 2*DSTATE
#define DINPROJ 3352            // 2*DINNER + 2*DSTATE + NHEADS
#define MROWS   (BATCH*SEQLEN)  // 1024

// ---------------- scratch (device globals: no allocation allowed) ----------
__device__ float g_zx[MROWS * DINPROJ];   // in-projection result
__device__ float g_X [MROWS * DINNER];    // conv-silu'd x
__device__ float g_Bm[MROWS * DSTATE];
__device__ float g_Cm[MROWS * DSTATE];
__device__ float g_dt[MROWS * NHEADS];
__device__ float g_dA[MROWS * NHEADS];
__device__ float g_Y [MROWS * DINNER];    // scan output (pre-gate)
__device__ float g_G [MROWS * DINNER];    // gated

// ---------------- generic NT GEMM: C[m,n] = sum_k A[m,k] * B[n,k] ----------
// A: M x K row-major, B: N x K row-major. BM=BN=64, BK=16, 256 threads, 4x4/thread.
__global__ void gemm_nt(const float* __restrict__ A, const float* __restrict__ B,
                        float* __restrict__ C, int M, int N, int K) {
    const int BM = 64, BN = 64, BK = 16;
    __shared__ float As[BK][BM];
    __shared__ float Bs[BK][BN];
    int tid = threadIdx.x;
    int m0 = blockIdx.y * BM, n0 = blockIdx.x * BN;
    int tx = tid % 16, ty = tid / 16;
    float acc[4][4];
#pragma unroll
    for (int i = 0; i < 4; i++)
#pragma unroll
        for (int j = 0; j < 4; j++) acc[i][j] = 0.f;

    for (int k0 = 0; k0 < K; k0 += BK) {
#pragma unroll
        for (int e = tid; e < BM * BK; e += 256) {
            int r = e / BK, c = e % BK;
            int gm = m0 + r;
            As[c][r] = (gm < M) ? A[(size_t)gm * K + k0 + c] : 0.f;
        }
#pragma unroll
        for (int e = tid; e < BN * BK; e += 256) {
            int r = e / BK, c = e % BK;
            int gn = n0 + r;
            Bs[c][r] = (gn < N) ? B[(size_t)gn * K + k0 + c] : 0.f;
        }
        __syncthreads();
#pragma unroll
        for (int kk = 0; kk < BK; kk++) {
            float a[4], b[4];
#pragma unroll
            for (int i = 0; i < 4; i++) a[i] = As[kk][ty * 4 + i];
#pragma unroll
            for (int j = 0; j < 4; j++) b[j] = Bs[kk][tx * 4 + j];
#pragma unroll
            for (int i = 0; i < 4; i++)
#pragma unroll
                for (int j = 0; j < 4; j++) acc[i][j] += a[i] * b[j];
        }
        __syncthreads();
    }
#pragma unroll
    for (int i = 0; i < 4; i++) {
        int gm = m0 + ty * 4 + i;
        if (gm >= M) continue;
#pragma unroll
        for (int j = 0; j < 4; j++) {
            int gn = n0 + tx * 4 + j;
            if (gn < N) C[(size_t)gm * N + gn] = acc[i][j];
        }
    }
}

// ---------------- causal depthwise conv (width 4) + SiLU + split -----------
__global__ void conv_kernel(const float* __restrict__ conv_w,
                            const float* __restrict__ conv_b) {
    int idx = blockIdx.x * blockDim.x + threadIdx.x;
    if (idx >= MROWS * CONVDIM) return;
    int c = idx % CONVDIM;
    int m = idx / CONVDIM;
    int t = m % SEQLEN;
    float s = conv_b[c];
#pragma unroll
    for (int k = 0; k < 4; k++) {
        int tt = t - 3 + k;
        if (tt >= 0)
            s += g_zx[(size_t)(m - 3 + k) * DINPROJ + DINNER + c] * conv_w[c * 4 + k];
    }
    float v = s / (1.f + expf(-s));   // silu
    if (c < DINNER)                g_X [m * DINNER + c] = v;
    else if (c < DINNER + DSTATE)  g_Bm[m * DSTATE + (c - DINNER)] = v;
    else                           g_Cm[m * DSTATE + (c - DINNER - DSTATE)] = v;
}

// ---------------- dt = softplus(dt_raw + bias), dA = exp(-dt*exp(A_log)) ---
__global__ void dt_kernel(const float* __restrict__ dt_bias,
                          const float* __restrict__ A_log) {
    int idx = blockIdx.x * blockDim.x + threadIdx.x;
    if (idx >= MROWS * NHEADS) return;
    int h = idx % NHEADS;
    int m = idx / NHEADS;
    float x = g_zx[(size_t)m * DINPROJ + DINNER + CONVDIM + h] + dt_bias[h];
    float dt = (x > 20.f) ? x : log1pf(expf(x));
    g_dt[idx] = dt;
    g_dA[idx] = expf(-dt * expf(A_log[h]));
}

// ---------------- SSM scan: one block per (b,h), 512 thr, 16 states/thr ----
__global__ void scan_kernel(const float* __restrict__ D_param) {
    int bh = blockIdx.x;           // 0..47
    int b = bh / NHEADS, h = bh % NHEADS;
    int tid = threadIdx.x;         // 0..511
    int p  = tid >> 3;             // 0..63
    int nb = tid & 7;              // 0..7
    int n0 = nb * 16;

    __shared__ __align__(16) float sB[DSTATE];
    __shared__ __align__(16) float sC[DSTATE];
    __shared__ __align__(16) float sx[HEADDIM];
    __shared__ float sdt, sdA;

    float s[16];
#pragma unroll
    for (int i = 0; i < 16; i++) s[i] = 0.f;
    float Dp = D_param[h];

    for (int t = 0; t < SEQLEN; t++) {
        int m = b * SEQLEN + t;
        if (tid < DSTATE)                      sB[tid] = g_Bm[m * DSTATE + tid];
        else if (tid < 2 * DSTATE)             sC[tid - DSTATE] = g_Cm[m * DSTATE + tid - DSTATE];
        else if (tid < 2 * DSTATE + HEADDIM)   sx[tid - 2 * DSTATE] =
                                                   g_X[m * DINNER + h * HEADDIM + (tid - 2 * DSTATE)];
        else if (tid == 2 * DSTATE + HEADDIM) { sdt = g_dt[m * NHEADS + h];
                                                sdA = g_dA[m * NHEADS + h]; }
        __syncthreads();

        float xv   = sx[p];
        float coef = sdt * xv;
        float dA   = sdA;
        const float4* B4 = (const float4*)(sB + n0);
        const float4* C4 = (const float4*)(sC + n0);
        float acc = 0.f;
#pragma unroll
        for (int q = 0; q < 4; q++) {
            float4 Bv = B4[q];
            float4 Cv = C4[q];
            int i = q * 4;
            s[i+0] = s[i+0] * dA + coef * Bv.x;  acc += s[i+0] * Cv.x;
            s[i+1] = s[i+1] * dA + coef * Bv.y;  acc += s[i+1] * Cv.y;
            s[i+2] = s[i+2] * dA + coef * Bv.z;  acc += s[i+2] * Cv.z;
            s[i+3] = s[i+3] * dA + coef * Bv.w;  acc += s[i+3] * Cv.w;
        }
        // reduce across the 8 lanes sharing the same p (consecutive lanes)
        acc += __shfl_down_sync(0xffffffffu, acc, 4, 8);
        acc += __shfl_down_sync(0xffffffffu, acc, 2, 8);
        acc += __shfl_down_sync(0xffffffffu, acc, 1, 8);
        if (nb == 0)
            g_Y[m * DINNER + h * HEADDIM + p] = acc + Dp * xv;
        __syncthreads();
    }
}

// ---------------- gating: G = Y * silu(z) -----------------------------------
__global__ void gate_kernel() {
    int idx = blockIdx.x * blockDim.x + threadIdx.x;
    if (idx >= MROWS * DINNER) return;
    int m = idx / DINNER, i = idx % DINNER;
    float z = g_zx[(size_t)m * DINPROJ + i];
    g_G[idx] = g_Y[idx] * (z / (1.f + expf(-z)));
}

// ---------------- launch ----------------------------------------------------
extern "C" void kernel_launch(void* const* d_in, const int* in_sizes, int n_in,
                              void* d_out, int out_size) {
    const float* u       = (const float*)d_in[0];
    const float* W_in    = (const float*)d_in[1];
    const float* conv_w  = (const float*)d_in[2];
    const float* conv_b  = (const float*)d_in[3];
    const float* dt_bias = (const float*)d_in[4];
    const float* A_log   = (const float*)d_in[5];
    const float* D_param = (const float*)d_in[6];
    const float* W_out   = (const float*)d_in[7];
    float* out = (float*)d_out;

    float *zx, *G;
    cudaGetSymbolAddress((void**)&zx, g_zx);
    cudaGetSymbolAddress((void**)&G,  g_G);

    // 1. in-projection: (1024 x 768) @ (3352 x 768)^T
    {
        dim3 grid((DINPROJ + 63) / 64, MROWS / 64);
        gemm_nt<<<grid, 256>>>(u, W_in, zx, MROWS, DINPROJ, DMODEL);
    }
    // 2. causal conv + silu
    conv_kernel<<<(MROWS * CONVDIM + 255) / 256, 256>>>(conv_w, conv_b);
    // 3. dt / dA
    dt_kernel<<<(MROWS * NHEADS + 255) / 256, 256>>>(dt_bias, A_log);
    // 4. sequential scan
    scan_kernel<<<BATCH * NHEADS, 512>>>(D_param);
    // 5. gate
    gate_kernel<<<(MROWS * DINNER + 255) / 256, 256>>>();
    // 6. out-projection: (1024 x 1536) @ (768 x 1536)^T
    {
        dim3 grid(DMODEL / 64, MROWS / 64);
        gemm_nt<<<grid, 256>>>(G, W_out, out, MROWS, DMODEL, DINNER);
    }
}

// round 2
// speedup vs baseline: 1.5970x; 1.5970x over previous
#include <cuda_runtime.h>
#include <math.h>

#define BATCH   2
#define SEQLEN  512
#define DMODEL  768
#define DINNER  1536
#define NHEADS  24
#define HEADDIM 64
#define DSTATE  128
#define CONVDIM 1792            // DINNER + 2*DSTATE
#define DINPROJ 3352            // 2*DINNER + 2*DSTATE + NHEADS
#define MROWS   (BATCH*SEQLEN)  // 1024

// ---------------- scratch (device globals: no allocation allowed) ----------
__device__ float g_zx[MROWS * DINPROJ];   // in-projection result
__device__ float g_X [MROWS * DINNER];    // conv-silu'd x
__device__ float g_Bm[MROWS * DSTATE];
__device__ float g_Cm[MROWS * DSTATE];
__device__ float g_dt[MROWS * NHEADS];
__device__ float g_dA[MROWS * NHEADS];
__device__ float g_Y0[MROWS * DINNER];    // scan partial (n-half 0, includes D*x)
__device__ float g_Y1[MROWS * DINNER];    // scan partial (n-half 1)
__device__ float g_G [MROWS * DINNER];    // gated

// ---------------- generic NT GEMM: C[m,n] = sum_k A[m,k] * B[n,k] ----------
__global__ void gemm_nt(const float* __restrict__ A, const float* __restrict__ B,
                        float* __restrict__ C, int M, int N, int K) {
    const int BM = 64, BN = 64, BK = 16;
    __shared__ float As[BK][BM];
    __shared__ float Bs[BK][BN];
    int tid = threadIdx.x;
    int m0 = blockIdx.y * BM, n0 = blockIdx.x * BN;
    int tx = tid % 16, ty = tid / 16;
    float acc[4][4];
#pragma unroll
    for (int i = 0; i < 4; i++)
#pragma unroll
        for (int j = 0; j < 4; j++) acc[i][j] = 0.f;

    for (int k0 = 0; k0 < K; k0 += BK) {
#pragma unroll
        for (int e = tid; e < BM * BK; e += 256) {
            int r = e / BK, c = e % BK;
            int gm = m0 + r;
            As[c][r] = (gm < M) ? A[(size_t)gm * K + k0 + c] : 0.f;
        }
#pragma unroll
        for (int e = tid; e < BN * BK; e += 256) {
            int r = e / BK, c = e % BK;
            int gn = n0 + r;
            Bs[c][r] = (gn < N) ? B[(size_t)gn * K + k0 + c] : 0.f;
        }
        __syncthreads();
#pragma unroll
        for (int kk = 0; kk < BK; kk++) {
            float a[4], b[4];
#pragma unroll
            for (int i = 0; i < 4; i++) a[i] = As[kk][ty * 4 + i];
#pragma unroll
            for (int j = 0; j < 4; j++) b[j] = Bs[kk][tx * 4 + j];
#pragma unroll
            for (int i = 0; i < 4; i++)
#pragma unroll
                for (int j = 0; j < 4; j++) acc[i][j] += a[i] * b[j];
        }
        __syncthreads();
    }
#pragma unroll
    for (int i = 0; i < 4; i++) {
        int gm = m0 + ty * 4 + i;
        if (gm >= M) continue;
#pragma unroll
        for (int j = 0; j < 4; j++) {
            int gn = n0 + tx * 4 + j;
            if (gn < N) C[(size_t)gm * N + gn] = acc[i][j];
        }
    }
}

// ---------------- causal depthwise conv (width 4) + SiLU + split -----------
__global__ void conv_kernel(const float* __restrict__ conv_w,
                            const float* __restrict__ conv_b) {
    int idx = blockIdx.x * blockDim.x + threadIdx.x;
    if (idx >= MROWS * CONVDIM) return;
    int c = idx % CONVDIM;
    int m = idx / CONVDIM;
    int t = m % SEQLEN;
    float s = conv_b[c];
#pragma unroll
    for (int k = 0; k < 4; k++) {
        int tt = t - 3 + k;
        if (tt >= 0)
            s += g_zx[(size_t)(m - 3 + k) * DINPROJ + DINNER + c] * conv_w[c * 4 + k];
    }
    float v = s / (1.f + expf(-s));   // silu
    if (c < DINNER)                g_X [m * DINNER + c] = v;
    else if (c < DINNER + DSTATE)  g_Bm[m * DSTATE + (c - DINNER)] = v;
    else                           g_Cm[m * DSTATE + (c - DINNER - DSTATE)] = v;
}

// ---------------- dt = softplus(dt_raw + bias), dA = exp(-dt*exp(A_log)) ---
__global__ void dt_kernel(const float* __restrict__ dt_bias,
                          const float* __restrict__ A_log) {
    int idx = blockIdx.x * blockDim.x + threadIdx.x;
    if (idx >= MROWS * NHEADS) return;
    int h = idx % NHEADS;
    int m = idx / NHEADS;
    float x = g_zx[(size_t)m * DINPROJ + DINNER + CONVDIM + h] + dt_bias[h];
    float dt = (x > 20.f) ? x : log1pf(expf(x));
    g_dt[idx] = dt;
    g_dA[idx] = expf(-dt * expf(A_log[h]));
}

// ---------------- SSM scan: pipelined, n-split across 2 blocks -------------
// grid = 96: blockIdx.x = (b*NHEADS + h)*2 + half   (half = which 64 of n)
// 512 threads: ng = tid>>6 (8 n-groups of 8), p = tid&63 (head dim)
// 8 states per thread. One __syncthreads per step. Double-buffered inputs.
__global__ __launch_bounds__(512, 1)
void scan_kernel(const float* __restrict__ D_param) {
    int blk  = blockIdx.x;
    int half = blk & 1;
    int bh   = blk >> 1;
    int b = bh / NHEADS, h = bh % NHEADS;
    int tid = threadIdx.x;
    int ng  = tid >> 6;     // 0..7
    int p   = tid & 63;     // 0..63

    // buf layout: [0,64)=B-half  [64,128)=C-half  [128,192)=x  192=dt 193=dA
    __shared__ __align__(16) float buf[2][208];
    __shared__ float sY[2][8 * 68];   // pad 68 => conflict-free strided reads

    float s[8];
#pragma unroll
    for (int i = 0; i < 8; i++) s[i] = 0.f;
    float Dp = D_param[h];

    // ---- initial load (t = 0) ----
    {
        int m = b * SEQLEN;
        if (tid < 16) {
            float4 v = *(const float4*)(g_Bm + (size_t)m * DSTATE + half * 64 + tid * 4);
            *(float4*)(&buf[0][tid * 4]) = v;
        } else if (tid < 32) {
            float4 v = *(const float4*)(g_Cm + (size_t)m * DSTATE + half * 64 + (tid - 16) * 4);
            *(float4*)(&buf[0][tid * 4]) = v;
        } else if (tid < 48) {
            float4 v = *(const float4*)(g_X + (size_t)m * DINNER + h * HEADDIM + (tid - 32) * 4);
            *(float4*)(&buf[0][tid * 4]) = v;
        } else if (tid == 48) {
            buf[0][192] = g_dt[m * NHEADS + h];
            buf[0][193] = g_dA[m * NHEADS + h];
        }
    }
    __syncthreads();

    for (int t = 0; t < SEQLEN; t++) {
        int cur = t & 1;
        int m   = b * SEQLEN + t;

        // ---- prefetch t+1 into registers (no sync needed) ----
        float4 nv; float ndt = 0.f, ndA = 0.f;
        {
            int tn = (t + 1 < SEQLEN) ? t + 1 : t;
            int mn = b * SEQLEN + tn;
            if (tid < 16)
                nv = *(const float4*)(g_Bm + (size_t)mn * DSTATE + half * 64 + tid * 4);
            else if (tid < 32)
                nv = *(const float4*)(g_Cm + (size_t)mn * DSTATE + half * 64 + (tid - 16) * 4);
            else if (tid < 48)
                nv = *(const float4*)(g_X + (size_t)mn * DINNER + h * HEADDIM + (tid - 32) * 4);
            else if (tid == 48) {
                ndt = g_dt[mn * NHEADS + h];
                ndA = g_dA[mn * NHEADS + h];
            }
        }

        // ---- compute step t ----
        float dt = buf[cur][192];
        float dA = buf[cur][193];
        float xv = buf[cur][128 + p];
        float coef = dt * xv;
        const float4* B4 = (const float4*)(&buf[cur][ng * 8]);        // warp-broadcast
        const float4* C4 = (const float4*)(&buf[cur][64 + ng * 8]);   // warp-broadcast
        float acc = 0.f;
#pragma unroll
        for (int q = 0; q < 2; q++) {
            float4 Bv = B4[q];
            float4 Cv = C4[q];
            int i = q * 4;
            s[i+0] = s[i+0] * dA + coef * Bv.x;  acc += s[i+0] * Cv.x;
            s[i+1] = s[i+1] * dA + coef * Bv.y;  acc += s[i+1] * Cv.y;
            s[i+2] = s[i+2] * dA + coef * Bv.z;  acc += s[i+2] * Cv.z;
            s[i+3] = s[i+3] * dA + coef * Bv.w;  acc += s[i+3] * Cv.w;
        }
        sY[cur][ng * 68 + p] = acc;

        // ---- stage t+1 into the other buffer ----
        int nxt = cur ^ 1;
        if (tid < 48)       *(float4*)(&buf[nxt][tid * 4]) = nv;
        else if (tid == 48) { buf[nxt][192] = ndt; buf[nxt][193] = ndA; }

        __syncthreads();

        // ---- reduce y over the 8 n-groups (threads 0..63; p == tid) ----
        if (tid < 64) {
            float y = 0.f;
#pragma unroll
            for (int g = 0; g < 8; g++) y += sY[cur][g * 68 + tid];
            if (half == 0) y += Dp * xv;   // xv valid: p == tid
            float* dst = half ? g_Y1 : g_Y0;
            dst[(size_t)m * DINNER + h * HEADDIM + tid] = y;
        }
    }
}

// ---------------- gating: G = (Y0 + Y1) * silu(z) ---------------------------
__global__ void gate_kernel() {
    int idx = blockIdx.x * blockDim.x + threadIdx.x;
    if (idx >= MROWS * DINNER) return;
    int m = idx / DINNER, i = idx % DINNER;
    float z = g_zx[(size_t)m * DINPROJ + i];
    g_G[idx] = (g_Y0[idx] + g_Y1[idx]) * (z / (1.f + expf(-z)));
}

// ---------------- launch ----------------------------------------------------
extern "C" void kernel_launch(void* const* d_in, const int* in_sizes, int n_in,
                              void* d_out, int out_size) {
    const float* u       = (const float*)d_in[0];
    const float* W_in    = (const float*)d_in[1];
    const float* conv_w  = (const float*)d_in[2];
    const float* conv_b  = (const float*)d_in[3];
    const float* dt_bias = (const float*)d_in[4];
    const float* A_log   = (const float*)d_in[5];
    const float* D_param = (const float*)d_in[6];
    const float* W_out   = (const float*)d_in[7];
    float* out = (float*)d_out;

    float *zx, *G;
    cudaGetSymbolAddress((void**)&zx, g_zx);
    cudaGetSymbolAddress((void**)&G,  g_G);

    // 1. in-projection: (1024 x 768) @ (3352 x 768)^T
    {
        dim3 grid((DINPROJ + 63) / 64, MROWS / 64);
        gemm_nt<<<grid, 256>>>(u, W_in, zx, MROWS, DINPROJ, DMODEL);
    }
    // 2. causal conv + silu
    conv_kernel<<<(MROWS * CONVDIM + 255) / 256, 256>>>(conv_w, conv_b);
    // 3. dt / dA
    dt_kernel<<<(MROWS * NHEADS + 255) / 256, 256>>>(dt_bias, A_log);
    // 4. sequential scan (pipelined, n-split)
    scan_kernel<<<BATCH * NHEADS * 2, 512>>>(D_param);
    // 5. gate
    gate_kernel<<<(MROWS * DINNER + 255) / 256, 256>>>();
    // 6. out-projection: (1024 x 1536) @ (768 x 1536)^T
    {
        dim3 grid(DMODEL / 64, MROWS / 64);
        gemm_nt<<<grid, 256>>>(G, W_out, out, MROWS, DMODEL, DINNER);
    }
}

// round 3
// speedup vs baseline: 1.9289x; 1.2078x over previous
#include <cuda_runtime.h>
#include <math.h>

#define BATCH   2
#define SEQLEN  512
#define DMODEL  768
#define DINNER  1536
#define NHEADS  24
#define HEADDIM 64
#define DSTATE  128
#define CONVDIM 1792            // DINNER + 2*DSTATE
#define DINPROJ 3352            // 2*DINNER + 2*DSTATE + NHEADS
#define MROWS   (BATCH*SEQLEN)  // 1024
#define LC      64              // chunk length
#define NCHUNK  (SEQLEN/LC)     // 8
#define NBH     (BATCH*NHEADS)  // 48

// ---------------- scratch (device globals: no allocation allowed) ----------
__device__ float g_zx [MROWS * DINPROJ];  // in-projection result
__device__ float g_X  [MROWS * DINNER];   // conv-silu'd x
__device__ float g_Bm [MROWS * DSTATE];
__device__ float g_Cm [MROWS * DSTATE];
__device__ float g_dtv[NBH * SEQLEN];     // dt (softplus), [bh][t]
__device__ float g_cum[NBH * SEQLEN];     // within-chunk inclusive cumsum of dt*A
__device__ float g_Y0 [MROWS * DINNER];   // intra-chunk Y + D*x
__device__ float g_S  [NBH * NCHUNK * HEADDIM * DSTATE];  // chunk-local end states
__device__ float g_P  [NBH * NCHUNK * HEADDIM * DSTATE];  // state entering each chunk
__device__ float g_G  [MROWS * DINNER];   // gated output

// ---------------- generic NT GEMM: C[m,n] = sum_k A[m,k] * B[n,k] ----------
__global__ void gemm_nt(const float* __restrict__ A, const float* __restrict__ B,
                        float* __restrict__ C, int M, int N, int K) {
    const int BM = 64, BN = 64, BK = 16;
    __shared__ float As[BK][BM];
    __shared__ float Bs[BK][BN];
    int tid = threadIdx.x;
    int m0 = blockIdx.y * BM, n0 = blockIdx.x * BN;
    int tx = tid % 16, ty = tid / 16;
    float acc[4][4];
#pragma unroll
    for (int i = 0; i < 4; i++)
#pragma unroll
        for (int j = 0; j < 4; j++) acc[i][j] = 0.f;

    for (int k0 = 0; k0 < K; k0 += BK) {
#pragma unroll
        for (int e = tid; e < BM * BK; e += 256) {
            int r = e / BK, c = e % BK;
            int gm = m0 + r;
            As[c][r] = (gm < M) ? A[(size_t)gm * K + k0 + c] : 0.f;
        }
#pragma unroll
        for (int e = tid; e < BN * BK; e += 256) {
            int r = e / BK, c = e % BK;
            int gn = n0 + r;
            Bs[c][r] = (gn < N) ? B[(size_t)gn * K + k0 + c] : 0.f;
        }
        __syncthreads();
#pragma unroll
        for (int kk = 0; kk < BK; kk++) {
            float a[4], b[4];
#pragma unroll
            for (int i = 0; i < 4; i++) a[i] = As[kk][ty * 4 + i];
#pragma unroll
            for (int j = 0; j < 4; j++) b[j] = Bs[kk][tx * 4 + j];
#pragma unroll
            for (int i = 0; i < 4; i++)
#pragma unroll
                for (int j = 0; j < 4; j++) acc[i][j] += a[i] * b[j];
        }
        __syncthreads();
    }
#pragma unroll
    for (int i = 0; i < 4; i++) {
        int gm = m0 + ty * 4 + i;
        if (gm >= M) continue;
#pragma unroll
        for (int j = 0; j < 4; j++) {
            int gn = n0 + tx * 4 + j;
            if (gn < N) C[(size_t)gm * N + gn] = acc[i][j];
        }
    }
}

// ---------------- causal depthwise conv (width 4) + SiLU + split -----------
__global__ void conv_kernel(const float* __restrict__ conv_w,
                            const float* __restrict__ conv_b) {
    int idx = blockIdx.x * blockDim.x + threadIdx.x;
    if (idx >= MROWS * CONVDIM) return;
    int c = idx % CONVDIM;
    int m = idx / CONVDIM;
    int t = m % SEQLEN;
    float s = conv_b[c];
#pragma unroll
    for (int k = 0; k < 4; k++) {
        int tt = t - 3 + k;
        if (tt >= 0)
            s += g_zx[(size_t)(m - 3 + k) * DINPROJ + DINNER + c] * conv_w[c * 4 + k];
    }
    float v = s / (1.f + expf(-s));   // silu
    if (c < DINNER)                g_X [m * DINNER + c] = v;
    else if (c < DINNER + DSTATE)  g_Bm[m * DSTATE + (c - DINNER)] = v;
    else                           g_Cm[m * DSTATE + (c - DINNER - DSTATE)] = v;
}

// ---------------- dt = softplus, within-chunk cumsum of dt*A ---------------
// grid = NBH*NCHUNK, block = 64 (one chunk per block)
__global__ void dtcum_kernel(const float* __restrict__ dt_bias,
                             const float* __restrict__ A_log) {
    int g  = blockIdx.x;
    int c  = g & (NCHUNK - 1);
    int bh = g >> 3;                 // NCHUNK == 8
    int h  = bh % NHEADS;
    int b  = bh / NHEADS;
    int t  = threadIdx.x;            // 0..63
    int m  = b * SEQLEN + c * LC + t;

    float x   = g_zx[(size_t)m * DINPROJ + DINNER + CONVDIM + h] + dt_bias[h];
    float dtv = (x > 20.f) ? x : log1pf(expf(x));
    float a   = -expf(A_log[h]) * dtv;

    // inclusive scan across 64 threads (2 warps)
    float sc = a;
#pragma unroll
    for (int o = 1; o < 32; o <<= 1) {
        float v = __shfl_up_sync(0xffffffffu, sc, o);
        if ((t & 31) >= o) sc += v;
    }
    __shared__ float w0tot;
    if (t == 31) w0tot = sc;
    __syncthreads();
    if (t >= 32) sc += w0tot;

    int idx = bh * SEQLEN + c * LC + t;
    g_dtv[idx] = dtv;
    g_cum[idx] = sc;
}

// ---------------- intra-chunk kernel ---------------------------------------
// grid = NBH*NCHUNK (384), block = 256, dynamic smem.
// Computes Y_intra (+D*x) and the chunk-local end state S.
#define SB_STRIDE 132
#define SX_STRIDE 68
#define SMEMB_FLOATS (2*64*SB_STRIDE + 2*64*SX_STRIDE + 3*64)
__global__ __launch_bounds__(256)
void intra_kernel(const float* __restrict__ D_param) {
    extern __shared__ float sm[];
    float* sB   = sm;                          // 64 x 132
    float* sC   = sB + 64 * SB_STRIDE;         // 64 x 132
    float* sX   = sC + 64 * SB_STRIDE;         // 64 x 68
    float* sG   = sX + 64 * SX_STRIDE;         // 64 x 68
    float* sdt  = sG + 64 * SX_STRIDE;         // 64
    float* scum = sdt + 64;                    // 64
    float* sw   = scum + 64;                   // 64

    int g  = blockIdx.x;
    int c  = g & (NCHUNK - 1);
    int bh = g >> 3;
    int h  = bh % NHEADS;
    int b  = bh / NHEADS;
    int tid = threadIdx.x;
    int m0 = b * SEQLEN + c * LC;

    // ---- loads ----
    for (int i = tid; i < 64 * 32; i += 256) {
        int r = i >> 5, q = i & 31;
        *(float4*)(sB + r * SB_STRIDE + q * 4) =
            *(const float4*)(g_Bm + (size_t)(m0 + r) * DSTATE + q * 4);
        *(float4*)(sC + r * SB_STRIDE + q * 4) =
            *(const float4*)(g_Cm + (size_t)(m0 + r) * DSTATE + q * 4);
    }
    for (int i = tid; i < 64 * 16; i += 256) {
        int r = i >> 4, q = i & 15;
        *(float4*)(sX + r * SX_STRIDE + q * 4) =
            *(const float4*)(g_X + (size_t)(m0 + r) * DINNER + h * HEADDIM + q * 4);
    }
    if (tid < 64) {
        sdt[tid]  = g_dtv[bh * SEQLEN + c * LC + tid];
        scum[tid] = g_cum[bh * SEQLEN + c * LC + tid];
    }
    __syncthreads();
    if (tid < 64) sw[tid] = expf(scum[63] - scum[tid]) * sdt[tid];

    int tx = tid & 15, ty = tid >> 4;

    // ---- stage 1: G[t][s] = (s<=t) * exp(cum[t]-cum[s]) * dt[s] * (C_t . B_s)
    {
        float acc[4][4] = {};
        for (int kk = 0; kk < 128; kk += 4) {
            float4 a4[4], b4[4];
#pragma unroll
            for (int i = 0; i < 4; i++) a4[i] = *(float4*)(sC + (ty * 4 + i) * SB_STRIDE + kk);
#pragma unroll
            for (int j = 0; j < 4; j++) b4[j] = *(float4*)(sB + (tx * 4 + j) * SB_STRIDE + kk);
#pragma unroll
            for (int i = 0; i < 4; i++)
#pragma unroll
                for (int j = 0; j < 4; j++)
                    acc[i][j] += a4[i].x * b4[j].x + a4[i].y * b4[j].y
                               + a4[i].z * b4[j].z + a4[i].w * b4[j].w;
        }
#pragma unroll
        for (int i = 0; i < 4; i++) {
            int t_ = ty * 4 + i;
#pragma unroll
            for (int j = 0; j < 4; j++) {
                int s_ = tx * 4 + j;
                float wgt = (s_ <= t_) ? expf(scum[t_] - scum[s_]) * sdt[s_] : 0.f;
                sG[t_ * SX_STRIDE + s_] = acc[i][j] * wgt;
            }
        }
    }
    __syncthreads();

    // ---- stage 2: Y_intra = G @ X + D*x ----
    {
        float acc[4][4] = {};
        for (int kk = 0; kk < 64; kk++) {
            float a_[4];
#pragma unroll
            for (int i = 0; i < 4; i++) a_[i] = sG[(ty * 4 + i) * SX_STRIDE + kk];
            float4 b4 = *(float4*)(sX + kk * SX_STRIDE + tx * 4);
#pragma unroll
            for (int i = 0; i < 4; i++) {
                acc[i][0] += a_[i] * b4.x;
                acc[i][1] += a_[i] * b4.y;
                acc[i][2] += a_[i] * b4.z;
                acc[i][3] += a_[i] * b4.w;
            }
        }
        float Dp = D_param[h];
#pragma unroll
        for (int i = 0; i < 4; i++) {
            int t_ = ty * 4 + i;
#pragma unroll
            for (int j = 0; j < 4; j++) {
                int p_ = tx * 4 + j;
                g_Y0[(size_t)(m0 + t_) * DINNER + h * HEADDIM + p_] =
                    acc[i][j] + Dp * sX[t_ * SX_STRIDE + p_];
            }
        }
    }

    // ---- stage 3: S[p][n] = sum_s w[s]*X[s][p]*B[s][n]  (64 x 128) ----
    {
        float acc[4][8] = {};
        for (int kk = 0; kk < 64; kk++) {
            float wk = sw[kk];
            float a_[4];
#pragma unroll
            for (int i = 0; i < 4; i++) a_[i] = sX[kk * SX_STRIDE + ty * 4 + i] * wk;
            float4 b0 = *(float4*)(sB + kk * SB_STRIDE + tx * 8);
            float4 b1 = *(float4*)(sB + kk * SB_STRIDE + tx * 8 + 4);
#pragma unroll
            for (int i = 0; i < 4; i++) {
                acc[i][0] += a_[i] * b0.x;  acc[i][1] += a_[i] * b0.y;
                acc[i][2] += a_[i] * b0.z;  acc[i][3] += a_[i] * b0.w;
                acc[i][4] += a_[i] * b1.x;  acc[i][5] += a_[i] * b1.y;
                acc[i][6] += a_[i] * b1.z;  acc[i][7] += a_[i] * b1.w;
            }
        }
        size_t base = (size_t)(bh * NCHUNK + c) * (HEADDIM * DSTATE);
#pragma unroll
        for (int i = 0; i < 4; i++) {
            int p_ = ty * 4 + i;
#pragma unroll
            for (int j = 0; j < 8; j++) {
                int n_ = tx * 8 + j;
                g_S[base + p_ * DSTATE + n_] = acc[i][j];
            }
        }
    }
}

// ---------------- inter-chunk state scan (8 steps) --------------------------
// grid = NBH (48), block = 512; each thread owns 16 state elements.
__global__ void chunkscan_kernel() {
    int bh  = blockIdx.x;
    int tid = threadIdx.x;
    float4 E[4];
#pragma unroll
    for (int i = 0; i < 4; i++) E[i] = make_float4(0.f, 0.f, 0.f, 0.f);
    size_t base = (size_t)bh * NCHUNK * (HEADDIM * DSTATE);
    for (int k = 0; k < NCHUNK; k++) {
        float dAk = expf(g_cum[bh * SEQLEN + k * LC + (LC - 1)]);
        size_t off = base + (size_t)k * (HEADDIM * DSTATE) + tid * 16;
#pragma unroll
        for (int i = 0; i < 4; i++) {
            *(float4*)(g_P + off + i * 4) = E[i];
            float4 s = *(const float4*)(g_S + off + i * 4);
            E[i].x = s.x + dAk * E[i].x;
            E[i].y = s.y + dAk * E[i].y;
            E[i].z = s.z + dAk * E[i].z;
            E[i].w = s.w + dAk * E[i].w;
        }
    }
}

// ---------------- inter-chunk Y + gating ------------------------------------
// grid = NBH*NCHUNK (384), block = 256, dynamic smem.
// Y[t][p] = Y_intra + exp(cum[t]) * sum_n C[t][n] * P[p][n]; G = Y * silu(z)
#define SMEMD_FLOATS (2*64*SB_STRIDE + 64)
__global__ __launch_bounds__(256)
void inter_gate_kernel() {
    extern __shared__ float sm[];
    float* sC   = sm;                   // 64 x 132
    float* sP   = sC + 64 * SB_STRIDE;  // 64 x 132
    float* scum = sP + 64 * SB_STRIDE;  // 64

    int g  = blockIdx.x;
    int c  = g & (NCHUNK - 1);
    int bh = g >> 3;
    int h  = bh % NHEADS;
    int b  = bh / NHEADS;
    int tid = threadIdx.x;
    int m0 = b * SEQLEN + c * LC;
    size_t pbase = (size_t)(bh * NCHUNK + c) * (HEADDIM * DSTATE);

    for (int i = tid; i < 64 * 32; i += 256) {
        int r = i >> 5, q = i & 31;
        *(float4*)(sC + r * SB_STRIDE + q * 4) =
            *(const float4*)(g_Cm + (size_t)(m0 + r) * DSTATE + q * 4);
        *(float4*)(sP + r * SB_STRIDE + q * 4) =
            *(const float4*)(g_P + pbase + r * DSTATE + q * 4);
    }
    if (tid < 64) scum[tid] = g_cum[bh * SEQLEN + c * LC + tid];
    __syncthreads();

    int tx = tid & 15, ty = tid >> 4;
    float acc[4][4] = {};
    for (int n = 0; n < 128; n += 4) {
        float4 a4[4], b4[4];
#pragma unroll
        for (int i = 0; i < 4; i++) a4[i] = *(float4*)(sC + (ty * 4 + i) * SB_STRIDE + n);
#pragma unroll
        for (int j = 0; j < 4; j++) b4[j] = *(float4*)(sP + (tx * 4 + j) * SB_STRIDE + n);
#pragma unroll
        for (int i = 0; i < 4; i++)
#pragma unroll
            for (int j = 0; j < 4; j++)
                acc[i][j] += a4[i].x * b4[j].x + a4[i].y * b4[j].y
                           + a4[i].z * b4[j].z + a4[i].w * b4[j].w;
    }
#pragma unroll
    for (int i = 0; i < 4; i++) {
        int t_ = ty * 4 + i;
        float dec = expf(scum[t_]);
#pragma unroll
        for (int j = 0; j < 4; j++) {
            int p_ = tx * 4 + j;
            size_t mi = (size_t)(m0 + t_) * DINNER + h * HEADDIM + p_;
            float y = g_Y0[mi] + dec * acc[i][j];
            float z = g_zx[(size_t)(m0 + t_) * DINPROJ + h * HEADDIM + p_];
            g_G[mi] = y * (z / (1.f + expf(-z)));
        }
    }
}

// ---------------- launch ----------------------------------------------------
extern "C" void kernel_launch(void* const* d_in, const int* in_sizes, int n_in,
                              void* d_out, int out_size) {
    const float* u       = (const float*)d_in[0];
    const float* W_in    = (const float*)d_in[1];
    const float* conv_w  = (const float*)d_in[2];
    const float* conv_b  = (const float*)d_in[3];
    const float* dt_bias = (const float*)d_in[4];
    const float* A_log   = (const float*)d_in[5];
    const float* D_param = (const float*)d_in[6];
    const float* W_out   = (const float*)d_in[7];
    float* out = (float*)d_out;

    float *zx, *G;
    cudaGetSymbolAddress((void**)&zx, g_zx);
    cudaGetSymbolAddress((void**)&G,  g_G);

    static bool attr_done = false;
    if (!attr_done) {
        cudaFuncSetAttribute(intra_kernel, cudaFuncAttributeMaxDynamicSharedMemorySize,
                             SMEMB_FLOATS * sizeof(float));
        cudaFuncSetAttribute(inter_gate_kernel, cudaFuncAttributeMaxDynamicSharedMemorySize,
                             SMEMD_FLOATS * sizeof(float));
        attr_done = true;
    }

    // 1. in-projection: (1024 x 768) @ (3352 x 768)^T
    {
        dim3 grid((DINPROJ + 63) / 64, MROWS / 64);
        gemm_nt<<<grid, 256>>>(u, W_in, zx, MROWS, DINPROJ, DMODEL);
    }
    // 2. causal conv + silu
    conv_kernel<<<(MROWS * CONVDIM + 255) / 256, 256>>>(conv_w, conv_b);
    // 3. dt + within-chunk cumsum
    dtcum_kernel<<<NBH * NCHUNK, 64>>>(dt_bias, A_log);
    // 4. intra-chunk (Y_intra + chunk states)
    intra_kernel<<<NBH * NCHUNK, 256, SMEMB_FLOATS * sizeof(float)>>>(D_param);
    // 5. inter-chunk state scan
    chunkscan_kernel<<<NBH, 512>>>();
    // 6. inter-chunk Y + gating
    inter_gate_kernel<<<NBH * NCHUNK, 256, SMEMD_FLOATS * sizeof(float)>>>();
    // 7. out-projection: (1024 x 1536) @ (768 x 1536)^T
    {
        dim3 grid(DMODEL / 64, MROWS / 64);
        gemm_nt<<<grid, 256>>>(G, W_out, out, MROWS, DMODEL, DINNER);
    }
}

// round 5
// speedup vs baseline: 3.8130x; 1.9768x over previous
#include <cuda_runtime.h>
#include <cuda_bf16.h>
#include <math.h>
#include <cstdint>

#define BATCH   2
#define SEQLEN  512
#define DMODEL  768
#define DINNER  1536
#define NHEADS  24
#define HEADDIM 64
#define DSTATE  128
#define CONVDIM 1792            // DINNER + 2*DSTATE
#define DINPROJ 3352            // 2*DINNER + 2*DSTATE + NHEADS
#define MROWS   (BATCH*SEQLEN)  // 1024
#define LC      64              // chunk length
#define NCHUNK  (SEQLEN/LC)     // 8
#define NBH     (BATCH*NHEADS)  // 48
#define NPAD_IN 3456            // 27*128 (padded DINPROJ)

// ---------------- scratch (device globals: no allocation allowed) ----------
__device__ float g_zx [MROWS * DINPROJ];
__device__ float g_X  [MROWS * DINNER];
__device__ float g_Bm [MROWS * DSTATE];
__device__ float g_Cm [MROWS * DSTATE];
__device__ float g_dtv[NBH * SEQLEN];
__device__ float g_cum[NBH * SEQLEN];
__device__ float g_Y0 [MROWS * DINNER];
__device__ float g_S  [NBH * NCHUNK * HEADDIM * DSTATE];
__device__ float g_P  [NBH * NCHUNK * HEADDIM * DSTATE];
__device__ float g_G  [MROWS * DINNER];

// bf16 hi/lo splits (16B-aligned for cp.async)
__device__ __align__(256) __nv_bfloat16 g_uhi[MROWS * DMODEL],   g_ulo[MROWS * DMODEL];
__device__ __align__(256) __nv_bfloat16 g_wih[NPAD_IN * DMODEL], g_wil[NPAD_IN * DMODEL];
__device__ __align__(256) __nv_bfloat16 g_ghi[MROWS * DINNER],   g_glo[MROWS * DINNER];
__device__ __align__(256) __nv_bfloat16 g_woh[DMODEL * DINNER],  g_wol[DMODEL * DINNER];

// ================= helpers =================================================
__device__ __forceinline__ uint32_t smem_u32(const void* p) {
    uint32_t a;
    asm("{ .reg .u64 t; cvta.to.shared.u64 t, %1; cvt.u32.u64 %0, t; }"
        : "=r"(a) : "l"(p));
    return a;
}
__device__ __forceinline__ void ldsm_x4(uint32_t* r, uint32_t addr) {
    asm volatile("ldmatrix.sync.aligned.m8n8.x4.shared.b16 {%0,%1,%2,%3}, [%4];"
                 : "=r"(r[0]), "=r"(r[1]), "=r"(r[2]), "=r"(r[3]) : "r"(addr));
}
__device__ __forceinline__ void ldsm_x2(uint32_t* r, uint32_t addr) {
    asm volatile("ldmatrix.sync.aligned.m8n8.x2.shared.b16 {%0,%1}, [%2];"
                 : "=r"(r[0]), "=r"(r[1]) : "r"(addr));
}
__device__ __forceinline__ void mma_bf16(float* c, const uint32_t* a, const uint32_t* b) {
    asm volatile(
        "mma.sync.aligned.m16n8k16.row.col.f32.bf16.bf16.f32 "
        "{%0,%1,%2,%3}, {%4,%5,%6,%7}, {%8,%9}, {%0,%1,%2,%3};"
        : "+f"(c[0]), "+f"(c[1]), "+f"(c[2]), "+f"(c[3])
        : "r"(a[0]), "r"(a[1]), "r"(a[2]), "r"(a[3]), "r"(b[0]), "r"(b[1]));
}

// ================= split fp32 -> (hi, lo) bf16 =============================
__global__ void split_kernel(const float* __restrict__ src,
                             __nv_bfloat16* __restrict__ hi,
                             __nv_bfloat16* __restrict__ lo,
                             int n_src, int n_total) {
    int i = blockIdx.x * blockDim.x + threadIdx.x;
    if (i >= n_total) return;
    float v = (i < n_src) ? src[i] : 0.f;
    __nv_bfloat16 h = __float2bfloat16(v);
    hi[i] = h;
    lo[i] = __float2bfloat16(v - __bfloat162float(h));
}

// ================= mma.sync bf16 GEMM (3-term compensated) =================
// C[m,n] = sum_k A[m,k]*B[n,k].  Tile 128x128, BK=16, 256 thr (8 warps 2x4,
// warp tile 64x32). hi*hi + hi*lo + lo*hi.
// smem per stage: Ahi,Alo,Bhi,Blo, each 128 rows x 16 bf16, stride 24 (48B).
#define GSTRIDE 24
#define GOP_BYTES (128 * GSTRIDE * 2)      // 6144
#define GSTAGE_BYTES (4 * GOP_BYTES)       // 24576
__global__ __launch_bounds__(256, 1)
void mma_gemm(const __nv_bfloat16* __restrict__ Ahi, const __nv_bfloat16* __restrict__ Alo,
              const __nv_bfloat16* __restrict__ Bhi, const __nv_bfloat16* __restrict__ Blo,
              float* __restrict__ C, int K, int Nact, int ldc) {
    extern __shared__ char smx[];
    uint32_t sb = smem_u32(smx);
    int tid  = threadIdx.x;
    int lane = tid & 31, wid = tid >> 5;
    int wm = wid >> 2, wn = wid & 3;            // 2 x 4 warp grid
    int m0 = blockIdx.y * 128, n0 = blockIdx.x * 128;
    const int KT = K / 16;

    const __nv_bfloat16* ptrs[4] = {Ahi, Alo, Bhi, Blo};
    int rbase[4] = {m0, m0, n0, n0};

    // loader: 256 chunks of 16B per operand (row r, 16B-half h)
    auto load_stage = [&](int kt, int s) {
        uint32_t sbase = sb + s * GSTAGE_BYTES;
#pragma unroll
        for (int op = 0; op < 4; op++) {
            int r = tid >> 1, hf = tid & 1;
            const void* g = ptrs[op] + (size_t)(rbase[op] + r) * K + kt * 16 + hf * 8;
            uint32_t d = sbase + op * GOP_BYTES + (r * GSTRIDE + hf * 8) * 2;
            asm volatile("cp.async.cg.shared.global [%0], [%1], 16;" :: "r"(d), "l"(g));
        }
        asm volatile("cp.async.commit_group;");
    };

    float acc[4][4][4];
#pragma unroll
    for (int i = 0; i < 4; i++)
#pragma unroll
        for (int j = 0; j < 4; j++)
#pragma unroll
            for (int q = 0; q < 4; q++) acc[i][j][q] = 0.f;

    load_stage(0, 0);

    for (int kt = 0; kt < KT; kt++) {
        int cur = kt & 1;
        if (kt + 1 < KT) {
            load_stage(kt + 1, cur ^ 1);
            asm volatile("cp.async.wait_group 1;");
        } else {
            asm volatile("cp.async.wait_group 0;");
        }
        __syncthreads();

        uint32_t st = sb + cur * GSTAGE_BYTES;
        // A fragments (hi & lo): 4 m16 tiles
        uint32_t ah[4][4], al[4][4], bh[4][2], bl[4][2];
        int arow = wm * 64 + (lane & 15);
        int acol = (lane >> 4) * 8;
#pragma unroll
        for (int i = 0; i < 4; i++) {
            uint32_t off = ((arow + i * 16) * GSTRIDE + acol) * 2;
            ldsm_x4(ah[i], st + off);
            ldsm_x4(al[i], st + GOP_BYTES + off);
        }
        int brow = wn * 32 + (lane & 7);
        int bcol = ((lane >> 3) & 1) * 8;
#pragma unroll
        for (int j = 0; j < 4; j++) {
            uint32_t off = ((brow + j * 8) * GSTRIDE + bcol) * 2;
            ldsm_x2(bh[j], st + 2 * GOP_BYTES + off);
            ldsm_x2(bl[j], st + 3 * GOP_BYTES + off);
        }
#pragma unroll
        for (int i = 0; i < 4; i++)
#pragma unroll
            for (int j = 0; j < 4; j++) {
                mma_bf16(acc[i][j], ah[i], bh[j]);
                mma_bf16(acc[i][j], ah[i], bl[j]);
                mma_bf16(acc[i][j], al[i], bh[j]);
            }
        __syncthreads();
    }

    // epilogue
    int r0 = m0 + wm * 64 + (lane >> 2);
    int c0 = n0 + wn * 32 + (lane & 3) * 2;
#pragma unroll
    for (int i = 0; i < 4; i++) {
#pragma unroll
        for (int j = 0; j < 4; j++) {
            int rr = r0 + i * 16;
            int cc = c0 + j * 8;
            if (cc < Nact)     C[(size_t)rr * ldc + cc]           = acc[i][j][0];
            if (cc + 1 < Nact) C[(size_t)rr * ldc + cc + 1]       = acc[i][j][1];
            if (cc < Nact)     C[(size_t)(rr + 8) * ldc + cc]     = acc[i][j][2];
            if (cc + 1 < Nact) C[(size_t)(rr + 8) * ldc + cc + 1] = acc[i][j][3];
        }
    }
}

// ---------------- causal depthwise conv (width 4) + SiLU + split -----------
__global__ void conv_kernel(const float* __restrict__ conv_w,
                            const float* __restrict__ conv_b) {
    int idx = blockIdx.x * blockDim.x + threadIdx.x;
    if (idx >= MROWS * CONVDIM) return;
    int c = idx % CONVDIM;
    int m = idx / CONVDIM;
    int t = m % SEQLEN;
    float s = conv_b[c];
#pragma unroll
    for (int k = 0; k < 4; k++) {
        int tt = t - 3 + k;
        if (tt >= 0)
            s += g_zx[(size_t)(m - 3 + k) * DINPROJ + DINNER + c] * conv_w[c * 4 + k];
    }
    float v = s / (1.f + expf(-s));
    if (c < DINNER)                g_X [m * DINNER + c] = v;
    else if (c < DINNER + DSTATE)  g_Bm[m * DSTATE + (c - DINNER)] = v;
    else                           g_Cm[m * DSTATE + (c - DINNER - DSTATE)] = v;
}

// ---------------- dt = softplus, within-chunk cumsum of dt*A ---------------
__global__ void dtcum_kernel(const float* __restrict__ dt_bias,
                             const float* __restrict__ A_log) {
    int g  = blockIdx.x;
    int c  = g & (NCHUNK - 1);
    int bh = g >> 3;
    int h  = bh % NHEADS;
    int b  = bh / NHEADS;
    int t  = threadIdx.x;
    int m  = b * SEQLEN + c * LC + t;

    float x   = g_zx[(size_t)m * DINPROJ + DINNER + CONVDIM + h] + dt_bias[h];
    float dtv = (x > 20.f) ? x : log1pf(expf(x));
    float a   = -expf(A_log[h]) * dtv;

    float sc = a;
#pragma unroll
    for (int o = 1; o < 32; o <<= 1) {
        float v = __shfl_up_sync(0xffffffffu, sc, o);
        if ((t & 31) >= o) sc += v;
    }
    __shared__ float w0tot;
    if (t == 31) w0tot = sc;
    __syncthreads();
    if (t >= 32) sc += w0tot;

    int idx = bh * SEQLEN + c * LC + t;
    g_dtv[idx] = dtv;
    g_cum[idx] = sc;
}

// ---------------- intra-chunk kernel ---------------------------------------
#define SB_STRIDE 132
#define SX_STRIDE 68
#define SMEMB_FLOATS (2*64*SB_STRIDE + 2*64*SX_STRIDE + 3*64)
__global__ __launch_bounds__(256)
void intra_kernel(const float* __restrict__ D_param) {
    extern __shared__ float sm[];
    float* sB   = sm;
    float* sC   = sB + 64 * SB_STRIDE;
    float* sX   = sC + 64 * SB_STRIDE;
    float* sG   = sX + 64 * SX_STRIDE;
    float* sdt  = sG + 64 * SX_STRIDE;
    float* scum = sdt + 64;
    float* sw   = scum + 64;

    int g  = blockIdx.x;
    int c  = g & (NCHUNK - 1);
    int bh = g >> 3;
    int h  = bh % NHEADS;
    int b  = bh / NHEADS;
    int tid = threadIdx.x;
    int m0 = b * SEQLEN + c * LC;

    for (int i = tid; i < 64 * 32; i += 256) {
        int r = i >> 5, q = i & 31;
        *(float4*)(sB + r * SB_STRIDE + q * 4) =
            *(const float4*)(g_Bm + (size_t)(m0 + r) * DSTATE + q * 4);
        *(float4*)(sC + r * SB_STRIDE + q * 4) =
            *(const float4*)(g_Cm + (size_t)(m0 + r) * DSTATE + q * 4);
    }
    for (int i = tid; i < 64 * 16; i += 256) {
        int r = i >> 4, q = i & 15;
        *(float4*)(sX + r * SX_STRIDE + q * 4) =
            *(const float4*)(g_X + (size_t)(m0 + r) * DINNER + h * HEADDIM + q * 4);
    }
    if (tid < 64) {
        sdt[tid]  = g_dtv[bh * SEQLEN + c * LC + tid];
        scum[tid] = g_cum[bh * SEQLEN + c * LC + tid];
    }
    __syncthreads();
    if (tid < 64) sw[tid] = expf(scum[63] - scum[tid]) * sdt[tid];

    int tx = tid & 15, ty = tid >> 4;

    {   // G[t][s]
        float acc[4][4] = {};
        for (int kk = 0; kk < 128; kk += 4) {
            float4 a4[4], b4[4];
#pragma unroll
            for (int i = 0; i < 4; i++) a4[i] = *(float4*)(sC + (ty * 4 + i) * SB_STRIDE + kk);
#pragma unroll
            for (int j = 0; j < 4; j++) b4[j] = *(float4*)(sB + (tx * 4 + j) * SB_STRIDE + kk);
#pragma unroll
            for (int i = 0; i < 4; i++)
#pragma unroll
                for (int j = 0; j < 4; j++)
                    acc[i][j] += a4[i].x * b4[j].x + a4[i].y * b4[j].y
                               + a4[i].z * b4[j].z + a4[i].w * b4[j].w;
        }
#pragma unroll
        for (int i = 0; i < 4; i++) {
            int t_ = ty * 4 + i;
#pragma unroll
            for (int j = 0; j < 4; j++) {
                int s_ = tx * 4 + j;
                float wgt = (s_ <= t_) ? expf(scum[t_] - scum[s_]) * sdt[s_] : 0.f;
                sG[t_ * SX_STRIDE + s_] = acc[i][j] * wgt;
            }
        }
    }
    __syncthreads();

    {   // Y_intra = G @ X + D*x
        float acc[4][4] = {};
        for (int kk = 0; kk < 64; kk++) {
            float a_[4];
#pragma unroll
            for (int i = 0; i < 4; i++) a_[i] = sG[(ty * 4 + i) * SX_STRIDE + kk];
            float4 b4 = *(float4*)(sX + kk * SX_STRIDE + tx * 4);
#pragma unroll
            for (int i = 0; i < 4; i++) {
                acc[i][0] += a_[i] * b4.x;
                acc[i][1] += a_[i] * b4.y;
                acc[i][2] += a_[i] * b4.z;
                acc[i][3] += a_[i] * b4.w;
            }
        }
        float Dp = D_param[h];
#pragma unroll
        for (int i = 0; i < 4; i++) {
            int t_ = ty * 4 + i;
#pragma unroll
            for (int j = 0; j < 4; j++) {
                int p_ = tx * 4 + j;
                g_Y0[(size_t)(m0 + t_) * DINNER + h * HEADDIM + p_] =
                    acc[i][j] + Dp * sX[t_ * SX_STRIDE + p_];
            }
        }
    }

    {   // S[p][n]
        float acc[4][8] = {};
        for (int kk = 0; kk < 64; kk++) {
            float wk = sw[kk];
            float a_[4];
#pragma unroll
            for (int i = 0; i < 4; i++) a_[i] = sX[kk * SX_STRIDE + ty * 4 + i] * wk;
            float4 b0 = *(float4*)(sB + kk * SB_STRIDE + tx * 8);
            float4 b1 = *(float4*)(sB + kk * SB_STRIDE + tx * 8 + 4);
#pragma unroll
            for (int i = 0; i < 4; i++) {
                acc[i][0] += a_[i] * b0.x;  acc[i][1] += a_[i] * b0.y;
                acc[i][2] += a_[i] * b0.z;  acc[i][3] += a_[i] * b0.w;
                acc[i][4] += a_[i] * b1.x;  acc[i][5] += a_[i] * b1.y;
                acc[i][6] += a_[i] * b1.z;  acc[i][7] += a_[i] * b1.w;
            }
        }
        size_t base = (size_t)(bh * NCHUNK + c) * (HEADDIM * DSTATE);
#pragma unroll
        for (int i = 0; i < 4; i++) {
            int p_ = ty * 4 + i;
#pragma unroll
            for (int j = 0; j < 8; j++) {
                int n_ = tx * 8 + j;
                g_S[base + p_ * DSTATE + n_] = acc[i][j];
            }
        }
    }
}

// ---------------- inter-chunk state scan (8 steps) --------------------------
__global__ void chunkscan_kernel() {
    int bh  = blockIdx.x;
    int tid = threadIdx.x;
    float4 E[4];
#pragma unroll
    for (int i = 0; i < 4; i++) E[i] = make_float4(0.f, 0.f, 0.f, 0.f);
    size_t base = (size_t)bh * NCHUNK * (HEADDIM * DSTATE);
    for (int k = 0; k < NCHUNK; k++) {
        float dAk = expf(g_cum[bh * SEQLEN + k * LC + (LC - 1)]);
        size_t off = base + (size_t)k * (HEADDIM * DSTATE) + tid * 16;
#pragma unroll
        for (int i = 0; i < 4; i++) {
            *(float4*)(g_P + off + i * 4) = E[i];
            float4 s = *(const float4*)(g_S + off + i * 4);
            E[i].x = s.x + dAk * E[i].x;
            E[i].y = s.y + dAk * E[i].y;
            E[i].z = s.z + dAk * E[i].z;
            E[i].w = s.w + dAk * E[i].w;
        }
    }
}

// ---------------- inter-chunk Y + gating ------------------------------------
#define SMEMD_FLOATS (2*64*SB_STRIDE + 64)
__global__ __launch_bounds__(256)
void inter_gate_kernel() {
    extern __shared__ float sm[];
    float* sC   = sm;
    float* sP   = sC + 64 * SB_STRIDE;
    float* scum = sP + 64 * SB_STRIDE;

    int g  = blockIdx.x;
    int c  = g & (NCHUNK - 1);
    int bh = g >> 3;
    int h  = bh % NHEADS;
    int b  = bh / NHEADS;
    int tid = threadIdx.x;
    int m0 = b * SEQLEN + c * LC;
    size_t pbase = (size_t)(bh * NCHUNK + c) * (HEADDIM * DSTATE);

    for (int i = tid; i < 64 * 32; i += 256) {
        int r = i >> 5, q = i & 31;
        *(float4*)(sC + r * SB_STRIDE + q * 4) =
            *(const float4*)(g_Cm + (size_t)(m0 + r) * DSTATE + q * 4);
        *(float4*)(sP + r * SB_STRIDE + q * 4) =
            *(const float4*)(g_P + pbase + r * DSTATE + q * 4);
    }
    if (tid < 64) scum[tid] = g_cum[bh * SEQLEN + c * LC + tid];
    __syncthreads();

    int tx = tid & 15, ty = tid >> 4;
    float acc[4][4] = {};
    for (int n = 0; n < 128; n += 4) {
        float4 a4[4], b4[4];
#pragma unroll
        for (int i = 0; i < 4; i++) a4[i] = *(float4*)(sC + (ty * 4 + i) * SB_STRIDE + n);
#pragma unroll
        for (int j = 0; j < 4; j++) b4[j] = *(float4*)(sP + (tx * 4 + j) * SB_STRIDE + n);
#pragma unroll
        for (int i = 0; i < 4; i++)
#pragma unroll
            for (int j = 0; j < 4; j++)
                acc[i][j] += a4[i].x * b4[j].x + a4[i].y * b4[j].y
                           + a4[i].z * b4[j].z + a4[i].w * b4[j].w;
    }
#pragma unroll
    for (int i = 0; i < 4; i++) {
        int t_ = ty * 4 + i;
        float dec = expf(scum[t_]);
#pragma unroll
        for (int j = 0; j < 4; j++) {
            int p_ = tx * 4 + j;
            size_t mi = (size_t)(m0 + t_) * DINNER + h * HEADDIM + p_;
            float y = g_Y0[mi] + dec * acc[i][j];
            float z = g_zx[(size_t)(m0 + t_) * DINPROJ + h * HEADDIM + p_];
            g_G[mi] = y * (z / (1.f + expf(-z)));
        }
    }
}

// ---------------- launch ----------------------------------------------------
extern "C" void kernel_launch(void* const* d_in, const int* in_sizes, int n_in,
                              void* d_out, int out_size) {
    const float* u       = (const float*)d_in[0];
    const float* W_in    = (const float*)d_in[1];
    const float* conv_w  = (const float*)d_in[2];
    const float* conv_b  = (const float*)d_in[3];
    const float* dt_bias = (const float*)d_in[4];
    const float* A_log   = (const float*)d_in[5];
    const float* D_param = (const float*)d_in[6];
    const float* W_out   = (const float*)d_in[7];
    float* out = (float*)d_out;

    float *zx, *G;
    cudaGetSymbolAddress((void**)&zx, g_zx);
    cudaGetSymbolAddress((void**)&G,  g_G);
    __nv_bfloat16 *uhi, *ulo, *wih, *wil, *ghi, *glo, *woh, *wol;
    cudaGetSymbolAddress((void**)&uhi, g_uhi);  cudaGetSymbolAddress((void**)&ulo, g_ulo);
    cudaGetSymbolAddress((void**)&wih, g_wih);  cudaGetSymbolAddress((void**)&wil, g_wil);
    cudaGetSymbolAddress((void**)&ghi, g_ghi);  cudaGetSymbolAddress((void**)&glo, g_glo);
    cudaGetSymbolAddress((void**)&woh, g_woh);  cudaGetSymbolAddress((void**)&wol, g_wol);

    static bool attr_done = false;
    if (!attr_done) {
        cudaFuncSetAttribute(intra_kernel, cudaFuncAttributeMaxDynamicSharedMemorySize,
                             SMEMB_FLOATS * sizeof(float));
        cudaFuncSetAttribute(inter_gate_kernel, cudaFuncAttributeMaxDynamicSharedMemorySize,
                             SMEMD_FLOATS * sizeof(float));
        cudaFuncSetAttribute(mma_gemm, cudaFuncAttributeMaxDynamicSharedMemorySize,
                             2 * GSTAGE_BYTES);
        attr_done = true;
    }
    const int TC_SMEM = 2 * GSTAGE_BYTES;  // 49152

    // 0. split inputs/weights to bf16 hi/lo
    {
        int n1 = MROWS * DMODEL;
        split_kernel<<<(n1 + 255) / 256, 256>>>(u, uhi, ulo, n1, n1);
        int n2s = DINPROJ * DMODEL, n2t = NPAD_IN * DMODEL;
        split_kernel<<<(n2t + 255) / 256, 256>>>(W_in, wih, wil, n2s, n2t);
        int n3 = DMODEL * DINNER;
        split_kernel<<<(n3 + 255) / 256, 256>>>(W_out, woh, wol, n3, n3);
    }
    // 1. in-projection (tensor cores): (1024 x 768) @ (3456p x 768)^T -> zx
    {
        dim3 grid(NPAD_IN / 128, MROWS / 128);
        mma_gemm<<<grid, 256, TC_SMEM>>>(uhi, ulo, wih, wil, zx, DMODEL, DINPROJ, DINPROJ);
    }
    // 2. causal conv + silu
    conv_kernel<<<(MROWS * CONVDIM + 255) / 256, 256>>>(conv_w, conv_b);
    // 3. dt + within-chunk cumsum
    dtcum_kernel<<<NBH * NCHUNK, 64>>>(dt_bias, A_log);
    // 4. intra-chunk
    intra_kernel<<<NBH * NCHUNK, 256, SMEMB_FLOATS * sizeof(float)>>>(D_param);
    // 5. inter-chunk state scan
    chunkscan_kernel<<<NBH, 512>>>();
    // 6. inter-chunk Y + gating
    inter_gate_kernel<<<NBH * NCHUNK, 256, SMEMD_FLOATS * sizeof(float)>>>();
    // 7. split gated activations, out-projection (tensor cores)
    {
        int n4 = MROWS * DINNER;
        split_kernel<<<(n4 + 255) / 256, 256>>>(G, ghi, glo, n4, n4);
        dim3 grid(DMODEL / 128, MROWS / 128);
        mma_gemm<<<grid, 256, TC_SMEM>>>(ghi, glo, woh, wol, out, DINNER, DMODEL, DMODEL);
    }
}

// round 6
// speedup vs baseline: 4.7596x; 1.2483x over previous
#include <cuda_runtime.h>
#include <cuda_bf16.h>
#include <math.h>
#include <cstdint>

#define BATCH   2
#define SEQLEN  512
#define DMODEL  768
#define DINNER  1536
#define NHEADS  24
#define HEADDIM 64
#define DSTATE  128
#define CONVDIM 1792            // DINNER + 2*DSTATE
#define DINPROJ 3352            // 2*DINNER + 2*DSTATE + NHEADS
#define MROWS   (BATCH*SEQLEN)  // 1024
#define LC      64
#define NCHUNK  (SEQLEN/LC)     // 8
#define NBH     (BATCH*NHEADS)  // 48
#define NPAD_IN 3456            // padded DINPROJ
#define NSPLIT  4               // split-K factor for out-proj

// ---------------- scratch ---------------------------------------------------
__device__ float g_zx [MROWS * DINPROJ];
__device__ float g_X  [MROWS * DINNER];
__device__ float g_Bm [MROWS * DSTATE];
__device__ float g_Cm [MROWS * DSTATE];
__device__ float g_dtv[NBH * SEQLEN];
__device__ float g_cum[NBH * SEQLEN];
__device__ float g_Y0 [MROWS * DINNER];
__device__ float g_S  [NBH * NCHUNK * HEADDIM * DSTATE];
__device__ float g_P  [NBH * NCHUNK * HEADDIM * DSTATE];
__device__ float g_pp [NSPLIT * MROWS * DMODEL];   // split-K partials

__device__ __align__(256) __nv_bfloat16 g_uhi[MROWS * DMODEL],   g_ulo[MROWS * DMODEL];
__device__ __align__(256) __nv_bfloat16 g_wih[NPAD_IN * DMODEL], g_wil[NPAD_IN * DMODEL];
__device__ __align__(256) __nv_bfloat16 g_ghi[MROWS * DINNER],   g_glo[MROWS * DINNER];
__device__ __align__(256) __nv_bfloat16 g_woh[DMODEL * DINNER],  g_wol[DMODEL * DINNER];

// ================= helpers =================================================
__device__ __forceinline__ uint32_t smem_u32(const void* p) {
    uint32_t a;
    asm("{ .reg .u64 t; cvta.to.shared.u64 t, %1; cvt.u32.u64 %0, t; }"
        : "=r"(a) : "l"(p));
    return a;
}
__device__ __forceinline__ void ldsm_x4(uint32_t* r, uint32_t addr) {
    asm volatile("ldmatrix.sync.aligned.m8n8.x4.shared.b16 {%0,%1,%2,%3}, [%4];"
                 : "=r"(r[0]), "=r"(r[1]), "=r"(r[2]), "=r"(r[3]) : "r"(addr));
}
__device__ __forceinline__ void ldsm_x2(uint32_t* r, uint32_t addr) {
    asm volatile("ldmatrix.sync.aligned.m8n8.x2.shared.b16 {%0,%1}, [%2];"
                 : "=r"(r[0]), "=r"(r[1]) : "r"(addr));
}
__device__ __forceinline__ void mma_bf16(float* c, const uint32_t* a, const uint32_t* b) {
    asm volatile(
        "mma.sync.aligned.m16n8k16.row.col.f32.bf16.bf16.f32 "
        "{%0,%1,%2,%3}, {%4,%5,%6,%7}, {%8,%9}, {%0,%1,%2,%3};"
        : "+f"(c[0]), "+f"(c[1]), "+f"(c[2]), "+f"(c[3])
        : "r"(a[0]), "r"(a[1]), "r"(a[2]), "r"(a[3]), "r"(b[0]), "r"(b[1]));
}

// ================= split fp32 -> (hi, lo) bf16 =============================
__global__ void split_kernel(const float* __restrict__ src,
                             __nv_bfloat16* __restrict__ hi,
                             __nv_bfloat16* __restrict__ lo,
                             int n_src, int n_total) {
    int i = blockIdx.x * blockDim.x + threadIdx.x;
    if (i >= n_total) return;
    float v = (i < n_src) ? src[i] : 0.f;
    __nv_bfloat16 h = __float2bfloat16(v);
    hi[i] = h;
    lo[i] = __float2bfloat16(v - __bfloat162float(h));
}

// ================= mma.sync bf16 GEMM (3-term compensated) =================
// C[m,n] = sum_{k in split z} A[m,k]*B[n,k]; split z writes C + z*csplit.
#define GSTRIDE 24
#define GOP_BYTES (128 * GSTRIDE * 2)      // 6144
#define GSTAGE_BYTES (4 * GOP_BYTES)       // 24576
__global__ __launch_bounds__(256, 2)
void mma_gemm(const __nv_bfloat16* __restrict__ Ahi, const __nv_bfloat16* __restrict__ Alo,
              const __nv_bfloat16* __restrict__ Bhi, const __nv_bfloat16* __restrict__ Blo,
              float* __restrict__ C, int Ktot, int Nact, int ldc, size_t csplit) {
    extern __shared__ char smx[];
    uint32_t sb = smem_u32(smx);
    int tid  = threadIdx.x;
    int lane = tid & 31, wid = tid >> 5;
    int wm = wid >> 2, wn = wid & 3;
    int m0 = blockIdx.y * 128, n0 = blockIdx.x * 128;
    int nsp  = gridDim.z;
    int Klen = Ktot / nsp;
    int k0   = blockIdx.z * Klen;
    float* Cp = C + (size_t)blockIdx.z * csplit;
    const int KT = Klen / 16;

    const __nv_bfloat16* ptrs[4] = {Ahi, Alo, Bhi, Blo};
    int rbase[4] = {m0, m0, n0, n0};

    auto load_stage = [&](int kt, int s) {
        uint32_t sbase = sb + s * GSTAGE_BYTES;
#pragma unroll
        for (int op = 0; op < 4; op++) {
            int r = tid >> 1, hf = tid & 1;
            const void* g = ptrs[op] + (size_t)(rbase[op] + r) * Ktot + k0 + kt * 16 + hf * 8;
            uint32_t d = sbase + op * GOP_BYTES + (r * GSTRIDE + hf * 8) * 2;
            asm volatile("cp.async.cg.shared.global [%0], [%1], 16;" :: "r"(d), "l"(g));
        }
        asm volatile("cp.async.commit_group;");
    };

    float acc[4][4][4];
#pragma unroll
    for (int i = 0; i < 4; i++)
#pragma unroll
        for (int j = 0; j < 4; j++)
#pragma unroll
            for (int q = 0; q < 4; q++) acc[i][j][q] = 0.f;

    load_stage(0, 0);

    for (int kt = 0; kt < KT; kt++) {
        int cur = kt & 1;
        if (kt + 1 < KT) {
            load_stage(kt + 1, cur ^ 1);
            asm volatile("cp.async.wait_group 1;");
        } else {
            asm volatile("cp.async.wait_group 0;");
        }
        __syncthreads();

        uint32_t st = sb + cur * GSTAGE_BYTES;
        uint32_t ah[4][4], al[4][4], bh[4][2], bl[4][2];
        int arow = wm * 64 + (lane & 15);
        int acol = (lane >> 4) * 8;
#pragma unroll
        for (int i = 0; i < 4; i++) {
            uint32_t off = ((arow + i * 16) * GSTRIDE + acol) * 2;
            ldsm_x4(ah[i], st + off);
            ldsm_x4(al[i], st + GOP_BYTES + off);
        }
        int brow = wn * 32 + (lane & 7);
        int bcol = ((lane >> 3) & 1) * 8;
#pragma unroll
        for (int j = 0; j < 4; j++) {
            uint32_t off = ((brow + j * 8) * GSTRIDE + bcol) * 2;
            ldsm_x2(bh[j], st + 2 * GOP_BYTES + off);
            ldsm_x2(bl[j], st + 3 * GOP_BYTES + off);
        }
#pragma unroll
        for (int i = 0; i < 4; i++)
#pragma unroll
            for (int j = 0; j < 4; j++) {
                mma_bf16(acc[i][j], ah[i], bh[j]);
                mma_bf16(acc[i][j], ah[i], bl[j]);
                mma_bf16(acc[i][j], al[i], bh[j]);
            }
        __syncthreads();
    }

    int r0 = m0 + wm * 64 + (lane >> 2);
    int c0 = n0 + wn * 32 + (lane & 3) * 2;
#pragma unroll
    for (int i = 0; i < 4; i++) {
#pragma unroll
        for (int j = 0; j < 4; j++) {
            int rr = r0 + i * 16;
            int cc = c0 + j * 8;
            if (cc < Nact)     Cp[(size_t)rr * ldc + cc]           = acc[i][j][0];
            if (cc + 1 < Nact) Cp[(size_t)rr * ldc + cc + 1]       = acc[i][j][1];
            if (cc < Nact)     Cp[(size_t)(rr + 8) * ldc + cc]     = acc[i][j][2];
            if (cc + 1 < Nact) Cp[(size_t)(rr + 8) * ldc + cc + 1] = acc[i][j][3];
        }
    }
}

// ---------------- reduce NSPLIT partials -> out -----------------------------
__global__ void reduce_kernel(float* __restrict__ out) {
    int i = blockIdx.x * blockDim.x + threadIdx.x;
    const int n4 = MROWS * DMODEL / 4;
    if (i >= n4) return;
    float4 a = *(const float4*)(g_pp + i * 4);
    float4 b = *(const float4*)(g_pp + MROWS * DMODEL + i * 4);
    float4 c = *(const float4*)(g_pp + 2 * MROWS * DMODEL + i * 4);
    float4 d = *(const float4*)(g_pp + 3 * MROWS * DMODEL + i * 4);
    float4 r = make_float4(a.x + b.x + c.x + d.x, a.y + b.y + c.y + d.y,
                           a.z + b.z + c.z + d.z, a.w + b.w + c.w + d.w);
    *(float4*)(out + i * 4) = r;
}

// ---------------- causal depthwise conv (width 4) + SiLU + split -----------
__global__ void conv_kernel(const float* __restrict__ conv_w,
                            const float* __restrict__ conv_b) {
    int idx = blockIdx.x * blockDim.x + threadIdx.x;
    if (idx >= MROWS * CONVDIM) return;
    int c = idx % CONVDIM;
    int m = idx / CONVDIM;
    int t = m % SEQLEN;
    float s = conv_b[c];
#pragma unroll
    for (int k = 0; k < 4; k++) {
        int tt = t - 3 + k;
        if (tt >= 0)
            s += g_zx[(size_t)(m - 3 + k) * DINPROJ + DINNER + c] * conv_w[c * 4 + k];
    }
    float v = s / (1.f + expf(-s));
    if (c < DINNER)                g_X [m * DINNER + c] = v;
    else if (c < DINNER + DSTATE)  g_Bm[m * DSTATE + (c - DINNER)] = v;
    else                           g_Cm[m * DSTATE + (c - DINNER - DSTATE)] = v;
}

// ---------------- dt = softplus, within-chunk cumsum of dt*A ---------------
__global__ void dtcum_kernel(const float* __restrict__ dt_bias,
                             const float* __restrict__ A_log) {
    int g  = blockIdx.x;
    int c  = g & (NCHUNK - 1);
    int bh = g >> 3;
    int h  = bh % NHEADS;
    int b  = bh / NHEADS;
    int t  = threadIdx.x;
    int m  = b * SEQLEN + c * LC + t;

    float x   = g_zx[(size_t)m * DINPROJ + DINNER + CONVDIM + h] + dt_bias[h];
    float dtv = (x > 20.f) ? x : log1pf(expf(x));
    float a   = -expf(A_log[h]) * dtv;

    float sc = a;
#pragma unroll
    for (int o = 1; o < 32; o <<= 1) {
        float v = __shfl_up_sync(0xffffffffu, sc, o);
        if ((t & 31) >= o) sc += v;
    }
    __shared__ float w0tot;
    if (t == 31) w0tot = sc;
    __syncthreads();
    if (t >= 32) sc += w0tot;

    int idx = bh * SEQLEN + c * LC + t;
    g_dtv[idx] = dtv;
    g_cum[idx] = sc;
}

// ---------------- intra-chunk kernel ---------------------------------------
#define SB_STRIDE 132
#define SX_STRIDE 68
#define SMEMB_FLOATS (2*64*SB_STRIDE + 2*64*SX_STRIDE + 3*64)
__global__ __launch_bounds__(256)
void intra_kernel(const float* __restrict__ D_param) {
    extern __shared__ float sm[];
    float* sB   = sm;
    float* sC   = sB + 64 * SB_STRIDE;
    float* sX   = sC + 64 * SB_STRIDE;
    float* sG   = sX + 64 * SX_STRIDE;
    float* sdt  = sG + 64 * SX_STRIDE;
    float* scum = sdt + 64;
    float* sw   = scum + 64;

    int g  = blockIdx.x;
    int c  = g & (NCHUNK - 1);
    int bh = g >> 3;
    int h  = bh % NHEADS;
    int b  = bh / NHEADS;
    int tid = threadIdx.x;
    int m0 = b * SEQLEN + c * LC;

    for (int i = tid; i < 64 * 32; i += 256) {
        int r = i >> 5, q = i & 31;
        *(float4*)(sB + r * SB_STRIDE + q * 4) =
            *(const float4*)(g_Bm + (size_t)(m0 + r) * DSTATE + q * 4);
        *(float4*)(sC + r * SB_STRIDE + q * 4) =
            *(const float4*)(g_Cm + (size_t)(m0 + r) * DSTATE + q * 4);
    }
    for (int i = tid; i < 64 * 16; i += 256) {
        int r = i >> 4, q = i & 15;
        *(float4*)(sX + r * SX_STRIDE + q * 4) =
            *(const float4*)(g_X + (size_t)(m0 + r) * DINNER + h * HEADDIM + q * 4);
    }
    if (tid < 64) {
        sdt[tid]  = g_dtv[bh * SEQLEN + c * LC + tid];
        scum[tid] = g_cum[bh * SEQLEN + c * LC + tid];
    }
    __syncthreads();
    if (tid < 64) sw[tid] = expf(scum[63] - scum[tid]) * sdt[tid];

    int tx = tid & 15, ty = tid >> 4;

    {   // G[t][s]
        float acc[4][4] = {};
        for (int kk = 0; kk < 128; kk += 4) {
            float4 a4[4], b4[4];
#pragma unroll
            for (int i = 0; i < 4; i++) a4[i] = *(float4*)(sC + (ty * 4 + i) * SB_STRIDE + kk);
#pragma unroll
            for (int j = 0; j < 4; j++) b4[j] = *(float4*)(sB + (tx * 4 + j) * SB_STRIDE + kk);
#pragma unroll
            for (int i = 0; i < 4; i++)
#pragma unroll
                for (int j = 0; j < 4; j++)
                    acc[i][j] += a4[i].x * b4[j].x + a4[i].y * b4[j].y
                               + a4[i].z * b4[j].z + a4[i].w * b4[j].w;
        }
#pragma unroll
        for (int i = 0; i < 4; i++) {
            int t_ = ty * 4 + i;
#pragma unroll
            for (int j = 0; j < 4; j++) {
                int s_ = tx * 4 + j;
                float wgt = (s_ <= t_) ? expf(scum[t_] - scum[s_]) * sdt[s_] : 0.f;
                sG[t_ * SX_STRIDE + s_] = acc[i][j] * wgt;
            }
        }
    }
    __syncthreads();

    {   // Y_intra = G @ X + D*x
        float acc[4][4] = {};
        for (int kk = 0; kk < 64; kk++) {
            float a_[4];
#pragma unroll
            for (int i = 0; i < 4; i++) a_[i] = sG[(ty * 4 + i) * SX_STRIDE + kk];
            float4 b4 = *(float4*)(sX + kk * SX_STRIDE + tx * 4);
#pragma unroll
            for (int i = 0; i < 4; i++) {
                acc[i][0] += a_[i] * b4.x;
                acc[i][1] += a_[i] * b4.y;
                acc[i][2] += a_[i] * b4.z;
                acc[i][3] += a_[i] * b4.w;
            }
        }
        float Dp = D_param[h];
#pragma unroll
        for (int i = 0; i < 4; i++) {
            int t_ = ty * 4 + i;
#pragma unroll
            for (int j = 0; j < 4; j++) {
                int p_ = tx * 4 + j;
                g_Y0[(size_t)(m0 + t_) * DINNER + h * HEADDIM + p_] =
                    acc[i][j] + Dp * sX[t_ * SX_STRIDE + p_];
            }
        }
    }

    {   // S[p][n]
        float acc[4][8] = {};
        for (int kk = 0; kk < 64; kk++) {
            float wk = sw[kk];
            float a_[4];
#pragma unroll
            for (int i = 0; i < 4; i++) a_[i] = sX[kk * SX_STRIDE + ty * 4 + i] * wk;
            float4 b0 = *(float4*)(sB + kk * SB_STRIDE + tx * 8);
            float4 b1 = *(float4*)(sB + kk * SB_STRIDE + tx * 8 + 4);
#pragma unroll
            for (int i = 0; i < 4; i++) {
                acc[i][0] += a_[i] * b0.x;  acc[i][1] += a_[i] * b0.y;
                acc[i][2] += a_[i] * b0.z;  acc[i][3] += a_[i] * b0.w;
                acc[i][4] += a_[i] * b1.x;  acc[i][5] += a_[i] * b1.y;
                acc[i][6] += a_[i] * b1.z;  acc[i][7] += a_[i] * b1.w;
            }
        }
        size_t base = (size_t)(bh * NCHUNK + c) * (HEADDIM * DSTATE);
#pragma unroll
        for (int i = 0; i < 4; i++) {
            int p_ = ty * 4 + i;
#pragma unroll
            for (int j = 0; j < 8; j++) {
                int n_ = tx * 8 + j;
                g_S[base + p_ * DSTATE + n_] = acc[i][j];
            }
        }
    }
}

// ---------------- inter-chunk state scan (8 steps) --------------------------
__global__ void chunkscan_kernel() {
    int bh  = blockIdx.x;
    int tid = threadIdx.x;
    float4 E[4];
#pragma unroll
    for (int i = 0; i < 4; i++) E[i] = make_float4(0.f, 0.f, 0.f, 0.f);
    size_t base = (size_t)bh * NCHUNK * (HEADDIM * DSTATE);
    for (int k = 0; k < NCHUNK; k++) {
        float dAk = expf(g_cum[bh * SEQLEN + k * LC + (LC - 1)]);
        size_t off = base + (size_t)k * (HEADDIM * DSTATE) + tid * 16;
#pragma unroll
        for (int i = 0; i < 4; i++) {
            *(float4*)(g_P + off + i * 4) = E[i];
            float4 s = *(const float4*)(g_S + off + i * 4);
            E[i].x = s.x + dAk * E[i].x;
            E[i].y = s.y + dAk * E[i].y;
            E[i].z = s.z + dAk * E[i].z;
            E[i].w = s.w + dAk * E[i].w;
        }
    }
}

// ---------------- inter-chunk Y + gating + bf16 split -----------------------
#define SMEMD_FLOATS (2*64*SB_STRIDE + 64)
__global__ __launch_bounds__(256)
void inter_gate_kernel() {
    extern __shared__ float sm[];
    float* sC   = sm;
    float* sP   = sC + 64 * SB_STRIDE;
    float* scum = sP + 64 * SB_STRIDE;

    int g  = blockIdx.x;
    int c  = g & (NCHUNK - 1);
    int bh = g >> 3;
    int h  = bh % NHEADS;
    int b  = bh / NHEADS;
    int tid = threadIdx.x;
    int m0 = b * SEQLEN + c * LC;
    size_t pbase = (size_t)(bh * NCHUNK + c) * (HEADDIM * DSTATE);

    for (int i = tid; i < 64 * 32; i += 256) {
        int r = i >> 5, q = i & 31;
        *(float4*)(sC + r * SB_STRIDE + q * 4) =
            *(const float4*)(g_Cm + (size_t)(m0 + r) * DSTATE + q * 4);
        *(float4*)(sP + r * SB_STRIDE + q * 4) =
            *(const float4*)(g_P + pbase + r * DSTATE + q * 4);
    }
    if (tid < 64) scum[tid] = g_cum[bh * SEQLEN + c * LC + tid];
    __syncthreads();

    int tx = tid & 15, ty = tid >> 4;
    float acc[4][4] = {};
    for (int n = 0; n < 128; n += 4) {
        float4 a4[4], b4[4];
#pragma unroll
        for (int i = 0; i < 4; i++) a4[i] = *(float4*)(sC + (ty * 4 + i) * SB_STRIDE + n);
#pragma unroll
        for (int j = 0; j < 4; j++) b4[j] = *(float4*)(sP + (tx * 4 + j) * SB_STRIDE + n);
#pragma unroll
        for (int i = 0; i < 4; i++)
#pragma unroll
            for (int j = 0; j < 4; j++)
                acc[i][j] += a4[i].x * b4[j].x + a4[i].y * b4[j].y
                           + a4[i].z * b4[j].z + a4[i].w * b4[j].w;
    }
#pragma unroll
    for (int i = 0; i < 4; i++) {
        int t_ = ty * 4 + i;
        float dec = expf(scum[t_]);
#pragma unroll
        for (int j = 0; j < 4; j++) {
            int p_ = tx * 4 + j;
            size_t mi = (size_t)(m0 + t_) * DINNER + h * HEADDIM + p_;
            float y = g_Y0[mi] + dec * acc[i][j];
            float z = g_zx[(size_t)(m0 + t_) * DINPROJ + h * HEADDIM + p_];
            float gv = y * (z / (1.f + expf(-z)));
            __nv_bfloat16 hb = __float2bfloat16(gv);
            g_ghi[mi] = hb;
            g_glo[mi] = __float2bfloat16(gv - __bfloat162float(hb));
        }
    }
}

// ---------------- launch ----------------------------------------------------
extern "C" void kernel_launch(void* const* d_in, const int* in_sizes, int n_in,
                              void* d_out, int out_size) {
    const float* u       = (const float*)d_in[0];
    const float* W_in    = (const float*)d_in[1];
    const float* conv_w  = (const float*)d_in[2];
    const float* conv_b  = (const float*)d_in[3];
    const float* dt_bias = (const float*)d_in[4];
    const float* A_log   = (const float*)d_in[5];
    const float* D_param = (const float*)d_in[6];
    const float* W_out   = (const float*)d_in[7];
    float* out = (float*)d_out;

    float *zx, *pp;
    cudaGetSymbolAddress((void**)&zx, g_zx);
    cudaGetSymbolAddress((void**)&pp, g_pp);
    __nv_bfloat16 *uhi, *ulo, *wih, *wil, *ghi, *glo, *woh, *wol;
    cudaGetSymbolAddress((void**)&uhi, g_uhi);  cudaGetSymbolAddress((void**)&ulo, g_ulo);
    cudaGetSymbolAddress((void**)&wih, g_wih);  cudaGetSymbolAddress((void**)&wil, g_wil);
    cudaGetSymbolAddress((void**)&ghi, g_ghi);  cudaGetSymbolAddress((void**)&glo, g_glo);
    cudaGetSymbolAddress((void**)&woh, g_woh);  cudaGetSymbolAddress((void**)&wol, g_wol);

    static bool attr_done = false;
    if (!attr_done) {
        cudaFuncSetAttribute(intra_kernel, cudaFuncAttributeMaxDynamicSharedMemorySize,
                             SMEMB_FLOATS * sizeof(float));
        cudaFuncSetAttribute(inter_gate_kernel, cudaFuncAttributeMaxDynamicSharedMemorySize,
                             SMEMD_FLOATS * sizeof(float));
        cudaFuncSetAttribute(mma_gemm, cudaFuncAttributeMaxDynamicSharedMemorySize,
                             2 * GSTAGE_BYTES);
        attr_done = true;
    }
    const int TC_SMEM = 2 * GSTAGE_BYTES;  // 49152

    // 0. split inputs/weights to bf16 hi/lo
    {
        int n1 = MROWS * DMODEL;
        split_kernel<<<(n1 + 255) / 256, 256>>>(u, uhi, ulo, n1, n1);
        int n2s = DINPROJ * DMODEL, n2t = NPAD_IN * DMODEL;
        split_kernel<<<(n2t + 255) / 256, 256>>>(W_in, wih, wil, n2s, n2t);
        int n3 = DMODEL * DINNER;
        split_kernel<<<(n3 + 255) / 256, 256>>>(W_out, woh, wol, n3, n3);
    }
    // 1. in-projection
    {
        dim3 grid(NPAD_IN / 128, MROWS / 128, 1);
        mma_gemm<<<grid, 256, TC_SMEM>>>(uhi, ulo, wih, wil, zx,
                                         DMODEL, DINPROJ, DINPROJ, 0);
    }
    // 2. causal conv + silu
    conv_kernel<<<(MROWS * CONVDIM + 255) / 256, 256>>>(conv_w, conv_b);
    // 3. dt + within-chunk cumsum
    dtcum_kernel<<<NBH * NCHUNK, 64>>>(dt_bias, A_log);
    // 4. intra-chunk
    intra_kernel<<<NBH * NCHUNK, 256, SMEMB_FLOATS * sizeof(float)>>>(D_param);
    // 5. inter-chunk state scan
    chunkscan_kernel<<<NBH, 512>>>();
    // 6. inter-chunk Y + gating (+ bf16 split of G)
    inter_gate_kernel<<<NBH * NCHUNK, 256, SMEMD_FLOATS * sizeof(float)>>>();
    // 7. out-projection, split-K x4 into partials, then reduce
    {
        dim3 grid(DMODEL / 128, MROWS / 128, NSPLIT);
        mma_gemm<<<grid, 256, TC_SMEM>>>(ghi, glo, woh, wol, pp,
                                         DINNER, DMODEL, DMODEL,
                                         (size_t)MROWS * DMODEL);
        reduce_kernel<<<(MROWS * DMODEL / 4 + 255) / 256, 256>>>(out);
    }
}

// round 7
// speedup vs baseline: 5.8063x; 1.2199x over previous
#include <cuda_runtime.h>
#include <cuda_bf16.h>
#include <math.h>
#include <cstdint>

#define BATCH   2
#define SEQLEN  512
#define DMODEL  768
#define DINNER  1536
#define NHEADS  24
#define HEADDIM 64
#define DSTATE  128
#define CONVDIM 1792
#define DINPROJ 3352
#define MROWS   (BATCH*SEQLEN)  // 1024
#define LC      64
#define NCHUNK  (SEQLEN/LC)     // 8
#define NBH     (BATCH*NHEADS)  // 48
#define NPAD_IN 3456
#define NSPLIT  4

// ---------------- scratch ---------------------------------------------------
__device__ float g_zx [MROWS * DINPROJ];
__device__ float g_X  [MROWS * DINNER];
__device__ float g_Bm [MROWS * DSTATE];
__device__ float g_Cm [MROWS * DSTATE];
__device__ float g_dtv[NBH * SEQLEN];
__device__ float g_cum[NBH * SEQLEN];
__device__ float g_Y0 [MROWS * DINNER];
__device__ float g_S  [NBH * NCHUNK * HEADDIM * DSTATE];
__device__ float g_P  [NBH * NCHUNK * HEADDIM * DSTATE];
__device__ float g_pp [NSPLIT * MROWS * DMODEL];

__device__ __align__(256) __nv_bfloat16 g_uhi[MROWS * DMODEL],   g_ulo[MROWS * DMODEL];
__device__ __align__(256) __nv_bfloat16 g_wih[NPAD_IN * DMODEL], g_wil[NPAD_IN * DMODEL];
__device__ __align__(256) __nv_bfloat16 g_ghi[MROWS * DINNER],   g_glo[MROWS * DINNER];
__device__ __align__(256) __nv_bfloat16 g_woh[DMODEL * DINNER],  g_wol[DMODEL * DINNER];

// ================= helpers =================================================
__device__ __forceinline__ uint32_t smem_u32(const void* p) {
    uint32_t a;
    asm("{ .reg .u64 t; cvta.to.shared.u64 t, %1; cvt.u32.u64 %0, t; }"
        : "=r"(a) : "l"(p));
    return a;
}
__device__ __forceinline__ void ldsm_x4(uint32_t* r, uint32_t addr) {
    asm volatile("ldmatrix.sync.aligned.m8n8.x4.shared.b16 {%0,%1,%2,%3}, [%4];"
                 : "=r"(r[0]), "=r"(r[1]), "=r"(r[2]), "=r"(r[3]) : "r"(addr));
}
__device__ __forceinline__ void ldsm_x2(uint32_t* r, uint32_t addr) {
    asm volatile("ldmatrix.sync.aligned.m8n8.x2.shared.b16 {%0,%1}, [%2];"
                 : "=r"(r[0]), "=r"(r[1]) : "r"(addr));
}
__device__ __forceinline__ void mma_bf16(float* c, const uint32_t* a, const uint32_t* b) {
    asm volatile(
        "mma.sync.aligned.m16n8k16.row.col.f32.bf16.bf16.f32 "
        "{%0,%1,%2,%3}, {%4,%5,%6,%7}, {%8,%9}, {%0,%1,%2,%3};"
        : "+f"(c[0]), "+f"(c[1]), "+f"(c[2]), "+f"(c[3])
        : "r"(a[0]), "r"(a[1]), "r"(a[2]), "r"(a[3]), "r"(b[0]), "r"(b[1]));
}

// ================= split fp32 -> (hi, lo) bf16 =============================
__global__ void split_kernel(const float* __restrict__ src,
                             __nv_bfloat16* __restrict__ hi,
                             __nv_bfloat16* __restrict__ lo,
                             int n_src, int n_total) {
    int i = blockIdx.x * blockDim.x + threadIdx.x;
    if (i >= n_total) return;
    float v = (i < n_src) ? src[i] : 0.f;
    __nv_bfloat16 h = __float2bfloat16(v);
    hi[i] = h;
    lo[i] = __float2bfloat16(v - __bfloat162float(h));
}

// ================= mma.sync bf16 GEMM, 4-stage pipeline ====================
#define GSTRIDE 24
#define GOP_BYTES (128 * GSTRIDE * 2)      // 6144
#define GSTAGE_BYTES (4 * GOP_BYTES)       // 24576
#define GNSTAGE 4
__global__ __launch_bounds__(256, 2)
void mma_gemm(const __nv_bfloat16* __restrict__ Ahi, const __nv_bfloat16* __restrict__ Alo,
              const __nv_bfloat16* __restrict__ Bhi, const __nv_bfloat16* __restrict__ Blo,
              float* __restrict__ C, int Ktot, int Nact, int ldc, size_t csplit) {
    extern __shared__ char smx[];
    uint32_t sb = smem_u32(smx);
    int tid  = threadIdx.x;
    int lane = tid & 31, wid = tid >> 5;
    int wm = wid >> 2, wn = wid & 3;
    int m0 = blockIdx.y * 128, n0 = blockIdx.x * 128;
    int nsp  = gridDim.z;
    int Klen = Ktot / nsp;
    int k0   = blockIdx.z * Klen;
    float* Cp = C + (size_t)blockIdx.z * csplit;
    const int KT = Klen / 16;

    const __nv_bfloat16* ptrs[4] = {Ahi, Alo, Bhi, Blo};
    int rbase[4] = {m0, m0, n0, n0};

    auto load_stage = [&](int kt, int s) {
        uint32_t sbase = sb + s * GSTAGE_BYTES;
#pragma unroll
        for (int op = 0; op < 4; op++) {
            int r = tid >> 1, hf = tid & 1;
            const void* g = ptrs[op] + (size_t)(rbase[op] + r) * Ktot + k0 + kt * 16 + hf * 8;
            uint32_t d = sbase + op * GOP_BYTES + (r * GSTRIDE + hf * 8) * 2;
            asm volatile("cp.async.cg.shared.global [%0], [%1], 16;" :: "r"(d), "l"(g));
        }
        asm volatile("cp.async.commit_group;");
    };

    float acc[4][4][4];
#pragma unroll
    for (int i = 0; i < 4; i++)
#pragma unroll
        for (int j = 0; j < 4; j++)
#pragma unroll
            for (int q = 0; q < 4; q++) acc[i][j][q] = 0.f;

    // prologue: 3 stages in flight
    load_stage(0, 0);
    load_stage(1, 1);
    load_stage(2, 2);

    for (int kt = 0; kt < KT; kt++) {
        asm volatile("cp.async.wait_group 2;");
        __syncthreads();

        uint32_t st = sb + (kt & 3) * GSTAGE_BYTES;
        uint32_t ah[4][4], al[4][4], bh[4][2], bl[4][2];
        int arow = wm * 64 + (lane & 15);
        int acol = (lane >> 4) * 8;
#pragma unroll
        for (int i = 0; i < 4; i++) {
            uint32_t off = ((arow + i * 16) * GSTRIDE + acol) * 2;
            ldsm_x4(ah[i], st + off);
            ldsm_x4(al[i], st + GOP_BYTES + off);
        }
        int brow = wn * 32 + (lane & 7);
        int bcol = ((lane >> 3) & 1) * 8;
#pragma unroll
        for (int j = 0; j < 4; j++) {
            uint32_t off = ((brow + j * 8) * GSTRIDE + bcol) * 2;
            ldsm_x2(bh[j], st + 2 * GOP_BYTES + off);
            ldsm_x2(bl[j], st + 3 * GOP_BYTES + off);
        }
#pragma unroll
        for (int i = 0; i < 4; i++)
#pragma unroll
            for (int j = 0; j < 4; j++) {
                mma_bf16(acc[i][j], ah[i], bh[j]);
                mma_bf16(acc[i][j], ah[i], bl[j]);
                mma_bf16(acc[i][j], al[i], bh[j]);
            }

        if (kt + 3 < KT) load_stage(kt + 3, (kt + 3) & 3);
        else             asm volatile("cp.async.commit_group;");
    }

    int r0 = m0 + wm * 64 + (lane >> 2);
    int c0 = n0 + wn * 32 + (lane & 3) * 2;
#pragma unroll
    for (int i = 0; i < 4; i++) {
#pragma unroll
        for (int j = 0; j < 4; j++) {
            int rr = r0 + i * 16;
            int cc = c0 + j * 8;
            if (cc < Nact)     Cp[(size_t)rr * ldc + cc]           = acc[i][j][0];
            if (cc + 1 < Nact) Cp[(size_t)rr * ldc + cc + 1]       = acc[i][j][1];
            if (cc < Nact)     Cp[(size_t)(rr + 8) * ldc + cc]     = acc[i][j][2];
            if (cc + 1 < Nact) Cp[(size_t)(rr + 8) * ldc + cc + 1] = acc[i][j][3];
        }
    }
}

// ---------------- reduce NSPLIT partials -> out -----------------------------
__global__ void reduce_kernel(float* __restrict__ out) {
    int i = blockIdx.x * blockDim.x + threadIdx.x;
    const int n4 = MROWS * DMODEL / 4;
    if (i >= n4) return;
    float4 a = *(const float4*)(g_pp + i * 4);
    float4 b = *(const float4*)(g_pp + MROWS * DMODEL + i * 4);
    float4 c = *(const float4*)(g_pp + 2 * MROWS * DMODEL + i * 4);
    float4 d = *(const float4*)(g_pp + 3 * MROWS * DMODEL + i * 4);
    float4 r = make_float4(a.x + b.x + c.x + d.x, a.y + b.y + c.y + d.y,
                           a.z + b.z + c.z + d.z, a.w + b.w + c.w + d.w);
    *(float4*)(out + i * 4) = r;
}

// ---------------- causal depthwise conv (width 4) + SiLU + split -----------
__global__ void conv_kernel(const float* __restrict__ conv_w,
                            const float* __restrict__ conv_b) {
    int idx = blockIdx.x * blockDim.x + threadIdx.x;
    if (idx >= MROWS * CONVDIM) return;
    int c = idx % CONVDIM;
    int m = idx / CONVDIM;
    int t = m % SEQLEN;
    float s = conv_b[c];
#pragma unroll
    for (int k = 0; k < 4; k++) {
        int tt = t - 3 + k;
        if (tt >= 0)
            s += g_zx[(size_t)(m - 3 + k) * DINPROJ + DINNER + c] * conv_w[c * 4 + k];
    }
    float v = s / (1.f + expf(-s));
    if (c < DINNER)                g_X [m * DINNER + c] = v;
    else if (c < DINNER + DSTATE)  g_Bm[m * DSTATE + (c - DINNER)] = v;
    else                           g_Cm[m * DSTATE + (c - DINNER - DSTATE)] = v;
}

// ---------------- dt = softplus, within-chunk cumsum of dt*A ---------------
__global__ void dtcum_kernel(const float* __restrict__ dt_bias,
                             const float* __restrict__ A_log) {
    int g  = blockIdx.x;
    int c  = g & (NCHUNK - 1);
    int bh = g >> 3;
    int h  = bh % NHEADS;
    int b  = bh / NHEADS;
    int t  = threadIdx.x;
    int m  = b * SEQLEN + c * LC + t;

    float x   = g_zx[(size_t)m * DINPROJ + DINNER + CONVDIM + h] + dt_bias[h];
    float dtv = (x > 20.f) ? x : log1pf(expf(x));
    float a   = -expf(A_log[h]) * dtv;

    float sc = a;
#pragma unroll
    for (int o = 1; o < 32; o <<= 1) {
        float v = __shfl_up_sync(0xffffffffu, sc, o);
        if ((t & 31) >= o) sc += v;
    }
    __shared__ float w0tot;
    if (t == 31) w0tot = sc;
    __syncthreads();
    if (t >= 32) sc += w0tot;

    int idx = bh * SEQLEN + c * LC + t;
    g_dtv[idx] = dtv;
    g_cum[idx] = sc;
}

// ---------------- intra-chunk kernel ---------------------------------------
#define SB_STRIDE 132
#define SX_STRIDE 68
#define SMEMB_FLOATS (2*64*SB_STRIDE + 2*64*SX_STRIDE + 3*64)
__global__ __launch_bounds__(256)
void intra_kernel(const float* __restrict__ D_param) {
    extern __shared__ float sm[];
    float* sB   = sm;
    float* sC   = sB + 64 * SB_STRIDE;
    float* sX   = sC + 64 * SB_STRIDE;
    float* sG   = sX + 64 * SX_STRIDE;
    float* sdt  = sG + 64 * SX_STRIDE;
    float* scum = sdt + 64;
    float* sw   = scum + 64;

    int g  = blockIdx.x;
    int c  = g & (NCHUNK - 1);
    int bh = g >> 3;
    int h  = bh % NHEADS;
    int b  = bh / NHEADS;
    int tid = threadIdx.x;
    int m0 = b * SEQLEN + c * LC;

    for (int i = tid; i < 64 * 32; i += 256) {
        int r = i >> 5, q = i & 31;
        *(float4*)(sB + r * SB_STRIDE + q * 4) =
            *(const float4*)(g_Bm + (size_t)(m0 + r) * DSTATE + q * 4);
        *(float4*)(sC + r * SB_STRIDE + q * 4) =
            *(const float4*)(g_Cm + (size_t)(m0 + r) * DSTATE + q * 4);
    }
    for (int i = tid; i < 64 * 16; i += 256) {
        int r = i >> 4, q = i & 15;
        *(float4*)(sX + r * SX_STRIDE + q * 4) =
            *(const float4*)(g_X + (size_t)(m0 + r) * DINNER + h * HEADDIM + q * 4);
    }
    if (tid < 64) {
        sdt[tid]  = g_dtv[bh * SEQLEN + c * LC + tid];
        scum[tid] = g_cum[bh * SEQLEN + c * LC + tid];
    }
    __syncthreads();
    if (tid < 64) sw[tid] = expf(scum[63] - scum[tid]) * sdt[tid];

    int tx = tid & 15, ty = tid >> 4;
    int rot = (tid & 15) * 4;   // per-thread k rotation (breaks bank conflicts)

    {   // G[t][s] = (s<=t)*exp(cum[t]-cum[s])*dt[s]*(C_t . B_s)
        float acc[4][4] = {};
        for (int k0_ = 0; k0_ < 128; k0_ += 4) {
            int kk = (k0_ + rot) & 127;
            float4 a4[4], b4[4];
#pragma unroll
            for (int i = 0; i < 4; i++) a4[i] = *(float4*)(sC + (ty * 4 + i) * SB_STRIDE + kk);
#pragma unroll
            for (int j = 0; j < 4; j++) b4[j] = *(float4*)(sB + (tx * 4 + j) * SB_STRIDE + kk);
#pragma unroll
            for (int i = 0; i < 4; i++)
#pragma unroll
                for (int j = 0; j < 4; j++)
                    acc[i][j] += a4[i].x * b4[j].x + a4[i].y * b4[j].y
                               + a4[i].z * b4[j].z + a4[i].w * b4[j].w;
        }
#pragma unroll
        for (int i = 0; i < 4; i++) {
            int t_ = ty * 4 + i;
#pragma unroll
            for (int j = 0; j < 4; j++) {
                int s_ = tx * 4 + j;
                float wgt = (s_ <= t_) ? expf(scum[t_] - scum[s_]) * sdt[s_] : 0.f;
                sG[t_ * SX_STRIDE + s_] = acc[i][j] * wgt;
            }
        }
    }
    __syncthreads();

    {   // Y_intra = G @ X + D*x
        float acc[4][4] = {};
        for (int kk = 0; kk < 64; kk++) {
            float a_[4];
#pragma unroll
            for (int i = 0; i < 4; i++) a_[i] = sG[(ty * 4 + i) * SX_STRIDE + kk];
            float4 b4 = *(float4*)(sX + kk * SX_STRIDE + tx * 4);
#pragma unroll
            for (int i = 0; i < 4; i++) {
                acc[i][0] += a_[i] * b4.x;
                acc[i][1] += a_[i] * b4.y;
                acc[i][2] += a_[i] * b4.z;
                acc[i][3] += a_[i] * b4.w;
            }
        }
        float Dp = D_param[h];
#pragma unroll
        for (int i = 0; i < 4; i++) {
            int t_ = ty * 4 + i;
#pragma unroll
            for (int j = 0; j < 4; j++) {
                int p_ = tx * 4 + j;
                g_Y0[(size_t)(m0 + t_) * DINNER + h * HEADDIM + p_] =
                    acc[i][j] + Dp * sX[t_ * SX_STRIDE + p_];
            }
        }
    }

    {   // S[p][n] = sum_s w[s]*X[s][p]*B[s][n]
        float acc[4][8] = {};
        for (int kk = 0; kk < 64; kk++) {
            float wk = sw[kk];
            float a_[4];
#pragma unroll
            for (int i = 0; i < 4; i++) a_[i] = sX[kk * SX_STRIDE + ty * 4 + i] * wk;
            float4 b0 = *(float4*)(sB + kk * SB_STRIDE + tx * 8);
            float4 b1 = *(float4*)(sB + kk * SB_STRIDE + tx * 8 + 4);
#pragma unroll
            for (int i = 0; i < 4; i++) {
                acc[i][0] += a_[i] * b0.x;  acc[i][1] += a_[i] * b0.y;
                acc[i][2] += a_[i] * b0.z;  acc[i][3] += a_[i] * b0.w;
                acc[i][4] += a_[i] * b1.x;  acc[i][5] += a_[i] * b1.y;
                acc[i][6] += a_[i] * b1.z;  acc[i][7] += a_[i] * b1.w;
            }
        }
        size_t base = (size_t)(bh * NCHUNK + c) * (HEADDIM * DSTATE);
#pragma unroll
        for (int i = 0; i < 4; i++) {
            int p_ = ty * 4 + i;
#pragma unroll
            for (int j = 0; j < 8; j++) {
                int n_ = tx * 8 + j;
                g_S[base + p_ * DSTATE + n_] = acc[i][j];
            }
        }
    }
}

// ---------------- inter-chunk state scan (8 steps) --------------------------
__global__ void chunkscan_kernel() {
    int bh  = blockIdx.x;
    int tid = threadIdx.x;
    float4 E[4];
#pragma unroll
    for (int i = 0; i < 4; i++) E[i] = make_float4(0.f, 0.f, 0.f, 0.f);
    size_t base = (size_t)bh * NCHUNK * (HEADDIM * DSTATE);
    for (int k = 0; k < NCHUNK; k++) {
        float dAk = expf(g_cum[bh * SEQLEN + k * LC + (LC - 1)]);
        size_t off = base + (size_t)k * (HEADDIM * DSTATE) + tid * 16;
#pragma unroll
        for (int i = 0; i < 4; i++) {
            *(float4*)(g_P + off + i * 4) = E[i];
            float4 s = *(const float4*)(g_S + off + i * 4);
            E[i].x = s.x + dAk * E[i].x;
            E[i].y = s.y + dAk * E[i].y;
            E[i].z = s.z + dAk * E[i].z;
            E[i].w = s.w + dAk * E[i].w;
        }
    }
}

// ---------------- inter-chunk Y + gating + bf16 split -----------------------
#define SMEMD_FLOATS (2*64*SB_STRIDE + 64)
__global__ __launch_bounds__(256)
void inter_gate_kernel() {
    extern __shared__ float sm[];
    float* sC   = sm;
    float* sP   = sC + 64 * SB_STRIDE;
    float* scum = sP + 64 * SB_STRIDE;

    int g  = blockIdx.x;
    int c  = g & (NCHUNK - 1);
    int bh = g >> 3;
    int h  = bh % NHEADS;
    int b  = bh / NHEADS;
    int tid = threadIdx.x;
    int m0 = b * SEQLEN + c * LC;
    size_t pbase = (size_t)(bh * NCHUNK + c) * (HEADDIM * DSTATE);

    for (int i = tid; i < 64 * 32; i += 256) {
        int r = i >> 5, q = i & 31;
        *(float4*)(sC + r * SB_STRIDE + q * 4) =
            *(const float4*)(g_Cm + (size_t)(m0 + r) * DSTATE + q * 4);
        *(float4*)(sP + r * SB_STRIDE + q * 4) =
            *(const float4*)(g_P + pbase + r * DSTATE + q * 4);
    }
    if (tid < 64) scum[tid] = g_cum[bh * SEQLEN + c * LC + tid];
    __syncthreads();

    int tx = tid & 15, ty = tid >> 4;
    int rot = (tid & 15) * 4;
    float acc[4][4] = {};
    for (int n0_ = 0; n0_ < 128; n0_ += 4) {
        int n = (n0_ + rot) & 127;
        float4 a4[4], b4[4];
#pragma unroll
        for (int i = 0; i < 4; i++) a4[i] = *(float4*)(sC + (ty * 4 + i) * SB_STRIDE + n);
#pragma unroll
        for (int j = 0; j < 4; j++) b4[j] = *(float4*)(sP + (tx * 4 + j) * SB_STRIDE + n);
#pragma unroll
        for (int i = 0; i < 4; i++)
#pragma unroll
            for (int j = 0; j < 4; j++)
                acc[i][j] += a4[i].x * b4[j].x + a4[i].y * b4[j].y
                           + a4[i].z * b4[j].z + a4[i].w * b4[j].w;
    }
#pragma unroll
    for (int i = 0; i < 4; i++) {
        int t_ = ty * 4 + i;
        float dec = expf(scum[t_]);
#pragma unroll
        for (int j = 0; j < 4; j++) {
            int p_ = tx * 4 + j;
            size_t mi = (size_t)(m0 + t_) * DINNER + h * HEADDIM + p_;
            float y = g_Y0[mi] + dec * acc[i][j];
            float z = g_zx[(size_t)(m0 + t_) * DINPROJ + h * HEADDIM + p_];
            float gv = y * (z / (1.f + expf(-z)));
            __nv_bfloat16 hb = __float2bfloat16(gv);
            g_ghi[mi] = hb;
            g_glo[mi] = __float2bfloat16(gv - __bfloat162float(hb));
        }
    }
}

// ---------------- launch ----------------------------------------------------
extern "C" void kernel_launch(void* const* d_in, const int* in_sizes, int n_in,
                              void* d_out, int out_size) {
    const float* u       = (const float*)d_in[0];
    const float* W_in    = (const float*)d_in[1];
    const float* conv_w  = (const float*)d_in[2];
    const float* conv_b  = (const float*)d_in[3];
    const float* dt_bias = (const float*)d_in[4];
    const float* A_log   = (const float*)d_in[5];
    const float* D_param = (const float*)d_in[6];
    const float* W_out   = (const float*)d_in[7];
    float* out = (float*)d_out;

    float *zx, *pp;
    cudaGetSymbolAddress((void**)&zx, g_zx);
    cudaGetSymbolAddress((void**)&pp, g_pp);
    __nv_bfloat16 *uhi, *ulo, *wih, *wil, *ghi, *glo, *woh, *wol;
    cudaGetSymbolAddress((void**)&uhi, g_uhi);  cudaGetSymbolAddress((void**)&ulo, g_ulo);
    cudaGetSymbolAddress((void**)&wih, g_wih);  cudaGetSymbolAddress((void**)&wil, g_wil);
    cudaGetSymbolAddress((void**)&ghi, g_ghi);  cudaGetSymbolAddress((void**)&glo, g_glo);
    cudaGetSymbolAddress((void**)&woh, g_woh);  cudaGetSymbolAddress((void**)&wol, g_wol);

    static bool attr_done = false;
    if (!attr_done) {
        cudaFuncSetAttribute(intra_kernel, cudaFuncAttributeMaxDynamicSharedMemorySize,
                             SMEMB_FLOATS * sizeof(float));
        cudaFuncSetAttribute(inter_gate_kernel, cudaFuncAttributeMaxDynamicSharedMemorySize,
                             SMEMD_FLOATS * sizeof(float));
        cudaFuncSetAttribute(mma_gemm, cudaFuncAttributeMaxDynamicSharedMemorySize,
                             GNSTAGE * GSTAGE_BYTES);
        attr_done = true;
    }
    const int TC_SMEM = GNSTAGE * GSTAGE_BYTES;  // 98304

    // 0. split inputs/weights to bf16 hi/lo
    {
        int n1 = MROWS * DMODEL;
        split_kernel<<<(n1 + 255) / 256, 256>>>(u, uhi, ulo, n1, n1);
        int n2s = DINPROJ * DMODEL, n2t = NPAD_IN * DMODEL;
        split_kernel<<<(n2t + 255) / 256, 256>>>(W_in, wih, wil, n2s, n2t);
        int n3 = DMODEL * DINNER;
        split_kernel<<<(n3 + 255) / 256, 256>>>(W_out, woh, wol, n3, n3);
    }
    // 1. in-projection
    {
        dim3 grid(NPAD_IN / 128, MROWS / 128, 1);
        mma_gemm<<<grid, 256, TC_SMEM>>>(uhi, ulo, wih, wil, zx,
                                         DMODEL, DINPROJ, DINPROJ, 0);
    }
    // 2. causal conv + silu
    conv_kernel<<<(MROWS * CONVDIM + 255) / 256, 256>>>(conv_w, conv_b);
    // 3. dt + within-chunk cumsum
    dtcum_kernel<<<NBH * NCHUNK, 64>>>(dt_bias, A_log);
    // 4. intra-chunk
    intra_kernel<<<NBH * NCHUNK, 256, SMEMB_FLOATS * sizeof(float)>>>(D_param);
    // 5. inter-chunk state scan
    chunkscan_kernel<<<NBH, 512>>>();
    // 6. inter-chunk Y + gating (+ bf16 split of G)
    inter_gate_kernel<<<NBH * NCHUNK, 256, SMEMD_FLOATS * sizeof(float)>>>();
    // 7. out-projection, split-K x4 into partials, then reduce
    {
        dim3 grid(DMODEL / 128, MROWS / 128, NSPLIT);
        mma_gemm<<<grid, 256, TC_SMEM>>>(ghi, glo, woh, wol, pp,
                                         DINNER, DMODEL, DMODEL,
                                         (size_t)MROWS * DMODEL);
        reduce_kernel<<<(MROWS * DMODEL / 4 + 255) / 256, 256>>>(out);
    }
}

// round 8
// speedup vs baseline: 5.9217x; 1.0199x over previous
#include <cuda_runtime.h>
#include <cuda_bf16.h>
#include <math.h>
#include <cstdint>

#define BATCH   2
#define SEQLEN  512
#define DMODEL  768
#define DINNER  1536
#define NHEADS  24
#define HEADDIM 64
#define DSTATE  128
#define CONVDIM 1792
#define DINPROJ 3352
#define MROWS   (BATCH*SEQLEN)  // 1024
#define LC      64
#define NCHUNK  (SEQLEN/LC)     // 8
#define NBH     (BATCH*NHEADS)  // 48
#define NPAD_IN 3456
#define NSPLIT  4

// ---------------- scratch ---------------------------------------------------
__device__ float g_zx [MROWS * DINPROJ];
__device__ float g_X  [MROWS * DINNER];
__device__ float g_Bm [MROWS * DSTATE];
__device__ float g_Cm [MROWS * DSTATE];
__device__ float g_dtv[NBH * SEQLEN];
__device__ float g_cum[NBH * SEQLEN];
__device__ float g_Y0 [MROWS * DINNER];
__device__ float g_S  [NBH * NCHUNK * HEADDIM * DSTATE];
__device__ float g_P  [NBH * NCHUNK * HEADDIM * DSTATE];
__device__ float g_pp [NSPLIT * MROWS * DMODEL];

__device__ __align__(256) __nv_bfloat16 g_uhi[MROWS * DMODEL],   g_ulo[MROWS * DMODEL];
__device__ __align__(256) __nv_bfloat16 g_wih[NPAD_IN * DMODEL], g_wil[NPAD_IN * DMODEL];
__device__ __align__(256) __nv_bfloat16 g_ghi[MROWS * DINNER],   g_glo[MROWS * DINNER];
__device__ __align__(256) __nv_bfloat16 g_woh[DMODEL * DINNER],  g_wol[DMODEL * DINNER];

// ================= helpers =================================================
__device__ __forceinline__ uint32_t smem_u32(const void* p) {
    uint32_t a;
    asm("{ .reg .u64 t; cvta.to.shared.u64 t, %1; cvt.u32.u64 %0, t; }"
        : "=r"(a) : "l"(p));
    return a;
}
__device__ __forceinline__ void ldsm_x4(uint32_t* r, uint32_t addr) {
    asm volatile("ldmatrix.sync.aligned.m8n8.x4.shared.b16 {%0,%1,%2,%3}, [%4];"
                 : "=r"(r[0]), "=r"(r[1]), "=r"(r[2]), "=r"(r[3]) : "r"(addr));
}
__device__ __forceinline__ void ldsm_x2(uint32_t* r, uint32_t addr) {
    asm volatile("ldmatrix.sync.aligned.m8n8.x2.shared.b16 {%0,%1}, [%2];"
                 : "=r"(r[0]), "=r"(r[1]) : "r"(addr));
}
__device__ __forceinline__ void mma_bf16(float* c, const uint32_t* a, const uint32_t* b) {
    asm volatile(
        "mma.sync.aligned.m16n8k16.row.col.f32.bf16.bf16.f32 "
        "{%0,%1,%2,%3}, {%4,%5,%6,%7}, {%8,%9}, {%0,%1,%2,%3};"
        : "+f"(c[0]), "+f"(c[1]), "+f"(c[2]), "+f"(c[3])
        : "r"(a[0]), "r"(a[1]), "r"(a[2]), "r"(a[3]), "r"(b[0]), "r"(b[1]));
}
__device__ __forceinline__ void split1(float v, __nv_bfloat16& h, __nv_bfloat16& l) {
    h = __float2bfloat16(v);
    l = __float2bfloat16(v - __bfloat162float(h));
}
__device__ __forceinline__ void split2(float2 v, uint32_t& hi2, uint32_t& lo2) {
    __nv_bfloat16 h0, l0, h1, l1;
    split1(v.x, h0, l0);
    split1(v.y, h1, l1);
    __nv_bfloat162 H, L;
    H.x = h0; H.y = h1; L.x = l0; L.y = l1;
    hi2 = *(uint32_t*)&H;
    lo2 = *(uint32_t*)&L;
}

// ================= split fp32 -> (hi, lo) bf16 =============================
__global__ void split_kernel(const float* __restrict__ src,
                             __nv_bfloat16* __restrict__ hi,
                             __nv_bfloat16* __restrict__ lo,
                             int n_src, int n_total) {
    int i = blockIdx.x * blockDim.x + threadIdx.x;
    if (i >= n_total) return;
    float v = (i < n_src) ? src[i] : 0.f;
    __nv_bfloat16 h, l;
    split1(v, h, l);
    hi[i] = h;
    lo[i] = l;
}

// ================= mma.sync bf16 GEMM, 4-stage pipeline ====================
#define GSTRIDE 24
#define GOP_BYTES (128 * GSTRIDE * 2)      // 6144
#define GSTAGE_BYTES (4 * GOP_BYTES)       // 24576
#define GNSTAGE 4
__global__ __launch_bounds__(256, 2)
void mma_gemm(const __nv_bfloat16* __restrict__ Ahi, const __nv_bfloat16* __restrict__ Alo,
              const __nv_bfloat16* __restrict__ Bhi, const __nv_bfloat16* __restrict__ Blo,
              float* __restrict__ C, int Ktot, int Nact, int ldc, size_t csplit) {
    extern __shared__ char smx[];
    uint32_t sb = smem_u32(smx);
    int tid  = threadIdx.x;
    int lane = tid & 31, wid = tid >> 5;
    int wm = wid >> 2, wn = wid & 3;
    int m0 = blockIdx.y * 128, n0 = blockIdx.x * 128;
    int nsp  = gridDim.z;
    int Klen = Ktot / nsp;
    int k0   = blockIdx.z * Klen;
    float* Cp = C + (size_t)blockIdx.z * csplit;
    const int KT = Klen / 16;

    const __nv_bfloat16* ptrs[4] = {Ahi, Alo, Bhi, Blo};
    int rbase[4] = {m0, m0, n0, n0};

    auto load_stage = [&](int kt, int s) {
        uint32_t sbase = sb + s * GSTAGE_BYTES;
#pragma unroll
        for (int op = 0; op < 4; op++) {
            int r = tid >> 1, hf = tid & 1;
            const void* g = ptrs[op] + (size_t)(rbase[op] + r) * Ktot + k0 + kt * 16 + hf * 8;
            uint32_t d = sbase + op * GOP_BYTES + (r * GSTRIDE + hf * 8) * 2;
            asm volatile("cp.async.cg.shared.global [%0], [%1], 16;" :: "r"(d), "l"(g));
        }
        asm volatile("cp.async.commit_group;");
    };

    float acc[4][4][4];
#pragma unroll
    for (int i = 0; i < 4; i++)
#pragma unroll
        for (int j = 0; j < 4; j++)
#pragma unroll
            for (int q = 0; q < 4; q++) acc[i][j][q] = 0.f;

    load_stage(0, 0);
    load_stage(1, 1);
    load_stage(2, 2);

    for (int kt = 0; kt < KT; kt++) {
        asm volatile("cp.async.wait_group 2;");
        __syncthreads();

        uint32_t st = sb + (kt & 3) * GSTAGE_BYTES;
        uint32_t ah[4][4], al[4][4], bh[4][2], bl[4][2];
        int arow = wm * 64 + (lane & 15);
        int acol = (lane >> 4) * 8;
#pragma unroll
        for (int i = 0; i < 4; i++) {
            uint32_t off = ((arow + i * 16) * GSTRIDE + acol) * 2;
            ldsm_x4(ah[i], st + off);
            ldsm_x4(al[i], st + GOP_BYTES + off);
        }
        int brow = wn * 32 + (lane & 7);
        int bcol = ((lane >> 3) & 1) * 8;
#pragma unroll
        for (int j = 0; j < 4; j++) {
            uint32_t off = ((brow + j * 8) * GSTRIDE + bcol) * 2;
            ldsm_x2(bh[j], st + 2 * GOP_BYTES + off);
            ldsm_x2(bl[j], st + 3 * GOP_BYTES + off);
        }
#pragma unroll
        for (int i = 0; i < 4; i++)
#pragma unroll
            for (int j = 0; j < 4; j++) {
                mma_bf16(acc[i][j], ah[i], bh[j]);
                mma_bf16(acc[i][j], ah[i], bl[j]);
                mma_bf16(acc[i][j], al[i], bh[j]);
            }

        if (kt + 3 < KT) load_stage(kt + 3, (kt + 3) & 3);
        else             asm volatile("cp.async.commit_group;");
    }

    int r0 = m0 + wm * 64 + (lane >> 2);
    int c0 = n0 + wn * 32 + (lane & 3) * 2;
#pragma unroll
    for (int i = 0; i < 4; i++) {
#pragma unroll
        for (int j = 0; j < 4; j++) {
            int rr = r0 + i * 16;
            int cc = c0 + j * 8;
            if (cc < Nact)     Cp[(size_t)rr * ldc + cc]           = acc[i][j][0];
            if (cc + 1 < Nact) Cp[(size_t)rr * ldc + cc + 1]       = acc[i][j][1];
            if (cc < Nact)     Cp[(size_t)(rr + 8) * ldc + cc]     = acc[i][j][2];
            if (cc + 1 < Nact) Cp[(size_t)(rr + 8) * ldc + cc + 1] = acc[i][j][3];
        }
    }
}

// ---------------- reduce NSPLIT partials -> out -----------------------------
__global__ void reduce_kernel(float* __restrict__ out) {
    int i = blockIdx.x * blockDim.x + threadIdx.x;
    const int n4 = MROWS * DMODEL / 4;
    if (i >= n4) return;
    float4 a = *(const float4*)(g_pp + i * 4);
    float4 b = *(const float4*)(g_pp + MROWS * DMODEL + i * 4);
    float4 c = *(const float4*)(g_pp + 2 * MROWS * DMODEL + i * 4);
    float4 d = *(const float4*)(g_pp + 3 * MROWS * DMODEL + i * 4);
    float4 r = make_float4(a.x + b.x + c.x + d.x, a.y + b.y + c.y + d.y,
                           a.z + b.z + c.z + d.z, a.w + b.w + c.w + d.w);
    *(float4*)(out + i * 4) = r;
}

// ---------------- causal depthwise conv (width 4) + SiLU + split -----------
__global__ void conv_kernel(const float* __restrict__ conv_w,
                            const float* __restrict__ conv_b) {
    int idx = blockIdx.x * blockDim.x + threadIdx.x;
    if (idx >= MROWS * CONVDIM) return;
    int c = idx % CONVDIM;
    int m = idx / CONVDIM;
    int t = m % SEQLEN;
    float s = conv_b[c];
#pragma unroll
    for (int k = 0; k < 4; k++) {
        int tt = t - 3 + k;
        if (tt >= 0)
            s += g_zx[(size_t)(m - 3 + k) * DINPROJ + DINNER + c] * conv_w[c * 4 + k];
    }
    float v = s / (1.f + expf(-s));
    if (c < DINNER)                g_X [m * DINNER + c] = v;
    else if (c < DINNER + DSTATE)  g_Bm[m * DSTATE + (c - DINNER)] = v;
    else                           g_Cm[m * DSTATE + (c - DINNER - DSTATE)] = v;
}

// ---------------- dt = softplus, within-chunk cumsum of dt*A ---------------
__global__ void dtcum_kernel(const float* __restrict__ dt_bias,
                             const float* __restrict__ A_log) {
    int g  = blockIdx.x;
    int c  = g & (NCHUNK - 1);
    int bh = g >> 3;
    int h  = bh % NHEADS;
    int b  = bh / NHEADS;
    int t  = threadIdx.x;
    int m  = b * SEQLEN + c * LC + t;

    float x   = g_zx[(size_t)m * DINPROJ + DINNER + CONVDIM + h] + dt_bias[h];
    float dtv = (x > 20.f) ? x : log1pf(expf(x));
    float a   = -expf(A_log[h]) * dtv;

    float sc = a;
#pragma unroll
    for (int o = 1; o < 32; o <<= 1) {
        float v = __shfl_up_sync(0xffffffffu, sc, o);
        if ((t & 31) >= o) sc += v;
    }
    __shared__ float w0tot;
    if (t == 31) w0tot = sc;
    __syncthreads();
    if (t >= 32) sc += w0tot;

    int idx = bh * SEQLEN + c * LC + t;
    g_dtv[idx] = dtv;
    g_cum[idx] = sc;
}

// ---------------- intra-chunk kernel (tensor cores) -------------------------
// per block: chunk (bh,c). Stages:
//  1: G0 = C(64x128) . B^T   -> mask/decay -> G (bf16 hi/lo in smem)
//  2: Y  = G(64x64) . Xt^T  (+ D*x)       -> g_Y0
//  3: S  = Xt(64x64 rows p) . Bwt^T(128 rows n)  -> g_S
// strides: 136 (128-col ops), 72 (64-col ops) => 16B-mod-128 conflict-free.
#define OFF_SCUM 0
#define OFF_SDT  256
#define OFF_SW   512
#define OFF_CHI  768
#define PLANE128 (64*136*2)     // 17408
#define PLANE64  (64*72*2)      // 9216
#define PLANE128T (128*72*2)    // 18432
#define OFF_CLO  (OFF_CHI  + PLANE128)
#define OFF_BHI  (OFF_CLO  + PLANE128)
#define OFF_BLO  (OFF_BHI  + PLANE128)
#define OFF_XTHI (OFF_BLO  + PLANE128)
#define OFF_XTLO (OFF_XTHI + PLANE64)
#define OFF_BWHI (OFF_XTLO + PLANE64)
#define OFF_BWLO (OFF_BWHI + PLANE128T)
#define OFF_GHI  (OFF_BWLO + PLANE128T)
#define OFF_GLO  (OFF_GHI  + PLANE64)
#define INTRA_SMEM (OFF_GLO + PLANE64)   // 144128
__global__ __launch_bounds__(256)
void intra_tc(const float* __restrict__ D_param) {
    extern __shared__ char smc[];
    uint32_t sb = smem_u32(smc);
    float* scum = (float*)(smc + OFF_SCUM);
    float* sdt  = (float*)(smc + OFF_SDT);
    float* sw   = (float*)(smc + OFF_SW);
    __nv_bfloat16* Xthi = (__nv_bfloat16*)(smc + OFF_XTHI);
    __nv_bfloat16* Xtlo = (__nv_bfloat16*)(smc + OFF_XTLO);
    __nv_bfloat16* Bwhi = (__nv_bfloat16*)(smc + OFF_BWHI);
    __nv_bfloat16* Bwlo = (__nv_bfloat16*)(smc + OFF_BWLO);
    __nv_bfloat16* Ghi  = (__nv_bfloat16*)(smc + OFF_GHI);
    __nv_bfloat16* Glo  = (__nv_bfloat16*)(smc + OFF_GLO);

    int g  = blockIdx.x;
    int c  = g & (NCHUNK - 1);
    int bh = g >> 3;
    int h  = bh % NHEADS;
    int b  = bh / NHEADS;
    int tid = threadIdx.x;
    int lane = tid & 31, wid = tid >> 5;
    int m0 = b * SEQLEN + c * LC;

    if (tid < 64) {
        scum[tid] = g_cum[bh * SEQLEN + c * LC + tid];
        sdt[tid]  = g_dtv[bh * SEQLEN + c * LC + tid];
    }
    // C, B conversion (k-major, stride 136), float2 granularity
    for (int i = tid; i < 64 * 64; i += 256) {
        int r = i >> 6, q = (i & 63) * 2;
        float2 vc = *(const float2*)(g_Cm + (size_t)(m0 + r) * DSTATE + q);
        float2 vb = *(const float2*)(g_Bm + (size_t)(m0 + r) * DSTATE + q);
        uint32_t h2, l2;
        split2(vc, h2, l2);
        *(uint32_t*)(smc + OFF_CHI + (r * 136 + q) * 2) = h2;
        *(uint32_t*)(smc + OFF_CLO + (r * 136 + q) * 2) = l2;
        split2(vb, h2, l2);
        *(uint32_t*)(smc + OFF_BHI + (r * 136 + q) * 2) = h2;
        *(uint32_t*)(smc + OFF_BLO + (r * 136 + q) * 2) = l2;
    }
    // X transpose conversion: Xt[p][t]
    for (int i = tid; i < 64 * 16; i += 256) {
        int t_ = i >> 4, p4 = (i & 15) * 4;
        float4 v = *(const float4*)(g_X + (size_t)(m0 + t_) * DINNER + h * HEADDIM + p4);
        float vv[4] = {v.x, v.y, v.z, v.w};
#pragma unroll
        for (int e = 0; e < 4; e++) {
            __nv_bfloat16 hh, ll;
            split1(vv[e], hh, ll);
            Xthi[(p4 + e) * 72 + t_] = hh;
            Xtlo[(p4 + e) * 72 + t_] = ll;
        }
    }
    __syncthreads();
    if (tid < 64) sw[tid] = expf(scum[63] - scum[tid]) * sdt[tid];
    __syncthreads();
    // Bwt[n][s] = w[s]*B[s][n]
    for (int i = tid; i < 64 * 32; i += 256) {
        int s_ = i >> 5, n4 = (i & 31) * 4;
        float4 v = *(const float4*)(g_Bm + (size_t)(m0 + s_) * DSTATE + n4);
        float w = sw[s_];
        float vv[4] = {v.x * w, v.y * w, v.z * w, v.w * w};
#pragma unroll
        for (int e = 0; e < 4; e++) {
            __nv_bfloat16 hh, ll;
            split1(vv[e], hh, ll);
            Bwhi[(n4 + e) * 72 + s_] = hh;
            Bwlo[(n4 + e) * 72 + s_] = ll;
        }
    }
    __syncthreads();

    int wm = wid & 3, wn = wid >> 2;      // 4 m-groups x 2 n-groups

    // ---- stage 1: G0 = C . B^T (m=t 64, n=s 64, k=128) ----
    {
        float acc[4][4] = {};
        for (int kk = 0; kk < 8; kk++) {
            uint32_t ah[4], al[4], bh2[4][2], bl2[4][2];
            int arow = wm * 16 + (lane & 15);
            int acol = (lane >> 4) * 8 + kk * 16;
            ldsm_x4(ah, sb + OFF_CHI + (arow * 136 + acol) * 2);
            ldsm_x4(al, sb + OFF_CLO + (arow * 136 + acol) * 2);
            int bcol = ((lane >> 3) & 1) * 8 + kk * 16;
#pragma unroll
            for (int j = 0; j < 4; j++) {
                int br = wn * 32 + j * 8 + (lane & 7);
                ldsm_x2(bh2[j], sb + OFF_BHI + (br * 136 + bcol) * 2);
                ldsm_x2(bl2[j], sb + OFF_BLO + (br * 136 + bcol) * 2);
            }
#pragma unroll
            for (int j = 0; j < 4; j++) {
                mma_bf16(acc[j], ah, bh2[j]);
                mma_bf16(acc[j], ah, bl2[j]);
                mma_bf16(acc[j], al, bh2[j]);
            }
        }
        // mask/decay, split, store G
        int tr = wm * 16 + (lane >> 2);
#pragma unroll
        for (int j = 0; j < 4; j++) {
            int sc0 = wn * 32 + j * 8 + (lane & 3) * 2;
#pragma unroll
            for (int hlf = 0; hlf < 2; hlf++) {
                int t_ = tr + hlf * 8;
#pragma unroll
                for (int e = 0; e < 2; e++) {
                    int s_ = sc0 + e;
                    float wgt = (s_ <= t_) ? expf(scum[t_] - scum[s_]) * sdt[s_] : 0.f;
                    float gv = acc[j][hlf * 2 + e] * wgt;
                    __nv_bfloat16 hh, ll;
                    split1(gv, hh, ll);
                    Ghi[t_ * 72 + s_] = hh;
                    Glo[t_ * 72 + s_] = ll;
                }
            }
        }
    }
    __syncthreads();

    // ---- stage 2: Y = G . Xt^T (+ D*x) (m=t 64, n=p 64, k=s 64) ----
    {
        float acc[4][4] = {};
        for (int kk = 0; kk < 4; kk++) {
            uint32_t ah[4], al[4], bh2[4][2], bl2[4][2];
            int arow = wm * 16 + (lane & 15);
            int acol = (lane >> 4) * 8 + kk * 16;
            ldsm_x4(ah, sb + OFF_GHI + (arow * 72 + acol) * 2);
            ldsm_x4(al, sb + OFF_GLO + (arow * 72 + acol) * 2);
            int bcol = ((lane >> 3) & 1) * 8 + kk * 16;
#pragma unroll
            for (int j = 0; j < 4; j++) {
                int br = wn * 32 + j * 8 + (lane & 7);
                ldsm_x2(bh2[j], sb + OFF_XTHI + (br * 72 + bcol) * 2);
                ldsm_x2(bl2[j], sb + OFF_XTLO + (br * 72 + bcol) * 2);
            }
#pragma unroll
            for (int j = 0; j < 4; j++) {
                mma_bf16(acc[j], ah, bh2[j]);
                mma_bf16(acc[j], ah, bl2[j]);
                mma_bf16(acc[j], al, bh2[j]);
            }
        }
        float Dp = D_param[h];
        int tr = wm * 16 + (lane >> 2);
#pragma unroll
        for (int j = 0; j < 4; j++) {
            int p0 = wn * 32 + j * 8 + (lane & 3) * 2;
#pragma unroll
            for (int hlf = 0; hlf < 2; hlf++) {
                int t_ = tr + hlf * 8;
#pragma unroll
                for (int e = 0; e < 2; e++) {
                    int p_ = p0 + e;
                    float xv = __bfloat162float(Xthi[p_ * 72 + t_])
                             + __bfloat162float(Xtlo[p_ * 72 + t_]);
                    g_Y0[(size_t)(m0 + t_) * DINNER + h * HEADDIM + p_] =
                        acc[j][hlf * 2 + e] + Dp * xv;
                }
            }
        }
    }

    // ---- stage 3: S = Xt . Bwt^T (m=p 64, n=n 128, k=s 64) ----
    {
        float acc[8][4] = {};
        for (int kk = 0; kk < 4; kk++) {
            uint32_t ah[4], al[4], bh2[8][2], bl2[8][2];
            int arow = wm * 16 + (lane & 15);
            int acol = (lane >> 4) * 8 + kk * 16;
            ldsm_x4(ah, sb + OFF_XTHI + (arow * 72 + acol) * 2);
            ldsm_x4(al, sb + OFF_XTLO + (arow * 72 + acol) * 2);
            int bcol = ((lane >> 3) & 1) * 8 + kk * 16;
#pragma unroll
            for (int j = 0; j < 8; j++) {
                int br = wn * 64 + j * 8 + (lane & 7);
                ldsm_x2(bh2[j], sb + OFF_BWHI + (br * 72 + bcol) * 2);
                ldsm_x2(bl2[j], sb + OFF_BWLO + (br * 72 + bcol) * 2);
            }
#pragma unroll
            for (int j = 0; j < 8; j++) {
                mma_bf16(acc[j], ah, bh2[j]);
                mma_bf16(acc[j], ah, bl2[j]);
                mma_bf16(acc[j], al, bh2[j]);
            }
        }
        size_t base = (size_t)(bh * NCHUNK + c) * (HEADDIM * DSTATE);
        int pr = wm * 16 + (lane >> 2);
#pragma unroll
        for (int j = 0; j < 8; j++) {
            int n0_ = wn * 64 + j * 8 + (lane & 3) * 2;
#pragma unroll
            for (int hlf = 0; hlf < 2; hlf++) {
                int p_ = pr + hlf * 8;
#pragma unroll
                for (int e = 0; e < 2; e++) {
                    g_S[base + p_ * DSTATE + n0_ + e] = acc[j][hlf * 2 + e];
                }
            }
        }
    }
}

// ---------------- inter-chunk state scan (8 steps) --------------------------
__global__ void chunkscan_kernel() {
    int bh  = blockIdx.x;
    int tid = threadIdx.x;
    float4 E[4];
#pragma unroll
    for (int i = 0; i < 4; i++) E[i] = make_float4(0.f, 0.f, 0.f, 0.f);
    size_t base = (size_t)bh * NCHUNK * (HEADDIM * DSTATE);
    for (int k = 0; k < NCHUNK; k++) {
        float dAk = expf(g_cum[bh * SEQLEN + k * LC + (LC - 1)]);
        size_t off = base + (size_t)k * (HEADDIM * DSTATE) + tid * 16;
#pragma unroll
        for (int i = 0; i < 4; i++) {
            *(float4*)(g_P + off + i * 4) = E[i];
            float4 s = *(const float4*)(g_S + off + i * 4);
            E[i].x = s.x + dAk * E[i].x;
            E[i].y = s.y + dAk * E[i].y;
            E[i].z = s.z + dAk * E[i].z;
            E[i].w = s.w + dAk * E[i].w;
        }
    }
}

// ---------------- inter-chunk Y + gating + bf16 split -----------------------
#define SB_STRIDE 132
#define SMEMD_FLOATS (2*64*SB_STRIDE + 64)
__global__ __launch_bounds__(256)
void inter_gate_kernel() {
    extern __shared__ float sm[];
    float* sC   = sm;
    float* sP   = sC + 64 * SB_STRIDE;
    float* scum = sP + 64 * SB_STRIDE;

    int g  = blockIdx.x;
    int c  = g & (NCHUNK - 1);
    int bh = g >> 3;
    int h  = bh % NHEADS;
    int b  = bh / NHEADS;
    int tid = threadIdx.x;
    int m0 = b * SEQLEN + c * LC;
    size_t pbase = (size_t)(bh * NCHUNK + c) * (HEADDIM * DSTATE);

    for (int i = tid; i < 64 * 32; i += 256) {
        int r = i >> 5, q = i & 31;
        *(float4*)(sC + r * SB_STRIDE + q * 4) =
            *(const float4*)(g_Cm + (size_t)(m0 + r) * DSTATE + q * 4);
        *(float4*)(sP + r * SB_STRIDE + q * 4) =
            *(const float4*)(g_P + pbase + r * DSTATE + q * 4);
    }
    if (tid < 64) scum[tid] = g_cum[bh * SEQLEN + c * LC + tid];
    __syncthreads();

    int tx = tid & 15, ty = tid >> 4;
    int rot = (tid & 15) * 4;
    float acc[4][4] = {};
    for (int n0_ = 0; n0_ < 128; n0_ += 4) {
        int n = (n0_ + rot) & 127;
        float4 a4[4], b4[4];
#pragma unroll
        for (int i = 0; i < 4; i++) a4[i] = *(float4*)(sC + (ty * 4 + i) * SB_STRIDE + n);
#pragma unroll
        for (int j = 0; j < 4; j++) b4[j] = *(float4*)(sP + (tx * 4 + j) * SB_STRIDE + n);
#pragma unroll
        for (int i = 0; i < 4; i++)
#pragma unroll
            for (int j = 0; j < 4; j++)
                acc[i][j] += a4[i].x * b4[j].x + a4[i].y * b4[j].y
                           + a4[i].z * b4[j].z + a4[i].w * b4[j].w;
    }
#pragma unroll
    for (int i = 0; i < 4; i++) {
        int t_ = ty * 4 + i;
        float dec = expf(scum[t_]);
#pragma unroll
        for (int j = 0; j < 4; j++) {
            int p_ = tx * 4 + j;
            size_t mi = (size_t)(m0 + t_) * DINNER + h * HEADDIM + p_;
            float y = g_Y0[mi] + dec * acc[i][j];
            float z = g_zx[(size_t)(m0 + t_) * DINPROJ + h * HEADDIM + p_];
            float gv = y * (z / (1.f + expf(-z)));
            __nv_bfloat16 hb, lb;
            split1(gv, hb, lb);
            g_ghi[mi] = hb;
            g_glo[mi] = lb;
        }
    }
}

// ---------------- launch ----------------------------------------------------
extern "C" void kernel_launch(void* const* d_in, const int* in_sizes, int n_in,
                              void* d_out, int out_size) {
    const float* u       = (const float*)d_in[0];
    const float* W_in    = (const float*)d_in[1];
    const float* conv_w  = (const float*)d_in[2];
    const float* conv_b  = (const float*)d_in[3];
    const float* dt_bias = (const float*)d_in[4];
    const float* A_log   = (const float*)d_in[5];
    const float* D_param = (const float*)d_in[6];
    const float* W_out   = (const float*)d_in[7];
    float* out = (float*)d_out;

    float *zx, *pp;
    cudaGetSymbolAddress((void**)&zx, g_zx);
    cudaGetSymbolAddress((void**)&pp, g_pp);
    __nv_bfloat16 *uhi, *ulo, *wih, *wil, *ghi, *glo, *woh, *wol;
    cudaGetSymbolAddress((void**)&uhi, g_uhi);  cudaGetSymbolAddress((void**)&ulo, g_ulo);
    cudaGetSymbolAddress((void**)&wih, g_wih);  cudaGetSymbolAddress((void**)&wil, g_wil);
    cudaGetSymbolAddress((void**)&ghi, g_ghi);  cudaGetSymbolAddress((void**)&glo, g_glo);
    cudaGetSymbolAddress((void**)&woh, g_woh);  cudaGetSymbolAddress((void**)&wol, g_wol);

    static bool attr_done = false;
    if (!attr_done) {
        cudaFuncSetAttribute(intra_tc, cudaFuncAttributeMaxDynamicSharedMemorySize,
                             INTRA_SMEM);
        cudaFuncSetAttribute(inter_gate_kernel, cudaFuncAttributeMaxDynamicSharedMemorySize,
                             SMEMD_FLOATS * sizeof(float));
        cudaFuncSetAttribute(mma_gemm, cudaFuncAttributeMaxDynamicSharedMemorySize,
                             GNSTAGE * GSTAGE_BYTES);
        attr_done = true;
    }
    const int TC_SMEM = GNSTAGE * GSTAGE_BYTES;  // 98304

    // 0. split inputs/weights to bf16 hi/lo
    {
        int n1 = MROWS * DMODEL;
        split_kernel<<<(n1 + 255) / 256, 256>>>(u, uhi, ulo, n1, n1);
        int n2s = DINPROJ * DMODEL, n2t = NPAD_IN * DMODEL;
        split_kernel<<<(n2t + 255) / 256, 256>>>(W_in, wih, wil, n2s, n2t);
        int n3 = DMODEL * DINNER;
        split_kernel<<<(n3 + 255) / 256, 256>>>(W_out, woh, wol, n3, n3);
    }
    // 1. in-projection
    {
        dim3 grid(NPAD_IN / 128, MROWS / 128, 1);
        mma_gemm<<<grid, 256, TC_SMEM>>>(uhi, ulo, wih, wil, zx,
                                         DMODEL, DINPROJ, DINPROJ, 0);
    }
    // 2. causal conv + silu
    conv_kernel<<<(MROWS * CONVDIM + 255) / 256, 256>>>(conv_w, conv_b);
    // 3. dt + within-chunk cumsum
    dtcum_kernel<<<NBH * NCHUNK, 64>>>(dt_bias, A_log);
    // 4. intra-chunk (tensor cores)
    intra_tc<<<NBH * NCHUNK, 256, INTRA_SMEM>>>(D_param);
    // 5. inter-chunk state scan
    chunkscan_kernel<<<NBH, 512>>>();
    // 6. inter-chunk Y + gating (+ bf16 split of G)
    inter_gate_kernel<<<NBH * NCHUNK, 256, SMEMD_FLOATS * sizeof(float)>>>();
    // 7. out-projection, split-K x4 into partials, then reduce
    {
        dim3 grid(DMODEL / 128, MROWS / 128, NSPLIT);
        mma_gemm<<<grid, 256, TC_SMEM>>>(ghi, glo, woh, wol, pp,
                                         DINNER, DMODEL, DMODEL,
                                         (size_t)MROWS * DMODEL);
        reduce_kernel<<<(MROWS * DMODEL / 4 + 255) / 256, 256>>>(out);
    }
}

// round 9
// speedup vs baseline: 6.4597x; 1.0909x over previous
#include <cuda_runtime.h>
#include <cuda_bf16.h>
#include <math.h>
#include <cstdint>

#define BATCH   2
#define SEQLEN  512
#define DMODEL  768
#define DINNER  1536
#define NHEADS  24
#define HEADDIM 64
#define DSTATE  128
#define CONVDIM 1792
#define DINPROJ 3352
#define MROWS   (BATCH*SEQLEN)  // 1024
#define LC      64
#define NCHUNK  (SEQLEN/LC)     // 8
#define NBH     (BATCH*NHEADS)  // 48
#define NPAD_IN 3456
#define NSPLIT  4

// ---------------- scratch ---------------------------------------------------
__device__ float g_zx [MROWS * DINPROJ];
__device__ float g_X  [MROWS * DINNER];
__device__ float g_Bm [MROWS * DSTATE];
__device__ float g_Cm [MROWS * DSTATE];
__device__ float g_dtv[NBH * SEQLEN];
__device__ float g_cum[NBH * SEQLEN];
__device__ float g_Y0 [MROWS * DINNER];
__device__ float g_S  [NBH * NCHUNK * HEADDIM * DSTATE];
__device__ float g_P  [NBH * NCHUNK * HEADDIM * DSTATE];
__device__ float g_pp [NSPLIT * MROWS * DMODEL];

__device__ __align__(256) __nv_bfloat16 g_uhi[MROWS * DMODEL],   g_ulo[MROWS * DMODEL];
__device__ __align__(256) __nv_bfloat16 g_wih[NPAD_IN * DMODEL], g_wil[NPAD_IN * DMODEL];
__device__ __align__(256) __nv_bfloat16 g_ghi[MROWS * DINNER],   g_glo[MROWS * DINNER];
__device__ __align__(256) __nv_bfloat16 g_woh[DMODEL * DINNER],  g_wol[DMODEL * DINNER];

// ================= helpers =================================================
__device__ __forceinline__ uint32_t smem_u32(const void* p) {
    uint32_t a;
    asm("{ .reg .u64 t; cvta.to.shared.u64 t, %1; cvt.u32.u64 %0, t; }"
        : "=r"(a) : "l"(p));
    return a;
}
__device__ __forceinline__ void ldsm_x4(uint32_t* r, uint32_t addr) {
    asm volatile("ldmatrix.sync.aligned.m8n8.x4.shared.b16 {%0,%1,%2,%3}, [%4];"
                 : "=r"(r[0]), "=r"(r[1]), "=r"(r[2]), "=r"(r[3]) : "r"(addr));
}
__device__ __forceinline__ void ldsm_x2(uint32_t* r, uint32_t addr) {
    asm volatile("ldmatrix.sync.aligned.m8n8.x2.shared.b16 {%0,%1}, [%2];"
                 : "=r"(r[0]), "=r"(r[1]) : "r"(addr));
}
__device__ __forceinline__ void mma_bf16(float* c, const uint32_t* a, const uint32_t* b) {
    asm volatile(
        "mma.sync.aligned.m16n8k16.row.col.f32.bf16.bf16.f32 "
        "{%0,%1,%2,%3}, {%4,%5,%6,%7}, {%8,%9}, {%0,%1,%2,%3};"
        : "+f"(c[0]), "+f"(c[1]), "+f"(c[2]), "+f"(c[3])
        : "r"(a[0]), "r"(a[1]), "r"(a[2]), "r"(a[3]), "r"(b[0]), "r"(b[1]));
}
__device__ __forceinline__ void split1(float v, __nv_bfloat16& h, __nv_bfloat16& l) {
    h = __float2bfloat16(v);
    l = __float2bfloat16(v - __bfloat162float(h));
}
__device__ __forceinline__ void split2(float2 v, uint32_t& hi2, uint32_t& lo2) {
    __nv_bfloat16 h0, l0, h1, l1;
    split1(v.x, h0, l0);
    split1(v.y, h1, l1);
    __nv_bfloat162 H, L;
    H.x = h0; H.y = h1; L.x = l0; L.y = l1;
    hi2 = *(uint32_t*)&H;
    lo2 = *(uint32_t*)&L;
}

// ================= split fp32 -> (hi, lo) bf16 =============================
__global__ void split_kernel(const float* __restrict__ src,
                             __nv_bfloat16* __restrict__ hi,
                             __nv_bfloat16* __restrict__ lo,
                             int n_src, int n_total) {
    int i = blockIdx.x * blockDim.x + threadIdx.x;
    if (i >= n_total) return;
    float v = (i < n_src) ? src[i] : 0.f;
    __nv_bfloat16 h, l;
    split1(v, h, l);
    hi[i] = h;
    lo[i] = l;
}

// ================= mma.sync bf16 GEMM, 4-stage pipeline ====================
#define GSTRIDE 24
#define GOP_BYTES (128 * GSTRIDE * 2)      // 6144
#define GSTAGE_BYTES (4 * GOP_BYTES)       // 24576
#define GNSTAGE 4
__global__ __launch_bounds__(256, 2)
void mma_gemm(const __nv_bfloat16* __restrict__ Ahi, const __nv_bfloat16* __restrict__ Alo,
              const __nv_bfloat16* __restrict__ Bhi, const __nv_bfloat16* __restrict__ Blo,
              float* __restrict__ C, int Ktot, int Nact, int ldc, size_t csplit) {
    extern __shared__ char smx[];
    uint32_t sb = smem_u32(smx);
    int tid  = threadIdx.x;
    int lane = tid & 31, wid = tid >> 5;
    int wm = wid >> 2, wn = wid & 3;
    int m0 = blockIdx.y * 128, n0 = blockIdx.x * 128;
    int nsp  = gridDim.z;
    int Klen = Ktot / nsp;
    int k0   = blockIdx.z * Klen;
    float* Cp = C + (size_t)blockIdx.z * csplit;
    const int KT = Klen / 16;

    const __nv_bfloat16* ptrs[4] = {Ahi, Alo, Bhi, Blo};
    int rbase[4] = {m0, m0, n0, n0};

    auto load_stage = [&](int kt, int s) {
        uint32_t sbase = sb + s * GSTAGE_BYTES;
#pragma unroll
        for (int op = 0; op < 4; op++) {
            int r = tid >> 1, hf = tid & 1;
            const void* g = ptrs[op] + (size_t)(rbase[op] + r) * Ktot + k0 + kt * 16 + hf * 8;
            uint32_t d = sbase + op * GOP_BYTES + (r * GSTRIDE + hf * 8) * 2;
            asm volatile("cp.async.cg.shared.global [%0], [%1], 16;" :: "r"(d), "l"(g));
        }
        asm volatile("cp.async.commit_group;");
    };

    float acc[4][4][4];
#pragma unroll
    for (int i = 0; i < 4; i++)
#pragma unroll
        for (int j = 0; j < 4; j++)
#pragma unroll
            for (int q = 0; q < 4; q++) acc[i][j][q] = 0.f;

    load_stage(0, 0);
    load_stage(1, 1);
    load_stage(2, 2);

    for (int kt = 0; kt < KT; kt++) {
        asm volatile("cp.async.wait_group 2;");
        __syncthreads();

        uint32_t st = sb + (kt & 3) * GSTAGE_BYTES;
        uint32_t ah[4][4], al[4][4], bh[4][2], bl[4][2];
        int arow = wm * 64 + (lane & 15);
        int acol = (lane >> 4) * 8;
#pragma unroll
        for (int i = 0; i < 4; i++) {
            uint32_t off = ((arow + i * 16) * GSTRIDE + acol) * 2;
            ldsm_x4(ah[i], st + off);
            ldsm_x4(al[i], st + GOP_BYTES + off);
        }
        int brow = wn * 32 + (lane & 7);
        int bcol = ((lane >> 3) & 1) * 8;
#pragma unroll
        for (int j = 0; j < 4; j++) {
            uint32_t off = ((brow + j * 8) * GSTRIDE + bcol) * 2;
            ldsm_x2(bh[j], st + 2 * GOP_BYTES + off);
            ldsm_x2(bl[j], st + 3 * GOP_BYTES + off);
        }
#pragma unroll
        for (int i = 0; i < 4; i++)
#pragma unroll
            for (int j = 0; j < 4; j++) {
                mma_bf16(acc[i][j], ah[i], bh[j]);
                mma_bf16(acc[i][j], ah[i], bl[j]);
                mma_bf16(acc[i][j], al[i], bh[j]);
            }

        if (kt + 3 < KT) load_stage(kt + 3, (kt + 3) & 3);
        else             asm volatile("cp.async.commit_group;");
    }

    int r0 = m0 + wm * 64 + (lane >> 2);
    int c0 = n0 + wn * 32 + (lane & 3) * 2;
#pragma unroll
    for (int i = 0; i < 4; i++) {
#pragma unroll
        for (int j = 0; j < 4; j++) {
            int rr = r0 + i * 16;
            int cc = c0 + j * 8;
            if (cc < Nact)     Cp[(size_t)rr * ldc + cc]           = acc[i][j][0];
            if (cc + 1 < Nact) Cp[(size_t)rr * ldc + cc + 1]       = acc[i][j][1];
            if (cc < Nact)     Cp[(size_t)(rr + 8) * ldc + cc]     = acc[i][j][2];
            if (cc + 1 < Nact) Cp[(size_t)(rr + 8) * ldc + cc + 1] = acc[i][j][3];
        }
    }
}

// ---------------- reduce NSPLIT partials -> out -----------------------------
__global__ void reduce_kernel(float* __restrict__ out) {
    int i = blockIdx.x * blockDim.x + threadIdx.x;
    const int n4 = MROWS * DMODEL / 4;
    if (i >= n4) return;
    float4 a = *(const float4*)(g_pp + i * 4);
    float4 b = *(const float4*)(g_pp + MROWS * DMODEL + i * 4);
    float4 c = *(const float4*)(g_pp + 2 * MROWS * DMODEL + i * 4);
    float4 d = *(const float4*)(g_pp + 3 * MROWS * DMODEL + i * 4);
    float4 r = make_float4(a.x + b.x + c.x + d.x, a.y + b.y + c.y + d.y,
                           a.z + b.z + c.z + d.z, a.w + b.w + c.w + d.w);
    *(float4*)(out + i * 4) = r;
}

// ---------------- causal depthwise conv (width 4) + SiLU + split -----------
__global__ void conv_kernel(const float* __restrict__ conv_w,
                            const float* __restrict__ conv_b) {
    int idx = blockIdx.x * blockDim.x + threadIdx.x;
    if (idx >= MROWS * CONVDIM) return;
    int c = idx % CONVDIM;
    int m = idx / CONVDIM;
    int t = m % SEQLEN;
    float s = conv_b[c];
#pragma unroll
    for (int k = 0; k < 4; k++) {
        int tt = t - 3 + k;
        if (tt >= 0)
            s += g_zx[(size_t)(m - 3 + k) * DINPROJ + DINNER + c] * conv_w[c * 4 + k];
    }
    float v = s / (1.f + expf(-s));
    if (c < DINNER)                g_X [m * DINNER + c] = v;
    else if (c < DINNER + DSTATE)  g_Bm[m * DSTATE + (c - DINNER)] = v;
    else                           g_Cm[m * DSTATE + (c - DINNER - DSTATE)] = v;
}

// ---------------- dt = softplus, within-chunk cumsum of dt*A ---------------
__global__ void dtcum_kernel(const float* __restrict__ dt_bias,
                             const float* __restrict__ A_log) {
    int g  = blockIdx.x;
    int c  = g & (NCHUNK - 1);
    int bh = g >> 3;
    int h  = bh % NHEADS;
    int b  = bh / NHEADS;
    int t  = threadIdx.x;
    int m  = b * SEQLEN + c * LC + t;

    float x   = g_zx[(size_t)m * DINPROJ + DINNER + CONVDIM + h] + dt_bias[h];
    float dtv = (x > 20.f) ? x : log1pf(expf(x));
    float a   = -expf(A_log[h]) * dtv;

    float sc = a;
#pragma unroll
    for (int o = 1; o < 32; o <<= 1) {
        float v = __shfl_up_sync(0xffffffffu, sc, o);
        if ((t & 31) >= o) sc += v;
    }
    __shared__ float w0tot;
    if (t == 31) w0tot = sc;
    __syncthreads();
    if (t >= 32) sc += w0tot;

    int idx = bh * SEQLEN + c * LC + t;
    g_dtv[idx] = dtv;
    g_cum[idx] = sc;
}

// ---------------- intra-chunk kernel (tensor cores, smem-compacted) --------
// Region reuse: phase A {C,B hi/lo} is overwritten by phase B {G hi/lo, Bwt hi/lo}
// after stage 1. Total 88832 B -> 2 blocks/SM.
#define OFF_SCUM 0
#define OFF_SDT  256
#define OFF_SW   512
#define PLANE128 (64*136*2)     // 17408
#define PLANE64  (64*72*2)      // 9216
#define PLANE128T (128*72*2)    // 18432
#define OFF_XTHI 768
#define OFF_XTLO (OFF_XTHI + PLANE64)
#define OFF_BIG  (OFF_XTLO + PLANE64)        // 19200
// phase A
#define OFF_CHI  (OFF_BIG)
#define OFF_CLO  (OFF_CHI + PLANE128)
#define OFF_BHI  (OFF_CLO + PLANE128)
#define OFF_BLO  (OFF_BHI + PLANE128)
// phase B (same region)
#define OFF_GHI  (OFF_BIG)
#define OFF_GLO  (OFF_GHI + PLANE64)
#define OFF_BWHI (OFF_GLO + PLANE64)
#define OFF_BWLO (OFF_BWHI + PLANE128T)
#define INTRA_SMEM (OFF_BIG + 4*PLANE128)    // 88832
__global__ __launch_bounds__(256, 2)
void intra_tc(const float* __restrict__ D_param) {
    extern __shared__ char smc[];
    uint32_t sb = smem_u32(smc);
    float* scum = (float*)(smc + OFF_SCUM);
    float* sdt  = (float*)(smc + OFF_SDT);
    float* sw   = (float*)(smc + OFF_SW);
    __nv_bfloat16* Xthi = (__nv_bfloat16*)(smc + OFF_XTHI);
    __nv_bfloat16* Xtlo = (__nv_bfloat16*)(smc + OFF_XTLO);
    __nv_bfloat16* Bwhi = (__nv_bfloat16*)(smc + OFF_BWHI);
    __nv_bfloat16* Bwlo = (__nv_bfloat16*)(smc + OFF_BWLO);
    __nv_bfloat16* Ghi  = (__nv_bfloat16*)(smc + OFF_GHI);
    __nv_bfloat16* Glo  = (__nv_bfloat16*)(smc + OFF_GLO);

    int g  = blockIdx.x;
    int c  = g & (NCHUNK - 1);
    int bh = g >> 3;
    int h  = bh % NHEADS;
    int b  = bh / NHEADS;
    int tid = threadIdx.x;
    int lane = tid & 31, wid = tid >> 5;
    int m0 = b * SEQLEN + c * LC;

    if (tid < 64) {
        scum[tid] = g_cum[bh * SEQLEN + c * LC + tid];
        sdt[tid]  = g_dtv[bh * SEQLEN + c * LC + tid];
    }
    // C, B conversion (k-major, stride 136)
    for (int i = tid; i < 64 * 64; i += 256) {
        int r = i >> 6, q = (i & 63) * 2;
        float2 vc = *(const float2*)(g_Cm + (size_t)(m0 + r) * DSTATE + q);
        float2 vb = *(const float2*)(g_Bm + (size_t)(m0 + r) * DSTATE + q);
        uint32_t h2, l2;
        split2(vc, h2, l2);
        *(uint32_t*)(smc + OFF_CHI + (r * 136 + q) * 2) = h2;
        *(uint32_t*)(smc + OFF_CLO + (r * 136 + q) * 2) = l2;
        split2(vb, h2, l2);
        *(uint32_t*)(smc + OFF_BHI + (r * 136 + q) * 2) = h2;
        *(uint32_t*)(smc + OFF_BLO + (r * 136 + q) * 2) = l2;
    }
    // X transpose conversion: Xt[p][t]
    for (int i = tid; i < 64 * 16; i += 256) {
        int t_ = i >> 4, p4 = (i & 15) * 4;
        float4 v = *(const float4*)(g_X + (size_t)(m0 + t_) * DINNER + h * HEADDIM + p4);
        float vv[4] = {v.x, v.y, v.z, v.w};
#pragma unroll
        for (int e = 0; e < 4; e++) {
            __nv_bfloat16 hh, ll;
            split1(vv[e], hh, ll);
            Xthi[(p4 + e) * 72 + t_] = hh;
            Xtlo[(p4 + e) * 72 + t_] = ll;
        }
    }
    __syncthreads();
    if (tid < 64) sw[tid] = expf(scum[63] - scum[tid]) * sdt[tid];
    __syncthreads();

    int wm = wid & 3, wn = wid >> 2;      // 4 m-groups x 2 n-groups

    // ---- stage 1: G0 = C . B^T (m=t 64, n=s 64, k=128) ----
    float acc1[4][4] = {};
    {
        for (int kk = 0; kk < 8; kk++) {
            uint32_t ah[4], al[4], bh2[4][2], bl2[4][2];
            int arow = wm * 16 + (lane & 15);
            int acol = (lane >> 4) * 8 + kk * 16;
            ldsm_x4(ah, sb + OFF_CHI + (arow * 136 + acol) * 2);
            ldsm_x4(al, sb + OFF_CLO + (arow * 136 + acol) * 2);
            int bcol = ((lane >> 3) & 1) * 8 + kk * 16;
#pragma unroll
            for (int j = 0; j < 4; j++) {
                int br = wn * 32 + j * 8 + (lane & 7);
                ldsm_x2(bh2[j], sb + OFF_BHI + (br * 136 + bcol) * 2);
                ldsm_x2(bl2[j], sb + OFF_BLO + (br * 136 + bcol) * 2);
            }
#pragma unroll
            for (int j = 0; j < 4; j++) {
                mma_bf16(acc1[j], ah, bh2[j]);
                mma_bf16(acc1[j], ah, bl2[j]);
                mma_bf16(acc1[j], al, bh2[j]);
            }
        }
    }
    __syncthreads();   // C/B planes dead; safe to overwrite with G and Bwt

    // store G (mask/decay applied)
    {
        int tr = wm * 16 + (lane >> 2);
#pragma unroll
        for (int j = 0; j < 4; j++) {
            int sc0 = wn * 32 + j * 8 + (lane & 3) * 2;
#pragma unroll
            for (int hlf = 0; hlf < 2; hlf++) {
                int t_ = tr + hlf * 8;
#pragma unroll
                for (int e = 0; e < 2; e++) {
                    int s_ = sc0 + e;
                    float wgt = (s_ <= t_) ? expf(scum[t_] - scum[s_]) * sdt[s_] : 0.f;
                    float gv = acc1[j][hlf * 2 + e] * wgt;
                    __nv_bfloat16 hh, ll;
                    split1(gv, hh, ll);
                    Ghi[t_ * 72 + s_] = hh;
                    Glo[t_ * 72 + s_] = ll;
                }
            }
        }
    }
    // Bwt[n][s] = w[s]*B[s][n] (reload B from L2)
    for (int i = tid; i < 64 * 32; i += 256) {
        int s_ = i >> 5, n4 = (i & 31) * 4;
        float4 v = *(const float4*)(g_Bm + (size_t)(m0 + s_) * DSTATE + n4);
        float w = sw[s_];
        float vv[4] = {v.x * w, v.y * w, v.z * w, v.w * w};
#pragma unroll
        for (int e = 0; e < 4; e++) {
            __nv_bfloat16 hh, ll;
            split1(vv[e], hh, ll);
            Bwhi[(n4 + e) * 72 + s_] = hh;
            Bwlo[(n4 + e) * 72 + s_] = ll;
        }
    }
    __syncthreads();

    // ---- stage 2: Y = G . Xt^T (+ D*x) (m=t 64, n=p 64, k=s 64) ----
    {
        float acc[4][4] = {};
        for (int kk = 0; kk < 4; kk++) {
            uint32_t ah[4], al[4], bh2[4][2], bl2[4][2];
            int arow = wm * 16 + (lane & 15);
            int acol = (lane >> 4) * 8 + kk * 16;
            ldsm_x4(ah, sb + OFF_GHI + (arow * 72 + acol) * 2);
            ldsm_x4(al, sb + OFF_GLO + (arow * 72 + acol) * 2);
            int bcol = ((lane >> 3) & 1) * 8 + kk * 16;
#pragma unroll
            for (int j = 0; j < 4; j++) {
                int br = wn * 32 + j * 8 + (lane & 7);
                ldsm_x2(bh2[j], sb + OFF_XTHI + (br * 72 + bcol) * 2);
                ldsm_x2(bl2[j], sb + OFF_XTLO + (br * 72 + bcol) * 2);
            }
#pragma unroll
            for (int j = 0; j < 4; j++) {
                mma_bf16(acc[j], ah, bh2[j]);
                mma_bf16(acc[j], ah, bl2[j]);
                mma_bf16(acc[j], al, bh2[j]);
            }
        }
        float Dp = D_param[h];
        int tr = wm * 16 + (lane >> 2);
#pragma unroll
        for (int j = 0; j < 4; j++) {
            int p0 = wn * 32 + j * 8 + (lane & 3) * 2;
#pragma unroll
            for (int hlf = 0; hlf < 2; hlf++) {
                int t_ = tr + hlf * 8;
#pragma unroll
                for (int e = 0; e < 2; e++) {
                    int p_ = p0 + e;
                    float xv = __bfloat162float(Xthi[p_ * 72 + t_])
                             + __bfloat162float(Xtlo[p_ * 72 + t_]);
                    g_Y0[(size_t)(m0 + t_) * DINNER + h * HEADDIM + p_] =
                        acc[j][hlf * 2 + e] + Dp * xv;
                }
            }
        }
    }

    // ---- stage 3: S = Xt . Bwt^T (m=p 64, n=n 128, k=s 64) ----
    {
        float acc[8][4] = {};
        for (int kk = 0; kk < 4; kk++) {
            uint32_t ah[4], al[4], bh2[8][2], bl2[8][2];
            int arow = wm * 16 + (lane & 15);
            int acol = (lane >> 4) * 8 + kk * 16;
            ldsm_x4(ah, sb + OFF_XTHI + (arow * 72 + acol) * 2);
            ldsm_x4(al, sb + OFF_XTLO + (arow * 72 + acol) * 2);
            int bcol = ((lane >> 3) & 1) * 8 + kk * 16;
#pragma unroll
            for (int j = 0; j < 8; j++) {
                int br = wn * 64 + j * 8 + (lane & 7);
                ldsm_x2(bh2[j], sb + OFF_BWHI + (br * 72 + bcol) * 2);
                ldsm_x2(bl2[j], sb + OFF_BWLO + (br * 72 + bcol) * 2);
            }
#pragma unroll
            for (int j = 0; j < 8; j++) {
                mma_bf16(acc[j], ah, bh2[j]);
                mma_bf16(acc[j], ah, bl2[j]);
                mma_bf16(acc[j], al, bh2[j]);
            }
        }
        size_t base = (size_t)(bh * NCHUNK + c) * (HEADDIM * DSTATE);
        int pr = wm * 16 + (lane >> 2);
#pragma unroll
        for (int j = 0; j < 8; j++) {
            int n0_ = wn * 64 + j * 8 + (lane & 3) * 2;
#pragma unroll
            for (int hlf = 0; hlf < 2; hlf++) {
                int p_ = pr + hlf * 8;
#pragma unroll
                for (int e = 0; e < 2; e++) {
                    g_S[base + p_ * DSTATE + n0_ + e] = acc[j][hlf * 2 + e];
                }
            }
        }
    }
}

// ---------------- inter-chunk state scan: 192 blocks, 1 float4/thread -------
__global__ void chunkscan_kernel() {
    int bh   = blockIdx.x >> 2;
    int part = blockIdx.x & 3;
    int idx4 = part * 2048 + threadIdx.x * 4;
    float4 E = make_float4(0.f, 0.f, 0.f, 0.f);
    size_t base = (size_t)bh * NCHUNK * (HEADDIM * DSTATE);
#pragma unroll
    for (int k = 0; k < NCHUNK; k++) {
        float dAk = expf(g_cum[bh * SEQLEN + k * LC + (LC - 1)]);
        size_t off = base + (size_t)k * (HEADDIM * DSTATE) + idx4;
        *(float4*)(g_P + off) = E;
        float4 s = *(const float4*)(g_S + off);
        E.x = s.x + dAk * E.x;
        E.y = s.y + dAk * E.y;
        E.z = s.z + dAk * E.z;
        E.w = s.w + dAk * E.w;
    }
}

// ---------------- inter-chunk Y + gating + bf16 split -----------------------
#define SB_STRIDE 132
#define SMEMD_FLOATS (2*64*SB_STRIDE + 64)
__global__ __launch_bounds__(256)
void inter_gate_kernel() {
    extern __shared__ float sm[];
    float* sC   = sm;
    float* sP   = sC + 64 * SB_STRIDE;
    float* scum = sP + 64 * SB_STRIDE;

    int g  = blockIdx.x;
    int c  = g & (NCHUNK - 1);
    int bh = g >> 3;
    int h  = bh % NHEADS;
    int b  = bh / NHEADS;
    int tid = threadIdx.x;
    int m0 = b * SEQLEN + c * LC;
    size_t pbase = (size_t)(bh * NCHUNK + c) * (HEADDIM * DSTATE);

    for (int i = tid; i < 64 * 32; i += 256) {
        int r = i >> 5, q = i & 31;
        *(float4*)(sC + r * SB_STRIDE + q * 4) =
            *(const float4*)(g_Cm + (size_t)(m0 + r) * DSTATE + q * 4);
        *(float4*)(sP + r * SB_STRIDE + q * 4) =
            *(const float4*)(g_P + pbase + r * DSTATE + q * 4);
    }
    if (tid < 64) scum[tid] = g_cum[bh * SEQLEN + c * LC + tid];
    __syncthreads();

    int tx = tid & 15, ty = tid >> 4;
    int rot = (tid & 15) * 4;
    float acc[4][4] = {};
    for (int n0_ = 0; n0_ < 128; n0_ += 4) {
        int n = (n0_ + rot) & 127;
        float4 a4[4], b4[4];
#pragma unroll
        for (int i = 0; i < 4; i++) a4[i] = *(float4*)(sC + (ty * 4 + i) * SB_STRIDE + n);
#pragma unroll
        for (int j = 0; j < 4; j++) b4[j] = *(float4*)(sP + (tx * 4 + j) * SB_STRIDE + n);
#pragma unroll
        for (int i = 0; i < 4; i++)
#pragma unroll
            for (int j = 0; j < 4; j++)
                acc[i][j] += a4[i].x * b4[j].x + a4[i].y * b4[j].y
                           + a4[i].z * b4[j].z + a4[i].w * b4[j].w;
    }
#pragma unroll
    for (int i = 0; i < 4; i++) {
        int t_ = ty * 4 + i;
        float dec = expf(scum[t_]);
#pragma unroll
        for (int j = 0; j < 4; j++) {
            int p_ = tx * 4 + j;
            size_t mi = (size_t)(m0 + t_) * DINNER + h * HEADDIM + p_;
            float y = g_Y0[mi] + dec * acc[i][j];
            float z = g_zx[(size_t)(m0 + t_) * DINPROJ + h * HEADDIM + p_];
            float gv = y * (z / (1.f + expf(-z)));
            __nv_bfloat16 hb, lb;
            split1(gv, hb, lb);
            g_ghi[mi] = hb;
            g_glo[mi] = lb;
        }
    }
}

// ---------------- launch ----------------------------------------------------
extern "C" void kernel_launch(void* const* d_in, const int* in_sizes, int n_in,
                              void* d_out, int out_size) {
    const float* u       = (const float*)d_in[0];
    const float* W_in    = (const float*)d_in[1];
    const float* conv_w  = (const float*)d_in[2];
    const float* conv_b  = (const float*)d_in[3];
    const float* dt_bias = (const float*)d_in[4];
    const float* A_log   = (const float*)d_in[5];
    const float* D_param = (const float*)d_in[6];
    const float* W_out   = (const float*)d_in[7];
    float* out = (float*)d_out;

    float *zx, *pp;
    cudaGetSymbolAddress((void**)&zx, g_zx);
    cudaGetSymbolAddress((void**)&pp, g_pp);
    __nv_bfloat16 *uhi, *ulo, *wih, *wil, *ghi, *glo, *woh, *wol;
    cudaGetSymbolAddress((void**)&uhi, g_uhi);  cudaGetSymbolAddress((void**)&ulo, g_ulo);
    cudaGetSymbolAddress((void**)&wih, g_wih);  cudaGetSymbolAddress((void**)&wil, g_wil);
    cudaGetSymbolAddress((void**)&ghi, g_ghi);  cudaGetSymbolAddress((void**)&glo, g_glo);
    cudaGetSymbolAddress((void**)&woh, g_woh);  cudaGetSymbolAddress((void**)&wol, g_wol);

    static bool attr_done = false;
    if (!attr_done) {
        cudaFuncSetAttribute(intra_tc, cudaFuncAttributeMaxDynamicSharedMemorySize,
                             INTRA_SMEM);
        cudaFuncSetAttribute(inter_gate_kernel, cudaFuncAttributeMaxDynamicSharedMemorySize,
                             SMEMD_FLOATS * sizeof(float));
        cudaFuncSetAttribute(mma_gemm, cudaFuncAttributeMaxDynamicSharedMemorySize,
                             GNSTAGE * GSTAGE_BYTES);
        attr_done = true;
    }
    const int TC_SMEM = GNSTAGE * GSTAGE_BYTES;  // 98304

    // 0. split inputs/weights to bf16 hi/lo
    {
        int n1 = MROWS * DMODEL;
        split_kernel<<<(n1 + 255) / 256, 256>>>(u, uhi, ulo, n1, n1);
        int n2s = DINPROJ * DMODEL, n2t = NPAD_IN * DMODEL;
        split_kernel<<<(n2t + 255) / 256, 256>>>(W_in, wih, wil, n2s, n2t);
        int n3 = DMODEL * DINNER;
        split_kernel<<<(n3 + 255) / 256, 256>>>(W_out, woh, wol, n3, n3);
    }
    // 1. in-projection
    {
        dim3 grid(NPAD_IN / 128, MROWS / 128, 1);
        mma_gemm<<<grid, 256, TC_SMEM>>>(uhi, ulo, wih, wil, zx,
                                         DMODEL, DINPROJ, DINPROJ, 0);
    }
    // 2. causal conv + silu
    conv_kernel<<<(MROWS * CONVDIM + 255) / 256, 256>>>(conv_w, conv_b);
    // 3. dt + within-chunk cumsum
    dtcum_kernel<<<NBH * NCHUNK, 64>>>(dt_bias, A_log);
    // 4. intra-chunk (tensor cores, 2 blocks/SM)
    intra_tc<<<NBH * NCHUNK, 256, INTRA_SMEM>>>(D_param);
    // 5. inter-chunk state scan (more parallel)
    chunkscan_kernel<<<NBH * 4, 512>>>();
    // 6. inter-chunk Y + gating (+ bf16 split of G)
    inter_gate_kernel<<<NBH * NCHUNK, 256, SMEMD_FLOATS * sizeof(float)>>>();
    // 7. out-projection, split-K x4 into partials, then reduce
    {
        dim3 grid(DMODEL / 128, MROWS / 128, NSPLIT);
        mma_gemm<<<grid, 256, TC_SMEM>>>(ghi, glo, woh, wol, pp,
                                         DINNER, DMODEL, DMODEL,
                                         (size_t)MROWS * DMODEL);
        reduce_kernel<<<(MROWS * DMODEL / 4 + 255) / 256, 256>>>(out);
    }
}

// round 10
// speedup vs baseline: 6.6483x; 1.0292x over previous
#include <cuda_runtime.h>
#include <cuda_bf16.h>
#include <math.h>
#include <cstdint>

#define BATCH   2
#define SEQLEN  512
#define DMODEL  768
#define DINNER  1536
#define NHEADS  24
#define HEADDIM 64
#define DSTATE  128
#define CONVDIM 1792
#define DINPROJ 3352
#define MROWS   (BATCH*SEQLEN)  // 1024
#define LC      64
#define NCHUNK  (SEQLEN/LC)     // 8
#define NBH     (BATCH*NHEADS)  // 48
#define NPAD_IN 3456
#define NSPLIT  6

// ---------------- scratch ---------------------------------------------------
__device__ float g_zx [MROWS * DINPROJ];
__device__ float g_X  [MROWS * DINNER];
__device__ float g_Bm [MROWS * DSTATE];
__device__ float g_Cm [MROWS * DSTATE];
__device__ float g_dtv[NBH * SEQLEN];
__device__ float g_cum[NBH * SEQLEN];
__device__ float g_Y0 [MROWS * DINNER];
__device__ float g_S  [NBH * NCHUNK * HEADDIM * DSTATE];
__device__ float g_P  [NBH * NCHUNK * HEADDIM * DSTATE];
__device__ float g_pp [NSPLIT * MROWS * DMODEL];

__device__ __align__(256) __nv_bfloat16 g_uhi[MROWS * DMODEL],   g_ulo[MROWS * DMODEL];
__device__ __align__(256) __nv_bfloat16 g_wih[NPAD_IN * DMODEL], g_wil[NPAD_IN * DMODEL];
__device__ __align__(256) __nv_bfloat16 g_ghi[MROWS * DINNER],   g_glo[MROWS * DINNER];
__device__ __align__(256) __nv_bfloat16 g_woh[DMODEL * DINNER],  g_wol[DMODEL * DINNER];

// ================= helpers =================================================
__device__ __forceinline__ uint32_t smem_u32(const void* p) {
    uint32_t a;
    asm("{ .reg .u64 t; cvta.to.shared.u64 t, %1; cvt.u32.u64 %0, t; }"
        : "=r"(a) : "l"(p));
    return a;
}
__device__ __forceinline__ void ldsm_x4(uint32_t* r, uint32_t addr) {
    asm volatile("ldmatrix.sync.aligned.m8n8.x4.shared.b16 {%0,%1,%2,%3}, [%4];"
                 : "=r"(r[0]), "=r"(r[1]), "=r"(r[2]), "=r"(r[3]) : "r"(addr));
}
__device__ __forceinline__ void mma_bf16(float* c, const uint32_t* a, const uint32_t* b) {
    asm volatile(
        "mma.sync.aligned.m16n8k16.row.col.f32.bf16.bf16.f32 "
        "{%0,%1,%2,%3}, {%4,%5,%6,%7}, {%8,%9}, {%0,%1,%2,%3};"
        : "+f"(c[0]), "+f"(c[1]), "+f"(c[2]), "+f"(c[3])
        : "r"(a[0]), "r"(a[1]), "r"(a[2]), "r"(a[3]), "r"(b[0]), "r"(b[1]));
}
__device__ __forceinline__ void split1(float v, __nv_bfloat16& h, __nv_bfloat16& l) {
    h = __float2bfloat16(v);
    l = __float2bfloat16(v - __bfloat162float(h));
}
__device__ __forceinline__ void split2(float2 v, uint32_t& hi2, uint32_t& lo2) {
    __nv_bfloat16 h0, l0, h1, l1;
    split1(v.x, h0, l0);
    split1(v.y, h1, l1);
    __nv_bfloat162 H, L;
    H.x = h0; H.y = h1; L.x = l0; L.y = l1;
    hi2 = *(uint32_t*)&H;
    lo2 = *(uint32_t*)&L;
}

// ================= split fp32 -> (hi, lo) bf16 =============================
__global__ void split_kernel(const float* __restrict__ src,
                             __nv_bfloat16* __restrict__ hi,
                             __nv_bfloat16* __restrict__ lo,
                             int n_src, int n_total) {
    int i = blockIdx.x * blockDim.x + threadIdx.x;
    if (i >= n_total) return;
    float v = (i < n_src) ? src[i] : 0.f;
    __nv_bfloat16 h, l;
    split1(v, h, l);
    hi[i] = h;
    lo[i] = l;
}

// ================= mma.sync bf16 GEMM, 4-stage pipeline ====================
#define GSTRIDE 24
#define GOP_BYTES (128 * GSTRIDE * 2)      // 6144
#define GSTAGE_BYTES (4 * GOP_BYTES)       // 24576
#define GNSTAGE 4
__global__ __launch_bounds__(256, 2)
void mma_gemm(const __nv_bfloat16* __restrict__ Ahi, const __nv_bfloat16* __restrict__ Alo,
              const __nv_bfloat16* __restrict__ Bhi, const __nv_bfloat16* __restrict__ Blo,
              float* __restrict__ C, int Ktot, int Nact, int ldc, size_t csplit) {
    extern __shared__ char smx[];
    uint32_t sb = smem_u32(smx);
    int tid  = threadIdx.x;
    int lane = tid & 31, wid = tid >> 5;
    int wm = wid >> 2, wn = wid & 3;
    int m0 = blockIdx.y * 128, n0 = blockIdx.x * 128;
    int nsp  = gridDim.z;
    int Klen = Ktot / nsp;
    int k0   = blockIdx.z * Klen;
    float* Cp = C + (size_t)blockIdx.z * csplit;
    const int KT = Klen / 16;

    const __nv_bfloat16* ptrs[4] = {Ahi, Alo, Bhi, Blo};
    int rbase[4] = {m0, m0, n0, n0};

    auto load_stage = [&](int kt, int s) {
        uint32_t sbase = sb + s * GSTAGE_BYTES;
#pragma unroll
        for (int op = 0; op < 4; op++) {
            int r = tid >> 1, hf = tid & 1;
            const void* g = ptrs[op] + (size_t)(rbase[op] + r) * Ktot + k0 + kt * 16 + hf * 8;
            uint32_t d = sbase + op * GOP_BYTES + (r * GSTRIDE + hf * 8) * 2;
            asm volatile("cp.async.cg.shared.global [%0], [%1], 16;" :: "r"(d), "l"(g));
        }
        asm volatile("cp.async.commit_group;");
    };

    float acc[4][4][4];
#pragma unroll
    for (int i = 0; i < 4; i++)
#pragma unroll
        for (int j = 0; j < 4; j++)
#pragma unroll
            for (int q = 0; q < 4; q++) acc[i][j][q] = 0.f;

    load_stage(0, 0);
    load_stage(1, 1);
    load_stage(2, 2);

    for (int kt = 0; kt < KT; kt++) {
        asm volatile("cp.async.wait_group 2;");
        __syncthreads();

        uint32_t st = sb + (kt & 3) * GSTAGE_BYTES;
        uint32_t ah[4][4], al[4][4], bh[4][2], bl[4][2];
        int arow = wm * 64 + (lane & 15);
        int acol = (lane >> 4) * 8;
#pragma unroll
        for (int i = 0; i < 4; i++) {
            uint32_t off = ((arow + i * 16) * GSTRIDE + acol) * 2;
            ldsm_x4(ah[i], st + off);
            ldsm_x4(al[i], st + GOP_BYTES + off);
        }
        // B fragments: x4 loads fetch two j-tiles each (lanes 16-31 -> 2nd tile)
        int brow8 = ((lane >> 4) & 1) * 8 + (lane & 7);
        int bcol  = ((lane >> 3) & 1) * 8;
#pragma unroll
        for (int j2 = 0; j2 < 2; j2++) {
            int br = wn * 32 + j2 * 16 + brow8;
            uint32_t off = (br * GSTRIDE + bcol) * 2;
            ldsm_x4(&bh[2 * j2][0], st + 2 * GOP_BYTES + off);
            ldsm_x4(&bl[2 * j2][0], st + 3 * GOP_BYTES + off);
        }
#pragma unroll
        for (int i = 0; i < 4; i++)
#pragma unroll
            for (int j = 0; j < 4; j++) {
                mma_bf16(acc[i][j], ah[i], bh[j]);
                mma_bf16(acc[i][j], ah[i], bl[j]);
                mma_bf16(acc[i][j], al[i], bh[j]);
            }

        if (kt + 3 < KT) load_stage(kt + 3, (kt + 3) & 3);
        else             asm volatile("cp.async.commit_group;");
    }

    int r0 = m0 + wm * 64 + (lane >> 2);
    int c0 = n0 + wn * 32 + (lane & 3) * 2;
#pragma unroll
    for (int i = 0; i < 4; i++) {
#pragma unroll
        for (int j = 0; j < 4; j++) {
            int rr = r0 + i * 16;
            int cc = c0 + j * 8;
            if (cc < Nact)     Cp[(size_t)rr * ldc + cc]           = acc[i][j][0];
            if (cc + 1 < Nact) Cp[(size_t)rr * ldc + cc + 1]       = acc[i][j][1];
            if (cc < Nact)     Cp[(size_t)(rr + 8) * ldc + cc]     = acc[i][j][2];
            if (cc + 1 < Nact) Cp[(size_t)(rr + 8) * ldc + cc + 1] = acc[i][j][3];
        }
    }
}

// ---------------- reduce NSPLIT partials -> out -----------------------------
__global__ void reduce_kernel(float* __restrict__ out) {
    int i = blockIdx.x * blockDim.x + threadIdx.x;
    const int n4 = MROWS * DMODEL / 4;
    if (i >= n4) return;
    float4 r = make_float4(0.f, 0.f, 0.f, 0.f);
#pragma unroll
    for (int s = 0; s < NSPLIT; s++) {
        float4 a = *(const float4*)(g_pp + (size_t)s * MROWS * DMODEL + i * 4);
        r.x += a.x; r.y += a.y; r.z += a.z; r.w += a.w;
    }
    *(float4*)(out + i * 4) = r;
}

// ---------------- causal depthwise conv (width 4) + SiLU + split -----------
__global__ void conv_kernel(const float* __restrict__ conv_w,
                            const float* __restrict__ conv_b) {
    int idx = blockIdx.x * blockDim.x + threadIdx.x;
    if (idx >= MROWS * CONVDIM) return;
    int c = idx % CONVDIM;
    int m = idx / CONVDIM;
    int t = m % SEQLEN;
    float s = conv_b[c];
#pragma unroll
    for (int k = 0; k < 4; k++) {
        int tt = t - 3 + k;
        if (tt >= 0)
            s += g_zx[(size_t)(m - 3 + k) * DINPROJ + DINNER + c] * conv_w[c * 4 + k];
    }
    float v = s / (1.f + expf(-s));
    if (c < DINNER)                g_X [m * DINNER + c] = v;
    else if (c < DINNER + DSTATE)  g_Bm[m * DSTATE + (c - DINNER)] = v;
    else                           g_Cm[m * DSTATE + (c - DINNER - DSTATE)] = v;
}

// ---------------- dt = softplus, within-chunk cumsum of dt*A ---------------
__global__ void dtcum_kernel(const float* __restrict__ dt_bias,
                             const float* __restrict__ A_log) {
    int g  = blockIdx.x;
    int c  = g & (NCHUNK - 1);
    int bh = g >> 3;
    int h  = bh % NHEADS;
    int b  = bh / NHEADS;
    int t  = threadIdx.x;
    int m  = b * SEQLEN + c * LC + t;

    float x   = g_zx[(size_t)m * DINPROJ + DINNER + CONVDIM + h] + dt_bias[h];
    float dtv = (x > 20.f) ? x : log1pf(expf(x));
    float a   = -expf(A_log[h]) * dtv;

    float sc = a;
#pragma unroll
    for (int o = 1; o < 32; o <<= 1) {
        float v = __shfl_up_sync(0xffffffffu, sc, o);
        if ((t & 31) >= o) sc += v;
    }
    __shared__ float w0tot;
    if (t == 31) w0tot = sc;
    __syncthreads();
    if (t >= 32) sc += w0tot;

    int idx = bh * SEQLEN + c * LC + t;
    g_dtv[idx] = dtv;
    g_cum[idx] = sc;
}

// ---------------- intra-chunk kernel (tensor cores, smem-compacted) --------
#define OFF_SCUM 0
#define OFF_SDT  256
#define OFF_SW   512
#define PLANE128 (64*136*2)     // 17408
#define PLANE64  (64*72*2)      // 9216
#define PLANE128T (128*72*2)    // 18432
#define OFF_XTHI 768
#define OFF_XTLO (OFF_XTHI + PLANE64)
#define OFF_BIG  (OFF_XTLO + PLANE64)        // 19200
#define OFF_CHI  (OFF_BIG)
#define OFF_CLO  (OFF_CHI + PLANE128)
#define OFF_BHI  (OFF_CLO + PLANE128)
#define OFF_BLO  (OFF_BHI + PLANE128)
#define OFF_GHI  (OFF_BIG)
#define OFF_GLO  (OFF_GHI + PLANE64)
#define OFF_BWHI (OFF_GLO + PLANE64)
#define OFF_BWLO (OFF_BWHI + PLANE128T)
#define INTRA_SMEM (OFF_BIG + 4*PLANE128)    // 88832
__global__ __launch_bounds__(256, 2)
void intra_tc(const float* __restrict__ D_param) {
    extern __shared__ char smc[];
    uint32_t sb = smem_u32(smc);
    float* scum = (float*)(smc + OFF_SCUM);
    float* sdt  = (float*)(smc + OFF_SDT);
    float* sw   = (float*)(smc + OFF_SW);
    __nv_bfloat16* Xthi = (__nv_bfloat16*)(smc + OFF_XTHI);
    __nv_bfloat16* Xtlo = (__nv_bfloat16*)(smc + OFF_XTLO);
    __nv_bfloat16* Bwhi = (__nv_bfloat16*)(smc + OFF_BWHI);
    __nv_bfloat16* Bwlo = (__nv_bfloat16*)(smc + OFF_BWLO);
    __nv_bfloat16* Ghi  = (__nv_bfloat16*)(smc + OFF_GHI);
    __nv_bfloat16* Glo  = (__nv_bfloat16*)(smc + OFF_GLO);

    int g  = blockIdx.x;
    int c  = g & (NCHUNK - 1);
    int bh = g >> 3;
    int h  = bh % NHEADS;
    int b  = bh / NHEADS;
    int tid = threadIdx.x;
    int lane = tid & 31, wid = tid >> 5;
    int m0 = b * SEQLEN + c * LC;

    if (tid < 64) {
        scum[tid] = g_cum[bh * SEQLEN + c * LC + tid];
        sdt[tid]  = g_dtv[bh * SEQLEN + c * LC + tid];
    }
    for (int i = tid; i < 64 * 64; i += 256) {
        int r = i >> 6, q = (i & 63) * 2;
        float2 vc = *(const float2*)(g_Cm + (size_t)(m0 + r) * DSTATE + q);
        float2 vb = *(const float2*)(g_Bm + (size_t)(m0 + r) * DSTATE + q);
        uint32_t h2, l2;
        split2(vc, h2, l2);
        *(uint32_t*)(smc + OFF_CHI + (r * 136 + q) * 2) = h2;
        *(uint32_t*)(smc + OFF_CLO + (r * 136 + q) * 2) = l2;
        split2(vb, h2, l2);
        *(uint32_t*)(smc + OFF_BHI + (r * 136 + q) * 2) = h2;
        *(uint32_t*)(smc + OFF_BLO + (r * 136 + q) * 2) = l2;
    }
    for (int i = tid; i < 64 * 16; i += 256) {
        int t_ = i >> 4, p4 = (i & 15) * 4;
        float4 v = *(const float4*)(g_X + (size_t)(m0 + t_) * DINNER + h * HEADDIM + p4);
        float vv[4] = {v.x, v.y, v.z, v.w};
#pragma unroll
        for (int e = 0; e < 4; e++) {
            __nv_bfloat16 hh, ll;
            split1(vv[e], hh, ll);
            Xthi[(p4 + e) * 72 + t_] = hh;
            Xtlo[(p4 + e) * 72 + t_] = ll;
        }
    }
    __syncthreads();
    if (tid < 64) sw[tid] = expf(scum[63] - scum[tid]) * sdt[tid];
    __syncthreads();

    int wm = wid & 3, wn = wid >> 2;      // 4 m-groups x 2 n-groups
    int brow8 = ((lane >> 4) & 1) * 8 + (lane & 7);
    int bcolb = ((lane >> 3) & 1) * 8;

    // ---- stage 1: G0 = C . B^T (m=t 64, n=s 64, k=128) ----
    float acc1[4][4] = {};
    {
        for (int kk = 0; kk < 8; kk++) {
            uint32_t ah[4], al[4], bh2[4][2], bl2[4][2];
            int arow = wm * 16 + (lane & 15);
            int acol = (lane >> 4) * 8 + kk * 16;
            ldsm_x4(ah, sb + OFF_CHI + (arow * 136 + acol) * 2);
            ldsm_x4(al, sb + OFF_CLO + (arow * 136 + acol) * 2);
            int bcol = bcolb + kk * 16;
#pragma unroll
            for (int j2 = 0; j2 < 2; j2++) {
                int br = wn * 32 + j2 * 16 + brow8;
                ldsm_x4(&bh2[2 * j2][0], sb + OFF_BHI + (br * 136 + bcol) * 2);
                ldsm_x4(&bl2[2 * j2][0], sb + OFF_BLO + (br * 136 + bcol) * 2);
            }
#pragma unroll
            for (int j = 0; j < 4; j++) {
                mma_bf16(acc1[j], ah, bh2[j]);
                mma_bf16(acc1[j], ah, bl2[j]);
                mma_bf16(acc1[j], al, bh2[j]);
            }
        }
    }
    __syncthreads();   // C/B planes dead; reuse for G and Bwt

    {
        int tr = wm * 16 + (lane >> 2);
#pragma unroll
        for (int j = 0; j < 4; j++) {
            int sc0 = wn * 32 + j * 8 + (lane & 3) * 2;
#pragma unroll
            for (int hlf = 0; hlf < 2; hlf++) {
                int t_ = tr + hlf * 8;
#pragma unroll
                for (int e = 0; e < 2; e++) {
                    int s_ = sc0 + e;
                    float wgt = (s_ <= t_) ? expf(scum[t_] - scum[s_]) * sdt[s_] : 0.f;
                    float gv = acc1[j][hlf * 2 + e] * wgt;
                    __nv_bfloat16 hh, ll;
                    split1(gv, hh, ll);
                    Ghi[t_ * 72 + s_] = hh;
                    Glo[t_ * 72 + s_] = ll;
                }
            }
        }
    }
    for (int i = tid; i < 64 * 32; i += 256) {
        int s_ = i >> 5, n4 = (i & 31) * 4;
        float4 v = *(const float4*)(g_Bm + (size_t)(m0 + s_) * DSTATE + n4);
        float w = sw[s_];
        float vv[4] = {v.x * w, v.y * w, v.z * w, v.w * w};
#pragma unroll
        for (int e = 0; e < 4; e++) {
            __nv_bfloat16 hh, ll;
            split1(vv[e], hh, ll);
            Bwhi[(n4 + e) * 72 + s_] = hh;
            Bwlo[(n4 + e) * 72 + s_] = ll;
        }
    }
    __syncthreads();

    // ---- stage 2: Y = G . Xt^T (+ D*x) (m=t 64, n=p 64, k=s 64) ----
    {
        float acc[4][4] = {};
        for (int kk = 0; kk < 4; kk++) {
            uint32_t ah[4], al[4], bh2[4][2], bl2[4][2];
            int arow = wm * 16 + (lane & 15);
            int acol = (lane >> 4) * 8 + kk * 16;
            ldsm_x4(ah, sb + OFF_GHI + (arow * 72 + acol) * 2);
            ldsm_x4(al, sb + OFF_GLO + (arow * 72 + acol) * 2);
            int bcol = bcolb + kk * 16;
#pragma unroll
            for (int j2 = 0; j2 < 2; j2++) {
                int br = wn * 32 + j2 * 16 + brow8;
                ldsm_x4(&bh2[2 * j2][0], sb + OFF_XTHI + (br * 72 + bcol) * 2);
                ldsm_x4(&bl2[2 * j2][0], sb + OFF_XTLO + (br * 72 + bcol) * 2);
            }
#pragma unroll
            for (int j = 0; j < 4; j++) {
                mma_bf16(acc[j], ah, bh2[j]);
                mma_bf16(acc[j], ah, bl2[j]);
                mma_bf16(acc[j], al, bh2[j]);
            }
        }
        float Dp = D_param[h];
        int tr = wm * 16 + (lane >> 2);
#pragma unroll
        for (int j = 0; j < 4; j++) {
            int p0 = wn * 32 + j * 8 + (lane & 3) * 2;
#pragma unroll
            for (int hlf = 0; hlf < 2; hlf++) {
                int t_ = tr + hlf * 8;
#pragma unroll
                for (int e = 0; e < 2; e++) {
                    int p_ = p0 + e;
                    float xv = __bfloat162float(Xthi[p_ * 72 + t_])
                             + __bfloat162float(Xtlo[p_ * 72 + t_]);
                    g_Y0[(size_t)(m0 + t_) * DINNER + h * HEADDIM + p_] =
                        acc[j][hlf * 2 + e] + Dp * xv;
                }
            }
        }
    }

    // ---- stage 3: S = Xt . Bwt^T (m=p 64, n=n 128, k=s 64) ----
    {
        float acc[8][4] = {};
        for (int kk = 0; kk < 4; kk++) {
            uint32_t ah[4], al[4], bh2[8][2], bl2[8][2];
            int arow = wm * 16 + (lane & 15);
            int acol = (lane >> 4) * 8 + kk * 16;
            ldsm_x4(ah, sb + OFF_XTHI + (arow * 72 + acol) * 2);
            ldsm_x4(al, sb + OFF_XTLO + (arow * 72 + acol) * 2);
            int bcol = bcolb + kk * 16;
#pragma unroll
            for (int j2 = 0; j2 < 4; j2++) {
                int br = wn * 64 + j2 * 16 + brow8;
                ldsm_x4(&bh2[2 * j2][0], sb + OFF_BWHI + (br * 72 + bcol) * 2);
                ldsm_x4(&bl2[2 * j2][0], sb + OFF_BWLO + (br * 72 + bcol) * 2);
            }
#pragma unroll
            for (int j = 0; j < 8; j++) {
                mma_bf16(acc[j], ah, bh2[j]);
                mma_bf16(acc[j], ah, bl2[j]);
                mma_bf16(acc[j], al, bh2[j]);
            }
        }
        size_t base = (size_t)(bh * NCHUNK + c) * (HEADDIM * DSTATE);
        int pr = wm * 16 + (lane >> 2);
#pragma unroll
        for (int j = 0; j < 8; j++) {
            int n0_ = wn * 64 + j * 8 + (lane & 3) * 2;
#pragma unroll
            for (int hlf = 0; hlf < 2; hlf++) {
                int p_ = pr + hlf * 8;
#pragma unroll
                for (int e = 0; e < 2; e++) {
                    g_S[base + p_ * DSTATE + n0_ + e] = acc[j][hlf * 2 + e];
                }
            }
        }
    }
}

// ---------------- inter-chunk state scan: 192 blocks, 1 float4/thread -------
__global__ void chunkscan_kernel() {
    int bh   = blockIdx.x >> 2;
    int part = blockIdx.x & 3;
    int idx4 = part * 2048 + threadIdx.x * 4;
    float4 E = make_float4(0.f, 0.f, 0.f, 0.f);
    size_t base = (size_t)bh * NCHUNK * (HEADDIM * DSTATE);
#pragma unroll
    for (int k = 0; k < NCHUNK; k++) {
        float dAk = expf(g_cum[bh * SEQLEN + k * LC + (LC - 1)]);
        size_t off = base + (size_t)k * (HEADDIM * DSTATE) + idx4;
        *(float4*)(g_P + off) = E;
        float4 s = *(const float4*)(g_S + off);
        E.x = s.x + dAk * E.x;
        E.y = s.y + dAk * E.y;
        E.z = s.z + dAk * E.z;
        E.w = s.w + dAk * E.w;
    }
}

// ---------------- inter-chunk Y + gating + bf16 split -----------------------
#define SB_STRIDE 132
#define SMEMD_FLOATS (2*64*SB_STRIDE + 64)
__global__ __launch_bounds__(256)
void inter_gate_kernel() {
    extern __shared__ float sm[];
    float* sC   = sm;
    float* sP   = sC + 64 * SB_STRIDE;
    float* scum = sP + 64 * SB_STRIDE;

    int g  = blockIdx.x;
    int c  = g & (NCHUNK - 1);
    int bh = g >> 3;
    int h  = bh % NHEADS;
    int b  = bh / NHEADS;
    int tid = threadIdx.x;
    int m0 = b * SEQLEN + c * LC;
    size_t pbase = (size_t)(bh * NCHUNK + c) * (HEADDIM * DSTATE);

    for (int i = tid; i < 64 * 32; i += 256) {
        int r = i >> 5, q = i & 31;
        *(float4*)(sC + r * SB_STRIDE + q * 4) =
            *(const float4*)(g_Cm + (size_t)(m0 + r) * DSTATE + q * 4);
        *(float4*)(sP + r * SB_STRIDE + q * 4) =
            *(const float4*)(g_P + pbase + r * DSTATE + q * 4);
    }
    if (tid < 64) scum[tid] = g_cum[bh * SEQLEN + c * LC + tid];
    __syncthreads();

    int tx = tid & 15, ty = tid >> 4;
    int rot = (tid & 15) * 4;
    float acc[4][4] = {};
    for (int n0_ = 0; n0_ < 128; n0_ += 4) {
        int n = (n0_ + rot) & 127;
        float4 a4[4], b4[4];
#pragma unroll
        for (int i = 0; i < 4; i++) a4[i] = *(float4*)(sC + (ty * 4 + i) * SB_STRIDE + n);
#pragma unroll
        for (int j = 0; j < 4; j++) b4[j] = *(float4*)(sP + (tx * 4 + j) * SB_STRIDE + n);
#pragma unroll
        for (int i = 0; i < 4; i++)
#pragma unroll
            for (int j = 0; j < 4; j++)
                acc[i][j] += a4[i].x * b4[j].x + a4[i].y * b4[j].y
                           + a4[i].z * b4[j].z + a4[i].w * b4[j].w;
    }
#pragma unroll
    for (int i = 0; i < 4; i++) {
        int t_ = ty * 4 + i;
        float dec = expf(scum[t_]);
#pragma unroll
        for (int j = 0; j < 4; j++) {
            int p_ = tx * 4 + j;
            size_t mi = (size_t)(m0 + t_) * DINNER + h * HEADDIM + p_;
            float y = g_Y0[mi] + dec * acc[i][j];
            float z = g_zx[(size_t)(m0 + t_) * DINPROJ + h * HEADDIM + p_];
            float gv = y * (z / (1.f + expf(-z)));
            __nv_bfloat16 hb, lb;
            split1(gv, hb, lb);
            g_ghi[mi] = hb;
            g_glo[mi] = lb;
        }
    }
}

// ---------------- launch ----------------------------------------------------
extern "C" void kernel_launch(void* const* d_in, const int* in_sizes, int n_in,
                              void* d_out, int out_size) {
    const float* u       = (const float*)d_in[0];
    const float* W_in    = (const float*)d_in[1];
    const float* conv_w  = (const float*)d_in[2];
    const float* conv_b  = (const float*)d_in[3];
    const float* dt_bias = (const float*)d_in[4];
    const float* A_log   = (const float*)d_in[5];
    const float* D_param = (const float*)d_in[6];
    const float* W_out   = (const float*)d_in[7];
    float* out = (float*)d_out;

    float *zx, *pp;
    cudaGetSymbolAddress((void**)&zx, g_zx);
    cudaGetSymbolAddress((void**)&pp, g_pp);
    __nv_bfloat16 *uhi, *ulo, *wih, *wil, *ghi, *glo, *woh, *wol;
    cudaGetSymbolAddress((void**)&uhi, g_uhi);  cudaGetSymbolAddress((void**)&ulo, g_ulo);
    cudaGetSymbolAddress((void**)&wih, g_wih);  cudaGetSymbolAddress((void**)&wil, g_wil);
    cudaGetSymbolAddress((void**)&ghi, g_ghi);  cudaGetSymbolAddress((void**)&glo, g_glo);
    cudaGetSymbolAddress((void**)&woh, g_woh);  cudaGetSymbolAddress((void**)&wol, g_wol);

    static bool attr_done = false;
    if (!attr_done) {
        cudaFuncSetAttribute(intra_tc, cudaFuncAttributeMaxDynamicSharedMemorySize,
                             INTRA_SMEM);
        cudaFuncSetAttribute(inter_gate_kernel, cudaFuncAttributeMaxDynamicSharedMemorySize,
                             SMEMD_FLOATS * sizeof(float));
        cudaFuncSetAttribute(mma_gemm, cudaFuncAttributeMaxDynamicSharedMemorySize,
                             GNSTAGE * GSTAGE_BYTES);
        attr_done = true;
    }
    const int TC_SMEM = GNSTAGE * GSTAGE_BYTES;  // 98304

    // 0. split inputs/weights to bf16 hi/lo
    {
        int n1 = MROWS * DMODEL;
        split_kernel<<<(n1 + 255) / 256, 256>>>(u, uhi, ulo, n1, n1);
        int n2s = DINPROJ * DMODEL, n2t = NPAD_IN * DMODEL;
        split_kernel<<<(n2t + 255) / 256, 256>>>(W_in, wih, wil, n2s, n2t);
        int n3 = DMODEL * DINNER;
        split_kernel<<<(n3 + 255) / 256, 256>>>(W_out, woh, wol, n3, n3);
    }
    // 1. in-projection
    {
        dim3 grid(NPAD_IN / 128, MROWS / 128, 1);
        mma_gemm<<<grid, 256, TC_SMEM>>>(uhi, ulo, wih, wil, zx,
                                         DMODEL, DINPROJ, DINPROJ, 0);
    }
    // 2. causal conv + silu
    conv_kernel<<<(MROWS * CONVDIM + 255) / 256, 256>>>(conv_w, conv_b);
    // 3. dt + within-chunk cumsum
    dtcum_kernel<<<NBH * NCHUNK, 64>>>(dt_bias, A_log);
    // 4. intra-chunk (tensor cores, 2 blocks/SM)
    intra_tc<<<NBH * NCHUNK, 256, INTRA_SMEM>>>(D_param);
    // 5. inter-chunk state scan
    chunkscan_kernel<<<NBH * 4, 512>>>();
    // 6. inter-chunk Y + gating (+ bf16 split of G)
    inter_gate_kernel<<<NBH * NCHUNK, 256, SMEMD_FLOATS * sizeof(float)>>>();
    // 7. out-projection, split-K x6 into partials, then reduce
    {
        dim3 grid(DMODEL / 128, MROWS / 128, NSPLIT);
        mma_gemm<<<grid, 256, TC_SMEM>>>(ghi, glo, woh, wol, pp,
                                         DINNER, DMODEL, DMODEL,
                                         (size_t)MROWS * DMODEL);
        reduce_kernel<<<(MROWS * DMODEL / 4 + 255) / 256, 256>>>(out);
    }
}